// round 8
// baseline (speedup 1.0000x reference)
#include <cuda_runtime.h>
#include <cuda_bf16.h>
#include <cstdint>

#define B_  2
#define T_  2048
#define NH_ 16
#define HS_ 64
#define C_  (NH_*HS_)   // 1024
#define M_  (B_*T_)     // 4096

// ======================= helpers ==============================================
__device__ __forceinline__ uint32_t smem_u32(const void* p) {
    uint32_t a;
    asm("{ .reg .u64 t; cvta.to.shared.u64 t, %1; cvt.u32.u64 %0, t; }" : "=r"(a) : "l"(p));
    return a;
}
#define CP_ASYNC16(dst_u32, src_ptr) \
    asm volatile("cp.async.cg.shared.global [%0], [%1], 16;" :: "r"(dst_u32), "l"(src_ptr))
#define CP_COMMIT() asm volatile("cp.async.commit_group;" ::: "memory")
#define CP_WAIT(n)  asm volatile("cp.async.wait_group %0;" :: "n"(n) : "memory")

__device__ __forceinline__ void ldm_x4(uint32_t& r0, uint32_t& r1, uint32_t& r2, uint32_t& r3,
                                       uint32_t addr) {
    asm volatile("ldmatrix.sync.aligned.m8n8.x4.shared.b16 {%0,%1,%2,%3}, [%4];"
                 : "=r"(r0), "=r"(r1), "=r"(r2), "=r"(r3) : "r"(addr));
}
__device__ __forceinline__ void ldm_x2(uint32_t& r0, uint32_t& r1, uint32_t addr) {
    asm volatile("ldmatrix.sync.aligned.m8n8.x2.shared.b16 {%0,%1}, [%2];"
                 : "=r"(r0), "=r"(r1) : "r"(addr));
}
__device__ __forceinline__ void mma_bf16(float* c, const uint32_t* a, const uint32_t* b) {
    asm volatile(
        "mma.sync.aligned.m16n8k16.row.col.f32.bf16.bf16.f32 "
        "{%0,%1,%2,%3}, {%4,%5,%6,%7}, {%8,%9}, {%0,%1,%2,%3};"
        : "+f"(c[0]), "+f"(c[1]), "+f"(c[2]), "+f"(c[3])
        : "r"(a[0]), "r"(a[1]), "r"(a[2]), "r"(a[3]), "r"(b[0]), "r"(b[1]));
}

// ---------------- scratch (device globals; no allocation allowed) -------------
__device__ float g_xl[(size_t)B_*T_*C_];
__device__ float g_xv[(size_t)B_*T_*C_];
__device__ float g_kraw[(size_t)B_*NH_*T_*HS_];

#define NCH 64
#define TCH 32
__device__ float g_fin[(size_t)B_*NCH*C_];
__device__ float g_carry[(size_t)B_*NCH*C_];

__device__ __nv_bfloat16 g_Ah[(size_t)M_*C_];
__device__ __nv_bfloat16 g_Al[(size_t)M_*C_];
__device__ __nv_bfloat16 g_Wla_h[(size_t)C_*C_];
__device__ __nv_bfloat16 g_Wla_l[(size_t)C_*C_];
__device__ __nv_bfloat16 g_Wv_h[(size_t)C_*C_];
__device__ __nv_bfloat16 g_Wv_l[(size_t)C_*C_];
__device__ __nv_bfloat16 g_Wp_h[(size_t)C_*C_];
__device__ __nv_bfloat16 g_Wp_l[(size_t)C_*C_];
__device__ __nv_bfloat16 g_kh[(size_t)B_*NH_*T_*HS_];
__device__ __nv_bfloat16 g_kl[(size_t)B_*NH_*T_*HS_];
__device__ __nv_bfloat16 g_vth[(size_t)B_*NH_*HS_*T_];   // [b,h,d,t]
__device__ __nv_bfloat16 g_vtl[(size_t)B_*NH_*HS_*T_];

// ================= fp32 -> bf16 hi/lo split (no transpose) ====================
__global__ void __launch_bounds__(256) split_bf16_k(
    const float* __restrict__ X, __nv_bfloat16* __restrict__ H,
    __nv_bfloat16* __restrict__ L, int n4)
{
    int i = blockIdx.x * blockDim.x + threadIdx.x;
    if (i >= n4) return;
    float4 v = ((const float4*)X)[i];
    __nv_bfloat16 h0 = __float2bfloat16_rn(v.x);
    __nv_bfloat16 h1 = __float2bfloat16_rn(v.y);
    __nv_bfloat16 h2 = __float2bfloat16_rn(v.z);
    __nv_bfloat16 h3 = __float2bfloat16_rn(v.w);
    __nv_bfloat16 l0 = __float2bfloat16_rn(v.x - __bfloat162float(h0));
    __nv_bfloat16 l1 = __float2bfloat16_rn(v.y - __bfloat162float(h1));
    __nv_bfloat16 l2 = __float2bfloat16_rn(v.z - __bfloat162float(h2));
    __nv_bfloat16 l3 = __float2bfloat16_rn(v.w - __bfloat162float(h3));
    __nv_bfloat162* Hp = (__nv_bfloat162*)H;
    __nv_bfloat162* Lp = (__nv_bfloat162*)L;
    Hp[2*i]   = __nv_bfloat162(h0, h1);
    Hp[2*i+1] = __nv_bfloat162(h2, h3);
    Lp[2*i]   = __nv_bfloat162(l0, l1);
    Lp[2*i+1] = __nv_bfloat162(l2, l3);
}

// ==== batched: 3 weights fp32 [K,N] -> bf16 hi/lo transposed [N,K] ============
__global__ void tsplit3_k(const float* __restrict__ W0, const float* __restrict__ W1,
                          const float* __restrict__ W2,
                          __nv_bfloat16* __restrict__ H0, __nv_bfloat16* __restrict__ L0,
                          __nv_bfloat16* __restrict__ H1, __nv_bfloat16* __restrict__ L1,
                          __nv_bfloat16* __restrict__ H2, __nv_bfloat16* __restrict__ L2)
{
    __shared__ float tile[32][33];
    const float* W = (blockIdx.z == 0) ? W0 : (blockIdx.z == 1) ? W1 : W2;
    __nv_bfloat16* TH = (blockIdx.z == 0) ? H0 : (blockIdx.z == 1) ? H1 : H2;
    __nv_bfloat16* TL = (blockIdx.z == 0) ? L0 : (blockIdx.z == 1) ? L1 : L2;
    const int n0 = blockIdx.x * 32, k0 = blockIdx.y * 32;
    const int tx = threadIdx.x, ty = threadIdx.y;  // 32 x 8
    #pragma unroll
    for (int j = ty; j < 32; j += 8)
        tile[j][tx] = W[(size_t)(k0 + j) * C_ + n0 + tx];
    __syncthreads();
    #pragma unroll
    for (int j = ty; j < 32; j += 8) {
        float v = tile[tx][j];
        __nv_bfloat16 h = __float2bfloat16_rn(v);
        __nv_bfloat16 l = __float2bfloat16_rn(v - __bfloat162float(h));
        TH[(size_t)(n0 + j) * C_ + k0 + tx] = h;
        TL[(size_t)(n0 + j) * C_ + k0 + tx] = l;
    }
}

// ===== wide-tile fused-pass HMMA split GEMM: 128x256 per CTA, 3-stage =========
#define GBM 128
#define GBN 256
#define GBK 32
#define GK  1024
#define GNN 1024
#define GNK (GK / GBK)                    // 32
#define GLDS 40                           // halves per smem row
#define GA_B (GBM * GLDS * 2)             // 10240 B per A matrix tile
#define GB_B (GBN * GLDS * 2)             // 20480 B per B matrix tile
#define GSTG (2*GA_B + 2*GB_B)            // 61440 per stage
#define GSMEM (3 * GSTG)                  // 184320

__global__ void __launch_bounds__(256, 1) gemm_tc_k(
    const __nv_bfloat16* __restrict__ Ah, const __nv_bfloat16* __restrict__ Al,
    const __nv_bfloat16* __restrict__ W1h, const __nv_bfloat16* __restrict__ W1l,
    const __nv_bfloat16* __restrict__ W2h, const __nv_bfloat16* __restrict__ W2l,
    float* __restrict__ C1, float* __restrict__ C2)
{
    extern __shared__ __align__(16) char gsm[];

    const int n0g = blockIdx.x * GBN;
    const bool sel = (n0g >= GNN);
    const int n0 = sel ? (n0g - GNN) : n0g;
    const __nv_bfloat16* Bh = sel ? W2h : W1h;
    const __nv_bfloat16* Bl = sel ? W2l : W1l;
    float* Cg = sel ? C2 : C1;

    const int m0 = blockIdx.y * GBM;
    const int tid  = threadIdx.x;
    const int wid  = tid >> 5;
    const int lane = tid & 31;
    const int wm = (wid >> 2) * 64;   // 0 or 64
    const int wn = (wid & 3) * 64;    // 0..192

    float acc[4][8][4];
    #pragma unroll
    for (int i = 0; i < 4; i++)
        #pragma unroll
        for (int j = 0; j < 8; j++)
            #pragma unroll
            for (int e = 0; e < 4; e++) acc[i][j][e] = 0.f;

    auto load_tile = [&](int stage, int kc) {
        const int k0 = kc * GBK;
        char* base = gsm + stage * GSTG;
        #pragma unroll
        for (int i = 0; i < 2; i++) {
            const int idx = tid + i * 256;
            const int row = idx >> 2;
            const int c8  = (idx & 3) * 8;
            const uint32_t so = (uint32_t)(row * GLDS + c8) * 2;
            CP_ASYNC16(smem_u32(base + so),        Ah + (size_t)(m0 + row) * GK + k0 + c8);
            CP_ASYNC16(smem_u32(base + GA_B + so), Al + (size_t)(m0 + row) * GK + k0 + c8);
        }
        #pragma unroll
        for (int i = 0; i < 4; i++) {
            const int idx = tid + i * 256;
            const int row = idx >> 2;
            const int c8  = (idx & 3) * 8;
            const uint32_t so = (uint32_t)(row * GLDS + c8) * 2;
            CP_ASYNC16(smem_u32(base + 2*GA_B + so),        Bh + (size_t)(n0 + row) * GK + k0 + c8);
            CP_ASYNC16(smem_u32(base + 2*GA_B + GB_B + so), Bl + (size_t)(n0 + row) * GK + k0 + c8);
        }
    };

    load_tile(0, 0);
    CP_COMMIT();
    load_tile(1, 1);
    CP_COMMIT();

    #pragma unroll 1
    for (int kc = 0; kc < GNK; kc++) {
        const int st = kc % 3;
        if (kc + 1 < GNK) { CP_WAIT(1); } else { CP_WAIT(0); }
        __syncthreads();
        if (kc + 2 < GNK) {
            load_tile((kc + 2) % 3, kc + 2);
            CP_COMMIT();
        }

        char* base = gsm + st * GSTG;
        char* bA_h = base;
        char* bA_l = base + GA_B;
        char* bB_h = base + 2*GA_B;
        char* bB_l = base + 2*GA_B + GB_B;

        #pragma unroll
        for (int ks = 0; ks < 2; ks++) {
            const int koff = ks * 16;
            uint32_t bh2[8][2], bl2[8][2];
            #pragma unroll
            for (int nj = 0; nj < 8; nj++) {
                const int brow = wn + nj*8 + (lane & 7);
                const int bcol = koff + ((lane >> 3) & 1) * 8;
                ldm_x2(bh2[nj][0], bh2[nj][1], smem_u32(bB_h + (brow * GLDS + bcol) * 2));
                ldm_x2(bl2[nj][0], bl2[nj][1], smem_u32(bB_l + (brow * GLDS + bcol) * 2));
            }
            #pragma unroll
            for (int mi = 0; mi < 4; mi++) {
                const int arow = wm + mi*16 + (lane & 15);
                const int acol = koff + ((lane >> 4) & 1) * 8;
                uint32_t a4h[4], a4l[4];
                ldm_x4(a4h[0], a4h[1], a4h[2], a4h[3],
                       smem_u32(bA_h + (arow * GLDS + acol) * 2));
                ldm_x4(a4l[0], a4l[1], a4l[2], a4l[3],
                       smem_u32(bA_l + (arow * GLDS + acol) * 2));
                // same-acc MMAs separated by 8 instructions (no back-to-back RAW)
                #pragma unroll
                for (int nj = 0; nj < 8; nj++)
                    mma_bf16(acc[mi][nj], a4h, bh2[nj]);
                #pragma unroll
                for (int nj = 0; nj < 8; nj++)
                    mma_bf16(acc[mi][nj], a4h, bl2[nj]);
                #pragma unroll
                for (int nj = 0; nj < 8; nj++)
                    mma_bf16(acc[mi][nj], a4l, bh2[nj]);
            }
        }
    }

    const int g = lane >> 2, t = lane & 3;
    #pragma unroll
    for (int mi = 0; mi < 4; mi++) {
        float* row0 = Cg + (size_t)(m0 + wm + mi*16 + g)     * GNN + n0 + wn;
        float* row1 = Cg + (size_t)(m0 + wm + mi*16 + g + 8) * GNN + n0 + wn;
        #pragma unroll
        for (int nj = 0; nj < 8; nj++) {
            *(float2*)(row0 + nj*8 + t*2) = make_float2(acc[mi][nj][0], acc[mi][nj][1]);
            *(float2*)(row1 + nj*8 + t*2) = make_float2(acc[mi][nj][2], acc[mi][nj][3]);
        }
    }
}

// ============== EMA scan: chunked parallel (local scan + combine) =============
__global__ void __launch_bounds__(256) ema_local_k(
    const float* __restrict__ xl, const float* __restrict__ la_coef,
    float* __restrict__ kraw, float* __restrict__ fin)
{
    const int gid = blockIdx.x * blockDim.x + threadIdx.x;
    if (gid >= B_ * NCH * C_) return;
    const int c = gid % C_;
    const int rest = gid / C_;
    const int chunk = rest % NCH;
    const int b = rest / NCH;
    const int h = c >> 6, d = c & 63;

    const float a = la_coef[h];
    const float onem = 1.0f - a;
    float carry = 0.0f;

    const float* src = xl + ((size_t)b * T_ + chunk * TCH) * C_ + c;
    float* dst = kraw + (((size_t)b * NH_ + h) * T_ + chunk * TCH) * HS_ + d;

    #pragma unroll 4
    for (int t = 0; t < TCH; t++) {
        carry = a * carry + onem * src[(size_t)t * C_];
        dst[(size_t)t * HS_] = carry;
    }
    fin[gid] = carry;
}

__global__ void ema_comb_k(const float* __restrict__ fin,
                           const float* __restrict__ la_coef,
                           float* __restrict__ carry_out)
{
    const int gid = blockIdx.x * blockDim.x + threadIdx.x;
    if (gid >= B_ * C_) return;
    const int c = gid % C_;
    const int b = gid / C_;
    const float a = la_coef[c >> 6];
    const float ach = __powf(a, (float)TCH);
    float Cv = 0.0f;
    #pragma unroll
    for (int i = 0; i < NCH; i++) {
        const size_t o = ((size_t)b * NCH + i) * C_ + c;
        carry_out[o] = Cv;
        Cv = ach * Cv + fin[o];
    }
}

// ----- carry-fix + k normalize + kb scale -> bf16 hi/lo, warp per row ---------
__global__ void knorm_bf16_k(const float* __restrict__ kraw,
                             const float* __restrict__ carry,
                             const float* __restrict__ la_coef,
                             const float* __restrict__ kernel_beta,
                             __nv_bfloat16* __restrict__ kh,
                             __nv_bfloat16* __restrict__ kl)
{
    const int row = blockIdx.x * (blockDim.x >> 5) + (threadIdx.x >> 5);
    const int lane = threadIdx.x & 31;
    if (row >= B_ * NH_ * T_) return;
    const int t = row % T_;
    const int bh = row / T_;
    const int h = bh % NH_;
    const int b = bh / NH_;
    const int tl = t % TCH;
    const int chunk = t / TCH;

    const float alpha = la_coef[h];
    const float m = __powf(alpha, (float)(tl + 1));
    const float2 C2 = ((const float2*)(carry + ((size_t)b * NCH + chunk) * C_ + h * HS_))[lane];

    float2 v = ((const float2*)(kraw + (size_t)row * HS_))[lane];
    v.x += m * C2.x;
    v.y += m * C2.y;

    float ss = v.x * v.x + v.y * v.y;
    #pragma unroll
    for (int o = 16; o > 0; o >>= 1) ss += __shfl_xor_sync(0xffffffffu, ss, o);

    const float kb = expf(fminf(kernel_beta[h] * 10.0f, 5.0f));
    const float scale = kb * rsqrtf(ss);
    float o0 = v.x * scale, o1 = v.y * scale;
    __nv_bfloat16 h0 = __float2bfloat16_rn(o0), h1 = __float2bfloat16_rn(o1);
    __nv_bfloat16 l0 = __float2bfloat16_rn(o0 - __bfloat162float(h0));
    __nv_bfloat16 l1 = __float2bfloat16_rn(o1 - __bfloat162float(h1));
    ((__nv_bfloat162*)(kh + (size_t)row * HS_))[lane] = __nv_bfloat162(h0, h1);
    ((__nv_bfloat162*)(kl + (size_t)row * HS_))[lane] = __nv_bfloat162(l0, l1);
}

// ---- fused v build + normalize + vb scale + transpose -> bf16 hi/lo [d][t] ---
__global__ void __launch_bounds__(256) vmaket_k(
    const float* __restrict__ xv,
    const float* __restrict__ v_coef,
    const float* __restrict__ value_beta,
    __nv_bfloat16* __restrict__ vth, __nv_bfloat16* __restrict__ vtl)
{
    __shared__ float tile[64][65];
    const int t0 = blockIdx.x * 64;
    const int bh = blockIdx.y;
    const int h = bh % NH_;
    const int b = bh / NH_;
    const int tid = threadIdx.x;
    const int wid = tid >> 5;
    const int lane = tid & 31;

    const float c = v_coef[h];
    const float vb = expf(value_beta[h] * 10.0f);

    #pragma unroll
    for (int r = wid; r < 64; r += 8) {
        const int t = t0 + r;
        const float* cur = xv + ((size_t)b * T_ + t) * C_ + h * HS_;
        const float2 vc = ((const float2*)cur)[lane];
        float2 vn = make_float2(0.f, 0.f);
        if (t + 1 < T_) vn = ((const float2*)(cur + C_))[lane];
        float2 vv = make_float2(vn.x * (1.f - c) + vc.x * c,
                                vn.y * (1.f - c) + vc.y * c);
        float ss = vv.x * vv.x + vv.y * vv.y;
        #pragma unroll
        for (int o = 16; o > 0; o >>= 1) ss += __shfl_xor_sync(0xffffffffu, ss, o);
        const float scale = vb * rsqrtf(ss);
        tile[r][2*lane]     = vv.x * scale;
        tile[r][2*lane + 1] = vv.y * scale;
    }
    __syncthreads();

    #pragma unroll
    for (int i = tid; i < 2048; i += 256) {
        const int d = i >> 5;
        const int tt = (i & 31) * 2;
        const float x0 = tile[tt][d], x1 = tile[tt + 1][d];
        __nv_bfloat16 h0 = __float2bfloat16_rn(x0), h1 = __float2bfloat16_rn(x1);
        __nv_bfloat16 l0 = __float2bfloat16_rn(x0 - __bfloat162float(h0));
        __nv_bfloat16 l1 = __float2bfloat16_rn(x1 - __bfloat162float(h1));
        const size_t o = ((size_t)bh * HS_ + d) * T_ + t0 + tt;
        *(__nv_bfloat162*)(vth + o) = __nv_bfloat162(h0, h1);
        *(__nv_bfloat162*)(vtl + o) = __nv_bfloat162(l0, l1);
    }
}

// =========== HMMA strict-causal flash attention (q == k, bf16 split) ==========
#define AQ 128
#define AK 64
#define APAD 72
#define AMATB (AK * APAD * 2)
#define ASTG  (4 * AMATB)         // 36864 per stage
#define ASMEM (3 * ASTG)          // 110592

__global__ void __launch_bounds__(256) attn_mma_k(
    const __nv_bfloat16* __restrict__ kh, const __nv_bfloat16* __restrict__ kl,
    const __nv_bfloat16* __restrict__ vth, const __nv_bfloat16* __restrict__ vtl,
    __nv_bfloat16* __restrict__ Yh, __nv_bfloat16* __restrict__ Yl)
{
    extern __shared__ __align__(16) char asmem[];

    const int b = blockIdx.z;
    const int h = blockIdx.y;
    const int qb = gridDim.x - 1 - blockIdx.x;
    const int p0 = qb * AQ;
    const int tid = threadIdx.x;
    const int wid = tid >> 5;
    const int lane = tid & 31;
    const int g = lane >> 2, t = lane & 3;
    const int wm = wid * 16;

    const __nv_bfloat16* Kh = kh + (((size_t)b * NH_ + h) * T_) * HS_;
    const __nv_bfloat16* Kl = kl + (((size_t)b * NH_ + h) * T_) * HS_;
    const __nv_bfloat16* Vh = vth + (((size_t)b * NH_ + h) * HS_) * T_;
    const __nv_bfloat16* Vl = vtl + (((size_t)b * NH_ + h) * HS_) * T_;

    auto sKh = [&](int st, int r, int cc) { return asmem + st*ASTG + 0*AMATB + (r*APAD + cc)*2; };
    auto sKl = [&](int st, int r, int cc) { return asmem + st*ASTG + 1*AMATB + (r*APAD + cc)*2; };
    auto sVh = [&](int st, int r, int cc) { return asmem + st*ASTG + 2*AMATB + (r*APAD + cc)*2; };
    auto sVl = [&](int st, int r, int cc) { return asmem + st*ASTG + 3*AMATB + (r*APAD + cc)*2; };

    // ---- stage Q fragments using stage-0 K buffers ----
    uint32_t Qh[4][4], Ql[4][4];
    #pragma unroll
    for (int half = 0; half < 2; half++) {
        #pragma unroll
        for (int i = 0; i < 2; i++) {
            const int v = tid + i * 256;
            const int row = v >> 3, seg = (v & 7) * 8;
            *(uint4*)sKh(0, row, seg) =
                *(const uint4*)(Kh + (size_t)(p0 + half * 64 + row) * HS_ + seg);
            *(uint4*)sKl(0, row, seg) =
                *(const uint4*)(Kl + (size_t)(p0 + half * 64 + row) * HS_ + seg);
        }
        __syncthreads();
        if ((wm >> 6) == half) {
            const int lr = (wm & 63) + (lane & 15);
            #pragma unroll
            for (int ks = 0; ks < 4; ks++) {
                const int cc = ks*16 + ((lane >> 4) & 1) * 8;
                ldm_x4(Qh[ks][0], Qh[ks][1], Qh[ks][2], Qh[ks][3],
                       smem_u32(sKh(0, lr, cc)));
                ldm_x4(Ql[ks][0], Ql[ks][1], Ql[ks][2], Ql[ks][3],
                       smem_u32(sKl(0, lr, cc)));
            }
        }
        __syncthreads();
    }

    float m0 = -1e30f, m1 = -1e30f, l0 = 0.f, l1 = 0.f;
    float O[8][4];
    #pragma unroll
    for (int nj = 0; nj < 8; nj++)
        #pragma unroll
        for (int e = 0; e < 4; e++) O[nj][e] = 0.f;

    const int r0 = p0 + wm + g;
    const int r1 = r0 + 8;
    const int ntiles = (p0 + AQ) / AK;

    auto load_tile = [&](int st, int j0) {
        #pragma unroll
        for (int i = 0; i < 2; i++) {
            const int v = tid + i * 256;
            const int row = v >> 3, seg = (v & 7) * 8;
            CP_ASYNC16(smem_u32(sKh(st, row, seg)), Kh + (size_t)(j0 + row) * HS_ + seg);
            CP_ASYNC16(smem_u32(sKl(st, row, seg)), Kl + (size_t)(j0 + row) * HS_ + seg);
            CP_ASYNC16(smem_u32(sVh(st, row, seg)), Vh + (size_t)row * T_ + j0 + seg);
            CP_ASYNC16(smem_u32(sVl(st, row, seg)), Vl + (size_t)row * T_ + j0 + seg);
        }
    };

    load_tile(0, 0);
    CP_COMMIT();
    if (ntiles > 1) {
        load_tile(1, AK);
        CP_COMMIT();
    }

    #pragma unroll 1
    for (int kt = 0; kt < ntiles; kt++) {
        const int j0 = kt * AK;
        const int st = kt % 3;
        if (kt + 1 < ntiles) { CP_WAIT(1); } else { CP_WAIT(0); }
        __syncthreads();
        if (kt + 2 < ntiles) {
            load_tile((kt + 2) % 3, (kt + 2) * AK);
            CP_COMMIT();
        }

        const bool active = (j0 < p0 + wm + 16);
        if (active) {
            float S[8][4];
            #pragma unroll
            for (int nj = 0; nj < 8; nj++)
                #pragma unroll
                for (int e = 0; e < 4; e++) S[nj][e] = 0.f;

            #pragma unroll
            for (int ks = 0; ks < 4; ks++) {
                const int koff = ks * 16;
                uint32_t bh2[8][2], bl2[8][2];
                #pragma unroll
                for (int nj = 0; nj < 8; nj++) {
                    const int br = nj*8 + (lane & 7);
                    const int bc = koff + ((lane >> 3) & 1) * 8;
                    ldm_x2(bh2[nj][0], bh2[nj][1], smem_u32(sKh(st, br, bc)));
                    ldm_x2(bl2[nj][0], bl2[nj][1], smem_u32(sKl(st, br, bc)));
                }
                // same-S MMAs separated by 8 instructions
                #pragma unroll
                for (int nj = 0; nj < 8; nj++)
                    mma_bf16(S[nj], Qh[ks], bh2[nj]);
                #pragma unroll
                for (int nj = 0; nj < 8; nj++)
                    mma_bf16(S[nj], Qh[ks], bl2[nj]);
                #pragma unroll
                for (int nj = 0; nj < 8; nj++)
                    mma_bf16(S[nj], Ql[ks], bh2[nj]);
            }

            if (j0 + AK > p0 + wm) {
                #pragma unroll
                for (int nj = 0; nj < 8; nj++) {
                    const int jb = j0 + nj*8 + 2*t;
                    if (jb     >= r0) S[nj][0] = -1e30f;
                    if (jb + 1 >= r0) S[nj][1] = -1e30f;
                    if (jb     >= r1) S[nj][2] = -1e30f;
                    if (jb + 1 >= r1) S[nj][3] = -1e30f;
                }
            }

            float tm0 = -1e30f, tm1 = -1e30f;
            #pragma unroll
            for (int nj = 0; nj < 8; nj++) {
                tm0 = fmaxf(tm0, fmaxf(S[nj][0], S[nj][1]));
                tm1 = fmaxf(tm1, fmaxf(S[nj][2], S[nj][3]));
            }
            tm0 = fmaxf(tm0, __shfl_xor_sync(0xffffffffu, tm0, 1));
            tm0 = fmaxf(tm0, __shfl_xor_sync(0xffffffffu, tm0, 2));
            tm1 = fmaxf(tm1, __shfl_xor_sync(0xffffffffu, tm1, 1));
            tm1 = fmaxf(tm1, __shfl_xor_sync(0xffffffffu, tm1, 2));

            const float m0n = fmaxf(m0, tm0), m1n = fmaxf(m1, tm1);
            const float c0 = __expf(m0 - m0n), c1 = __expf(m1 - m1n);
            l0 *= c0; l1 *= c1;
            #pragma unroll
            for (int nj = 0; nj < 8; nj++) {
                O[nj][0] *= c0; O[nj][1] *= c0;
                O[nj][2] *= c1; O[nj][3] *= c1;
            }
            m0 = m0n; m1 = m1n;

            uint32_t PhA[8][2], PlA[8][2];
            float s0 = 0.f, s1 = 0.f;
            #pragma unroll
            for (int nj = 0; nj < 8; nj++) {
                float e0 = __expf(S[nj][0] - m0n), e1 = __expf(S[nj][1] - m0n);
                float e2 = __expf(S[nj][2] - m1n), e3 = __expf(S[nj][3] - m1n);
                s0 += e0 + e1; s1 += e2 + e3;
                __nv_bfloat162 h01(__float2bfloat16_rn(e0), __float2bfloat16_rn(e1));
                __nv_bfloat162 h23(__float2bfloat16_rn(e2), __float2bfloat16_rn(e3));
                PhA[nj][0] = *(uint32_t*)&h01;
                PhA[nj][1] = *(uint32_t*)&h23;
                __nv_bfloat162 q01(__float2bfloat16_rn(e0 - __bfloat162float(h01.x)),
                                   __float2bfloat16_rn(e1 - __bfloat162float(h01.y)));
                __nv_bfloat162 q23(__float2bfloat16_rn(e2 - __bfloat162float(h23.x)),
                                   __float2bfloat16_rn(e3 - __bfloat162float(h23.y)));
                PlA[nj][0] = *(uint32_t*)&q01;
                PlA[nj][1] = *(uint32_t*)&q23;
            }
            s0 += __shfl_xor_sync(0xffffffffu, s0, 1);
            s0 += __shfl_xor_sync(0xffffffffu, s0, 2);
            s1 += __shfl_xor_sync(0xffffffffu, s1, 1);
            s1 += __shfl_xor_sync(0xffffffffu, s1, 2);
            l0 += s0; l1 += s1;

            #pragma unroll
            for (int ks = 0; ks < 4; ks++) {
                const int koff = ks * 16;
                uint32_t ah[4] = {PhA[2*ks][0], PhA[2*ks][1], PhA[2*ks+1][0], PhA[2*ks+1][1]};
                uint32_t al[4] = {PlA[2*ks][0], PlA[2*ks][1], PlA[2*ks+1][0], PlA[2*ks+1][1]};
                uint32_t bv[8][2], bw[8][2];
                #pragma unroll
                for (int nj = 0; nj < 8; nj++) {
                    const int br = nj*8 + (lane & 7);
                    const int bc = koff + ((lane >> 3) & 1) * 8;
                    ldm_x2(bv[nj][0], bv[nj][1], smem_u32(sVh(st, br, bc)));
                    ldm_x2(bw[nj][0], bw[nj][1], smem_u32(sVl(st, br, bc)));
                }
                // same-O MMAs separated by 8 instructions
                #pragma unroll
                for (int nj = 0; nj < 8; nj++)
                    mma_bf16(O[nj], ah, bv[nj]);
                #pragma unroll
                for (int nj = 0; nj < 8; nj++)
                    mma_bf16(O[nj], ah, bw[nj]);
                #pragma unroll
                for (int nj = 0; nj < 8; nj++)
                    mma_bf16(O[nj], al, bv[nj]);
            }
        }
    }

    const float il0 = (r0 == 0) ? 0.f : 1.f / l0;
    const float il1 = 1.f / l1;
    __nv_bfloat16* y0h = Yh + ((size_t)b * T_ + r0) * C_ + h * HS_;
    __nv_bfloat16* y0l = Yl + ((size_t)b * T_ + r0) * C_ + h * HS_;
    __nv_bfloat16* y1h = Yh + ((size_t)b * T_ + r1) * C_ + h * HS_;
    __nv_bfloat16* y1l = Yl + ((size_t)b * T_ + r1) * C_ + h * HS_;
    #pragma unroll
    for (int nj = 0; nj < 8; nj++) {
        const int col = nj*8 + 2*t;
        float o0 = O[nj][0] * il0, o1 = O[nj][1] * il0;
        float o2 = O[nj][2] * il1, o3 = O[nj][3] * il1;
        __nv_bfloat162 h01(__float2bfloat16_rn(o0), __float2bfloat16_rn(o1));
        __nv_bfloat162 l01(__float2bfloat16_rn(o0 - __bfloat162float(h01.x)),
                           __float2bfloat16_rn(o1 - __bfloat162float(h01.y)));
        __nv_bfloat162 h23(__float2bfloat16_rn(o2), __float2bfloat16_rn(o3));
        __nv_bfloat162 l23(__float2bfloat16_rn(o2 - __bfloat162float(h23.x)),
                           __float2bfloat16_rn(o3 - __bfloat162float(h23.y)));
        *(__nv_bfloat162*)(y0h + col) = h01;
        *(__nv_bfloat162*)(y0l + col) = l01;
        *(__nv_bfloat162*)(y1h + col) = h23;
        *(__nv_bfloat162*)(y1l + col) = l23;
    }
}

// ------------------------------- launcher --------------------------------------
extern "C" void kernel_launch(void* const* d_in, const int* in_sizes, int n_in,
                              void* d_out, int out_size)
{
    const float* x           = (const float*)d_in[0];
    const float* W_la        = (const float*)d_in[1];
    const float* la_coef     = (const float*)d_in[2];
    const float* kernel_beta = (const float*)d_in[3];
    const float* value_beta  = (const float*)d_in[4];
    const float* W_v         = (const float*)d_in[5];
    const float* v_coef      = (const float*)d_in[6];
    const float* W_proj      = (const float*)d_in[7];
    float* out = (float*)d_out;

    float *xl, *xv, *kraw, *fin, *carry;
    __nv_bfloat16 *Ah, *Al, *Wla_h, *Wla_l, *Wv_h, *Wv_l, *Wp_h, *Wp_l;
    __nv_bfloat16 *kh, *kl, *vth, *vtl;
    cudaGetSymbolAddress((void**)&xl,    g_xl);
    cudaGetSymbolAddress((void**)&xv,    g_xv);
    cudaGetSymbolAddress((void**)&kraw,  g_kraw);
    cudaGetSymbolAddress((void**)&fin,   g_fin);
    cudaGetSymbolAddress((void**)&carry, g_carry);
    cudaGetSymbolAddress((void**)&Ah,    g_Ah);
    cudaGetSymbolAddress((void**)&Al,    g_Al);
    cudaGetSymbolAddress((void**)&Wla_h, g_Wla_h);
    cudaGetSymbolAddress((void**)&Wla_l, g_Wla_l);
    cudaGetSymbolAddress((void**)&Wv_h,  g_Wv_h);
    cudaGetSymbolAddress((void**)&Wv_l,  g_Wv_l);
    cudaGetSymbolAddress((void**)&Wp_h,  g_Wp_h);
    cudaGetSymbolAddress((void**)&Wp_l,  g_Wp_l);
    cudaGetSymbolAddress((void**)&kh,    g_kh);
    cudaGetSymbolAddress((void**)&kl,    g_kl);
    cudaGetSymbolAddress((void**)&vth,   g_vth);
    cudaGetSymbolAddress((void**)&vtl,   g_vtl);

    cudaFuncSetAttribute(gemm_tc_k, cudaFuncAttributeMaxDynamicSharedMemorySize, GSMEM);
    cudaFuncSetAttribute(attn_mma_k, cudaFuncAttributeMaxDynamicSharedMemorySize, ASMEM);

    const int n4 = (M_ * C_) / 4;

    split_bf16_k<<<(n4 + 255) / 256, 256>>>(x, Ah, Al, n4);
    tsplit3_k<<<dim3(32, 32, 3), dim3(32, 8)>>>(W_la, W_v, W_proj,
                                                Wla_h, Wla_l, Wv_h, Wv_l, Wp_h, Wp_l);

    // fused QKV GEMM: N-concat of W_la (-> xl) and W_v (-> xv)
    gemm_tc_k<<<dim3(2 * GNN / GBN, M_ / GBM), 256, GSMEM>>>(
        Ah, Al, Wla_h, Wla_l, Wv_h, Wv_l, xl, xv);

    ema_local_k<<<(B_*NCH*C_) / 256, 256>>>(xl, la_coef, kraw, fin);
    ema_comb_k<<<(B_*C_ + 255) / 256, 256>>>(fin, la_coef, carry);

    knorm_bf16_k<<<(B_*NH_*T_)/8, 256>>>(kraw, carry, la_coef, kernel_beta, kh, kl);
    vmaket_k<<<dim3(T_/64, B_*NH_), 256>>>(xv, v_coef, value_beta, vth, vtl);

    attn_mma_k<<<dim3(T_/AQ, NH_, B_), 256, ASMEM>>>(kh, kl, vth, vtl, Ah, Al);

    // projection GEMM (single weight): N = 1024 -> 4 n-tiles
    gemm_tc_k<<<dim3(GNN / GBN, M_ / GBM), 256, GSMEM>>>(
        Ah, Al, Wp_h, Wp_l, Wp_h, Wp_l, out, out);
}

// round 9
// speedup vs baseline: 1.3946x; 1.3946x over previous
#include <cuda_runtime.h>
#include <cuda_fp16.h>
#include <cstdint>

#define B_  2
#define T_  2048
#define NH_ 16
#define HS_ 64
#define C_  (NH_*HS_)   // 1024
#define M_  (B_*T_)     // 4096

// ======================= helpers ==============================================
__device__ __forceinline__ uint32_t smem_u32(const void* p) {
    uint32_t a;
    asm("{ .reg .u64 t; cvta.to.shared.u64 t, %1; cvt.u32.u64 %0, t; }" : "=r"(a) : "l"(p));
    return a;
}
#define CP_ASYNC16(dst_u32, src_ptr) \
    asm volatile("cp.async.cg.shared.global [%0], [%1], 16;" :: "r"(dst_u32), "l"(src_ptr))
#define CP_COMMIT() asm volatile("cp.async.commit_group;" ::: "memory")
#define CP_WAIT(n)  asm volatile("cp.async.wait_group %0;" :: "n"(n) : "memory")

__device__ __forceinline__ void ldm_x4(uint32_t& r0, uint32_t& r1, uint32_t& r2, uint32_t& r3,
                                       uint32_t addr) {
    asm volatile("ldmatrix.sync.aligned.m8n8.x4.shared.b16 {%0,%1,%2,%3}, [%4];"
                 : "=r"(r0), "=r"(r1), "=r"(r2), "=r"(r3) : "r"(addr));
}
__device__ __forceinline__ void ldm_x2(uint32_t& r0, uint32_t& r1, uint32_t addr) {
    asm volatile("ldmatrix.sync.aligned.m8n8.x2.shared.b16 {%0,%1}, [%2];"
                 : "=r"(r0), "=r"(r1) : "r"(addr));
}
__device__ __forceinline__ void mma_f16(float* c, const uint32_t* a, const uint32_t* b) {
    asm volatile(
        "mma.sync.aligned.m16n8k16.row.col.f32.f16.f16.f32 "
        "{%0,%1,%2,%3}, {%4,%5,%6,%7}, {%8,%9}, {%0,%1,%2,%3};"
        : "+f"(c[0]), "+f"(c[1]), "+f"(c[2]), "+f"(c[3])
        : "r"(a[0]), "r"(a[1]), "r"(a[2]), "r"(a[3]), "r"(b[0]), "r"(b[1]));
}

// ---------------- scratch (device globals; no allocation allowed) -------------
__device__ float g_xl[(size_t)B_*T_*C_];
__device__ float g_xv[(size_t)B_*T_*C_];
__device__ float g_kraw[(size_t)B_*NH_*T_*HS_];

#define NCH 64
#define TCH 32
__device__ float g_fin[(size_t)B_*NCH*C_];
__device__ float g_carry[(size_t)B_*NCH*C_];

__device__ __half g_Ah[(size_t)M_*C_];
__device__ __half g_Al[(size_t)M_*C_];
__device__ __half g_Wla[(size_t)C_*C_];
__device__ __half g_Wv[(size_t)C_*C_];
__device__ __half g_Wp[(size_t)C_*C_];
__device__ __half g_kh[(size_t)B_*NH_*T_*HS_];
__device__ __half g_kl[(size_t)B_*NH_*T_*HS_];
__device__ __half g_vth[(size_t)B_*NH_*HS_*T_];   // [b,h,d,t]

// ================= fp32 -> fp16 hi/lo split (no transpose) ====================
__global__ void __launch_bounds__(256) split_fp16_k(
    const float* __restrict__ X, __half* __restrict__ H,
    __half* __restrict__ L, int n4)
{
    int i = blockIdx.x * blockDim.x + threadIdx.x;
    if (i >= n4) return;
    float4 v = ((const float4*)X)[i];
    __half h0 = __float2half_rn(v.x);
    __half h1 = __float2half_rn(v.y);
    __half h2 = __float2half_rn(v.z);
    __half h3 = __float2half_rn(v.w);
    __half l0 = __float2half_rn(v.x - __half2float(h0));
    __half l1 = __float2half_rn(v.y - __half2float(h1));
    __half l2 = __float2half_rn(v.z - __half2float(h2));
    __half l3 = __float2half_rn(v.w - __half2float(h3));
    __half2* Hp = (__half2*)H;
    __half2* Lp = (__half2*)L;
    Hp[2*i]   = __half2(h0, h1);
    Hp[2*i+1] = __half2(h2, h3);
    Lp[2*i]   = __half2(l0, l1);
    Lp[2*i+1] = __half2(l2, l3);
}

// ==== batched: 3 weights fp32 [K,N] -> fp16 transposed [N,K] (no lo) ==========
__global__ void tsplit3_k(const float* __restrict__ W0, const float* __restrict__ W1,
                          const float* __restrict__ W2,
                          __half* __restrict__ T0, __half* __restrict__ T1,
                          __half* __restrict__ T2)
{
    __shared__ float tile[32][33];
    const float* W = (blockIdx.z == 0) ? W0 : (blockIdx.z == 1) ? W1 : W2;
    __half* TH = (blockIdx.z == 0) ? T0 : (blockIdx.z == 1) ? T1 : T2;
    const int n0 = blockIdx.x * 32, k0 = blockIdx.y * 32;
    const int tx = threadIdx.x, ty = threadIdx.y;  // 32 x 8
    #pragma unroll
    for (int j = ty; j < 32; j += 8)
        tile[j][tx] = W[(size_t)(k0 + j) * C_ + n0 + tx];
    __syncthreads();
    #pragma unroll
    for (int j = ty; j < 32; j += 8)
        TH[(size_t)(n0 + j) * C_ + k0 + tx] = __float2half_rn(tile[tx][j]);
}

// ===== fp16 2-pass HMMA GEMM: C = (Ah+Al) @ Bh^T, 128x256 per CTA, 3-stage ====
#define GBM 128
#define GBN 256
#define GBK 32
#define GK  1024
#define GNN 1024
#define GNK (GK / GBK)                    // 32
#define GLDS 40                           // halves per smem row
#define GA_B (GBM * GLDS * 2)             // 10240 B per A matrix tile
#define GB_B (GBN * GLDS * 2)             // 20480 B per B matrix tile
#define GSTG (2*GA_B + GB_B)              // 40960 per stage
#define GSMEM (3 * GSTG)                  // 122880

__global__ void __launch_bounds__(256, 1) gemm_tc_k(
    const __half* __restrict__ Ah, const __half* __restrict__ Al,
    const __half* __restrict__ W1, const __half* __restrict__ W2,
    float* __restrict__ C1, float* __restrict__ C2)
{
    extern __shared__ __align__(16) char gsm[];

    const int n0g = blockIdx.x * GBN;
    const bool sel = (n0g >= GNN);
    const int n0 = sel ? (n0g - GNN) : n0g;
    const __half* Bm = sel ? W2 : W1;
    float* Cg = sel ? C2 : C1;

    const int m0 = blockIdx.y * GBM;
    const int tid  = threadIdx.x;
    const int wid  = tid >> 5;
    const int lane = tid & 31;
    const int wm = (wid >> 2) * 64;   // 0 or 64
    const int wn = (wid & 3) * 64;    // 0..192

    float acc[4][8][4];
    #pragma unroll
    for (int i = 0; i < 4; i++)
        #pragma unroll
        for (int j = 0; j < 8; j++)
            #pragma unroll
            for (int e = 0; e < 4; e++) acc[i][j][e] = 0.f;

    auto load_tile = [&](int stage, int kc) {
        const int k0 = kc * GBK;
        char* base = gsm + stage * GSTG;
        #pragma unroll
        for (int i = 0; i < 2; i++) {
            const int idx = tid + i * 256;
            const int row = idx >> 2;
            const int c8  = (idx & 3) * 8;
            const uint32_t so = (uint32_t)(row * GLDS + c8) * 2;
            CP_ASYNC16(smem_u32(base + so),        Ah + (size_t)(m0 + row) * GK + k0 + c8);
            CP_ASYNC16(smem_u32(base + GA_B + so), Al + (size_t)(m0 + row) * GK + k0 + c8);
        }
        #pragma unroll
        for (int i = 0; i < 4; i++) {
            const int idx = tid + i * 256;
            const int row = idx >> 2;
            const int c8  = (idx & 3) * 8;
            const uint32_t so = (uint32_t)(row * GLDS + c8) * 2;
            CP_ASYNC16(smem_u32(base + 2*GA_B + so), Bm + (size_t)(n0 + row) * GK + k0 + c8);
        }
    };

    load_tile(0, 0);
    CP_COMMIT();
    load_tile(1, 1);
    CP_COMMIT();

    #pragma unroll 1
    for (int kc = 0; kc < GNK; kc++) {
        const int st = kc % 3;
        if (kc + 1 < GNK) { CP_WAIT(1); } else { CP_WAIT(0); }
        __syncthreads();
        if (kc + 2 < GNK) {
            load_tile((kc + 2) % 3, kc + 2);
            CP_COMMIT();
        }

        char* base = gsm + st * GSTG;
        char* bA_h = base;
        char* bA_l = base + GA_B;
        char* bB   = base + 2*GA_B;

        #pragma unroll
        for (int ks = 0; ks < 2; ks++) {
            const int koff = ks * 16;
            uint32_t b2[8][2];
            #pragma unroll
            for (int nj = 0; nj < 8; nj++) {
                const int brow = wn + nj*8 + (lane & 7);
                const int bcol = koff + ((lane >> 3) & 1) * 8;
                ldm_x2(b2[nj][0], b2[nj][1], smem_u32(bB + (brow * GLDS + bcol) * 2));
            }
            #pragma unroll
            for (int mi = 0; mi < 4; mi++) {
                const int arow = wm + mi*16 + (lane & 15);
                const int acol = koff + ((lane >> 4) & 1) * 8;
                uint32_t a4h[4], a4l[4];
                ldm_x4(a4h[0], a4h[1], a4h[2], a4h[3],
                       smem_u32(bA_h + (arow * GLDS + acol) * 2));
                ldm_x4(a4l[0], a4l[1], a4l[2], a4l[3],
                       smem_u32(bA_l + (arow * GLDS + acol) * 2));
                #pragma unroll
                for (int nj = 0; nj < 8; nj++)
                    mma_f16(acc[mi][nj], a4h, b2[nj]);
                #pragma unroll
                for (int nj = 0; nj < 8; nj++)
                    mma_f16(acc[mi][nj], a4l, b2[nj]);
            }
        }
    }

    const int g = lane >> 2, t = lane & 3;
    #pragma unroll
    for (int mi = 0; mi < 4; mi++) {
        float* row0 = Cg + (size_t)(m0 + wm + mi*16 + g)     * GNN + n0 + wn;
        float* row1 = Cg + (size_t)(m0 + wm + mi*16 + g + 8) * GNN + n0 + wn;
        #pragma unroll
        for (int nj = 0; nj < 8; nj++) {
            *(float2*)(row0 + nj*8 + t*2) = make_float2(acc[mi][nj][0], acc[mi][nj][1]);
            *(float2*)(row1 + nj*8 + t*2) = make_float2(acc[mi][nj][2], acc[mi][nj][3]);
        }
    }
}

// ============== EMA scan: chunked parallel (local scan + combine) =============
__global__ void __launch_bounds__(256) ema_local_k(
    const float* __restrict__ xl, const float* __restrict__ la_coef,
    float* __restrict__ kraw, float* __restrict__ fin)
{
    const int gid = blockIdx.x * blockDim.x + threadIdx.x;
    if (gid >= B_ * NCH * C_) return;
    const int c = gid % C_;
    const int rest = gid / C_;
    const int chunk = rest % NCH;
    const int b = rest / NCH;
    const int h = c >> 6, d = c & 63;

    const float a = la_coef[h];
    const float onem = 1.0f - a;
    float carry = 0.0f;

    const float* src = xl + ((size_t)b * T_ + chunk * TCH) * C_ + c;
    float* dst = kraw + (((size_t)b * NH_ + h) * T_ + chunk * TCH) * HS_ + d;

    #pragma unroll 4
    for (int t = 0; t < TCH; t++) {
        carry = a * carry + onem * src[(size_t)t * C_];
        dst[(size_t)t * HS_] = carry;
    }
    fin[gid] = carry;
}

__global__ void ema_comb_k(const float* __restrict__ fin,
                           const float* __restrict__ la_coef,
                           float* __restrict__ carry_out)
{
    const int gid = blockIdx.x * blockDim.x + threadIdx.x;
    if (gid >= B_ * C_) return;
    const int c = gid % C_;
    const int b = gid / C_;
    const float a = la_coef[c >> 6];
    const float ach = __powf(a, (float)TCH);
    float Cv = 0.0f;
    #pragma unroll
    for (int i = 0; i < NCH; i++) {
        const size_t o = ((size_t)b * NCH + i) * C_ + c;
        carry_out[o] = Cv;
        Cv = ach * Cv + fin[o];
    }
}

// ----- carry-fix + k normalize + kb scale -> fp16 hi/lo, warp per row ---------
__global__ void knorm_fp16_k(const float* __restrict__ kraw,
                             const float* __restrict__ carry,
                             const float* __restrict__ la_coef,
                             const float* __restrict__ kernel_beta,
                             __half* __restrict__ kh,
                             __half* __restrict__ kl)
{
    const int row = blockIdx.x * (blockDim.x >> 5) + (threadIdx.x >> 5);
    const int lane = threadIdx.x & 31;
    if (row >= B_ * NH_ * T_) return;
    const int t = row % T_;
    const int bh = row / T_;
    const int h = bh % NH_;
    const int b = bh / NH_;
    const int tl = t % TCH;
    const int chunk = t / TCH;

    const float alpha = la_coef[h];
    const float m = __powf(alpha, (float)(tl + 1));
    const float2 C2 = ((const float2*)(carry + ((size_t)b * NCH + chunk) * C_ + h * HS_))[lane];

    float2 v = ((const float2*)(kraw + (size_t)row * HS_))[lane];
    v.x += m * C2.x;
    v.y += m * C2.y;

    float ss = v.x * v.x + v.y * v.y;
    #pragma unroll
    for (int o = 16; o > 0; o >>= 1) ss += __shfl_xor_sync(0xffffffffu, ss, o);

    const float kb = expf(fminf(kernel_beta[h] * 10.0f, 5.0f));
    const float scale = kb * rsqrtf(ss);
    float o0 = v.x * scale, o1 = v.y * scale;
    __half h0 = __float2half_rn(o0), h1 = __float2half_rn(o1);
    __half l0 = __float2half_rn(o0 - __half2float(h0));
    __half l1 = __float2half_rn(o1 - __half2float(h1));
    ((__half2*)(kh + (size_t)row * HS_))[lane] = __half2(h0, h1);
    ((__half2*)(kl + (size_t)row * HS_))[lane] = __half2(l0, l1);
}

// ---- fused v build + normalize + vb scale + transpose -> fp16 [d][t] ---------
__global__ void __launch_bounds__(256) vmaket_k(
    const float* __restrict__ xv,
    const float* __restrict__ v_coef,
    const float* __restrict__ value_beta,
    __half* __restrict__ vth)
{
    __shared__ float tile[64][65];
    const int t0 = blockIdx.x * 64;
    const int bh = blockIdx.y;
    const int h = bh % NH_;
    const int b = bh / NH_;
    const int tid = threadIdx.x;
    const int wid = tid >> 5;
    const int lane = tid & 31;

    const float c = v_coef[h];
    const float vb = expf(value_beta[h] * 10.0f);

    #pragma unroll
    for (int r = wid; r < 64; r += 8) {
        const int t = t0 + r;
        const float* cur = xv + ((size_t)b * T_ + t) * C_ + h * HS_;
        const float2 vc = ((const float2*)cur)[lane];
        float2 vn = make_float2(0.f, 0.f);
        if (t + 1 < T_) vn = ((const float2*)(cur + C_))[lane];
        float2 vv = make_float2(vn.x * (1.f - c) + vc.x * c,
                                vn.y * (1.f - c) + vc.y * c);
        float ss = vv.x * vv.x + vv.y * vv.y;
        #pragma unroll
        for (int o = 16; o > 0; o >>= 1) ss += __shfl_xor_sync(0xffffffffu, ss, o);
        const float scale = vb * rsqrtf(ss);
        tile[r][2*lane]     = vv.x * scale;
        tile[r][2*lane + 1] = vv.y * scale;
    }
    __syncthreads();

    #pragma unroll
    for (int i = tid; i < 2048; i += 256) {
        const int d = i >> 5;
        const int tt = (i & 31) * 2;
        const float x0 = tile[tt][d], x1 = tile[tt + 1][d];
        const size_t o = ((size_t)bh * HS_ + d) * T_ + t0 + tt;
        *(__half2*)(vth + o) = __half2(__float2half_rn(x0), __float2half_rn(x1));
    }
}

// ====== fp16 2-pass HMMA strict-causal flash attention (q == k) ===============
// S = (Qh+Ql) @ Kh^T ; O = (Ph+Pl) @ Vh. Stage = {Kh, Vh}, 3-stage cp.async.
#define AQ 128
#define AK 64
#define APAD 72
#define AMATB (AK * APAD * 2)     // 9216
#define ASTG  (2 * AMATB)         // 18432 per stage
#define ASMEM (3 * ASTG)          // 55296

__global__ void __launch_bounds__(256) attn_mma_k(
    const __half* __restrict__ kh, const __half* __restrict__ kl,
    const __half* __restrict__ vth,
    __half* __restrict__ Yh, __half* __restrict__ Yl)
{
    extern __shared__ __align__(16) char asmem[];

    const int b = blockIdx.z;
    const int h = blockIdx.y;
    const int qb = gridDim.x - 1 - blockIdx.x;
    const int p0 = qb * AQ;
    const int tid = threadIdx.x;
    const int wid = tid >> 5;
    const int lane = tid & 31;
    const int g = lane >> 2, t = lane & 3;
    const int wm = wid * 16;

    const __half* Kh = kh + (((size_t)b * NH_ + h) * T_) * HS_;
    const __half* Kl = kl + (((size_t)b * NH_ + h) * T_) * HS_;
    const __half* Vh = vth + (((size_t)b * NH_ + h) * HS_) * T_;

    auto sK = [&](int st, int r, int cc) { return asmem + st*ASTG + (r*APAD + cc)*2; };
    auto sV = [&](int st, int r, int cc) { return asmem + st*ASTG + AMATB + (r*APAD + cc)*2; };

    // ---- stage Q fragments (Kh -> sK(0), Kl -> sV(0) slot reuse) ----
    uint32_t Qh[4][4], Ql[4][4];
    #pragma unroll
    for (int half = 0; half < 2; half++) {
        #pragma unroll
        for (int i = 0; i < 2; i++) {
            const int v = tid + i * 256;
            const int row = v >> 3, seg = (v & 7) * 8;
            *(uint4*)sK(0, row, seg) =
                *(const uint4*)(Kh + (size_t)(p0 + half * 64 + row) * HS_ + seg);
            *(uint4*)sV(0, row, seg) =
                *(const uint4*)(Kl + (size_t)(p0 + half * 64 + row) * HS_ + seg);
        }
        __syncthreads();
        if ((wm >> 6) == half) {
            const int lr = (wm & 63) + (lane & 15);
            #pragma unroll
            for (int ks = 0; ks < 4; ks++) {
                const int cc = ks*16 + ((lane >> 4) & 1) * 8;
                ldm_x4(Qh[ks][0], Qh[ks][1], Qh[ks][2], Qh[ks][3],
                       smem_u32(sK(0, lr, cc)));
                ldm_x4(Ql[ks][0], Ql[ks][1], Ql[ks][2], Ql[ks][3],
                       smem_u32(sV(0, lr, cc)));
            }
        }
        __syncthreads();
    }

    float m0 = -1e30f, m1 = -1e30f, l0 = 0.f, l1 = 0.f;
    float O[8][4];
    #pragma unroll
    for (int nj = 0; nj < 8; nj++)
        #pragma unroll
        for (int e = 0; e < 4; e++) O[nj][e] = 0.f;

    const int r0 = p0 + wm + g;
    const int r1 = r0 + 8;
    const int ntiles = (p0 + AQ) / AK;

    auto load_tile = [&](int st, int j0) {
        #pragma unroll
        for (int i = 0; i < 2; i++) {
            const int v = tid + i * 256;
            const int row = v >> 3, seg = (v & 7) * 8;
            CP_ASYNC16(smem_u32(sK(st, row, seg)), Kh + (size_t)(j0 + row) * HS_ + seg);
            CP_ASYNC16(smem_u32(sV(st, row, seg)), Vh + (size_t)row * T_ + j0 + seg);
        }
    };

    load_tile(0, 0);
    CP_COMMIT();
    if (ntiles > 1) {
        load_tile(1, AK);
        CP_COMMIT();
    }

    #pragma unroll 1
    for (int kt = 0; kt < ntiles; kt++) {
        const int j0 = kt * AK;
        const int st = kt % 3;
        if (kt + 1 < ntiles) { CP_WAIT(1); } else { CP_WAIT(0); }
        __syncthreads();
        if (kt + 2 < ntiles) {
            load_tile((kt + 2) % 3, (kt + 2) * AK);
            CP_COMMIT();
        }

        const bool active = (j0 < p0 + wm + 16);
        if (active) {
            float S[8][4];
            #pragma unroll
            for (int nj = 0; nj < 8; nj++)
                #pragma unroll
                for (int e = 0; e < 4; e++) S[nj][e] = 0.f;

            #pragma unroll
            for (int ks = 0; ks < 4; ks++) {
                const int koff = ks * 16;
                uint32_t b2[8][2];
                #pragma unroll
                for (int nj = 0; nj < 8; nj++) {
                    const int br = nj*8 + (lane & 7);
                    const int bc = koff + ((lane >> 3) & 1) * 8;
                    ldm_x2(b2[nj][0], b2[nj][1], smem_u32(sK(st, br, bc)));
                }
                #pragma unroll
                for (int nj = 0; nj < 8; nj++)
                    mma_f16(S[nj], Qh[ks], b2[nj]);
                #pragma unroll
                for (int nj = 0; nj < 8; nj++)
                    mma_f16(S[nj], Ql[ks], b2[nj]);
            }

            if (j0 + AK > p0 + wm) {
                #pragma unroll
                for (int nj = 0; nj < 8; nj++) {
                    const int jb = j0 + nj*8 + 2*t;
                    if (jb     >= r0) S[nj][0] = -1e30f;
                    if (jb + 1 >= r0) S[nj][1] = -1e30f;
                    if (jb     >= r1) S[nj][2] = -1e30f;
                    if (jb + 1 >= r1) S[nj][3] = -1e30f;
                }
            }

            float tm0 = -1e30f, tm1 = -1e30f;
            #pragma unroll
            for (int nj = 0; nj < 8; nj++) {
                tm0 = fmaxf(tm0, fmaxf(S[nj][0], S[nj][1]));
                tm1 = fmaxf(tm1, fmaxf(S[nj][2], S[nj][3]));
            }
            tm0 = fmaxf(tm0, __shfl_xor_sync(0xffffffffu, tm0, 1));
            tm0 = fmaxf(tm0, __shfl_xor_sync(0xffffffffu, tm0, 2));
            tm1 = fmaxf(tm1, __shfl_xor_sync(0xffffffffu, tm1, 1));
            tm1 = fmaxf(tm1, __shfl_xor_sync(0xffffffffu, tm1, 2));

            const float m0n = fmaxf(m0, tm0), m1n = fmaxf(m1, tm1);
            const float c0 = __expf(m0 - m0n), c1 = __expf(m1 - m1n);
            l0 *= c0; l1 *= c1;
            #pragma unroll
            for (int nj = 0; nj < 8; nj++) {
                O[nj][0] *= c0; O[nj][1] *= c0;
                O[nj][2] *= c1; O[nj][3] *= c1;
            }
            m0 = m0n; m1 = m1n;

            uint32_t PhA[8][2], PlA[8][2];
            float s0 = 0.f, s1 = 0.f;
            #pragma unroll
            for (int nj = 0; nj < 8; nj++) {
                float e0 = __expf(S[nj][0] - m0n), e1 = __expf(S[nj][1] - m0n);
                float e2 = __expf(S[nj][2] - m1n), e3 = __expf(S[nj][3] - m1n);
                s0 += e0 + e1; s1 += e2 + e3;
                __half2 h01(__float2half_rn(e0), __float2half_rn(e1));
                __half2 h23(__float2half_rn(e2), __float2half_rn(e3));
                PhA[nj][0] = *(uint32_t*)&h01;
                PhA[nj][1] = *(uint32_t*)&h23;
                __half2 q01(__float2half_rn(e0 - __half2float(h01.x)),
                            __float2half_rn(e1 - __half2float(h01.y)));
                __half2 q23(__float2half_rn(e2 - __half2float(h23.x)),
                            __float2half_rn(e3 - __half2float(h23.y)));
                PlA[nj][0] = *(uint32_t*)&q01;
                PlA[nj][1] = *(uint32_t*)&q23;
            }
            s0 += __shfl_xor_sync(0xffffffffu, s0, 1);
            s0 += __shfl_xor_sync(0xffffffffu, s0, 2);
            s1 += __shfl_xor_sync(0xffffffffu, s1, 1);
            s1 += __shfl_xor_sync(0xffffffffu, s1, 2);
            l0 += s0; l1 += s1;

            #pragma unroll
            for (int ks = 0; ks < 4; ks++) {
                const int koff = ks * 16;
                uint32_t ah[4] = {PhA[2*ks][0], PhA[2*ks][1], PhA[2*ks+1][0], PhA[2*ks+1][1]};
                uint32_t al[4] = {PlA[2*ks][0], PlA[2*ks][1], PlA[2*ks+1][0], PlA[2*ks+1][1]};
                uint32_t bv[8][2];
                #pragma unroll
                for (int nj = 0; nj < 8; nj++) {
                    const int br = nj*8 + (lane & 7);
                    const int bc = koff + ((lane >> 3) & 1) * 8;
                    ldm_x2(bv[nj][0], bv[nj][1], smem_u32(sV(st, br, bc)));
                }
                #pragma unroll
                for (int nj = 0; nj < 8; nj++)
                    mma_f16(O[nj], ah, bv[nj]);
                #pragma unroll
                for (int nj = 0; nj < 8; nj++)
                    mma_f16(O[nj], al, bv[nj]);
            }
        }
    }

    const float il0 = (r0 == 0) ? 0.f : 1.f / l0;
    const float il1 = 1.f / l1;
    __half* y0h = Yh + ((size_t)b * T_ + r0) * C_ + h * HS_;
    __half* y0l = Yl + ((size_t)b * T_ + r0) * C_ + h * HS_;
    __half* y1h = Yh + ((size_t)b * T_ + r1) * C_ + h * HS_;
    __half* y1l = Yl + ((size_t)b * T_ + r1) * C_ + h * HS_;
    #pragma unroll
    for (int nj = 0; nj < 8; nj++) {
        const int col = nj*8 + 2*t;
        float o0 = O[nj][0] * il0, o1 = O[nj][1] * il0;
        float o2 = O[nj][2] * il1, o3 = O[nj][3] * il1;
        __half2 h01(__float2half_rn(o0), __float2half_rn(o1));
        __half2 l01(__float2half_rn(o0 - __half2float(h01.x)),
                    __float2half_rn(o1 - __half2float(h01.y)));
        __half2 h23(__float2half_rn(o2), __float2half_rn(o3));
        __half2 l23(__float2half_rn(o2 - __half2float(h23.x)),
                    __float2half_rn(o3 - __half2float(h23.y)));
        *(__half2*)(y0h + col) = h01;
        *(__half2*)(y0l + col) = l01;
        *(__half2*)(y1h + col) = h23;
        *(__half2*)(y1l + col) = l23;
    }
}

// ------------------------------- launcher --------------------------------------
extern "C" void kernel_launch(void* const* d_in, const int* in_sizes, int n_in,
                              void* d_out, int out_size)
{
    const float* x           = (const float*)d_in[0];
    const float* W_la        = (const float*)d_in[1];
    const float* la_coef     = (const float*)d_in[2];
    const float* kernel_beta = (const float*)d_in[3];
    const float* value_beta  = (const float*)d_in[4];
    const float* W_v         = (const float*)d_in[5];
    const float* v_coef      = (const float*)d_in[6];
    const float* W_proj      = (const float*)d_in[7];
    float* out = (float*)d_out;

    float *xl, *xv, *kraw, *fin, *carry;
    __half *Ah, *Al, *Wla, *Wv, *Wp, *kh, *kl, *vth;
    cudaGetSymbolAddress((void**)&xl,    g_xl);
    cudaGetSymbolAddress((void**)&xv,    g_xv);
    cudaGetSymbolAddress((void**)&kraw,  g_kraw);
    cudaGetSymbolAddress((void**)&fin,   g_fin);
    cudaGetSymbolAddress((void**)&carry, g_carry);
    cudaGetSymbolAddress((void**)&Ah,    g_Ah);
    cudaGetSymbolAddress((void**)&Al,    g_Al);
    cudaGetSymbolAddress((void**)&Wla,   g_Wla);
    cudaGetSymbolAddress((void**)&Wv,    g_Wv);
    cudaGetSymbolAddress((void**)&Wp,    g_Wp);
    cudaGetSymbolAddress((void**)&kh,    g_kh);
    cudaGetSymbolAddress((void**)&kl,    g_kl);
    cudaGetSymbolAddress((void**)&vth,   g_vth);

    cudaFuncSetAttribute(gemm_tc_k, cudaFuncAttributeMaxDynamicSharedMemorySize, GSMEM);
    cudaFuncSetAttribute(attn_mma_k, cudaFuncAttributeMaxDynamicSharedMemorySize, ASMEM);

    const int n4 = (M_ * C_) / 4;

    split_fp16_k<<<(n4 + 255) / 256, 256>>>(x, Ah, Al, n4);
    tsplit3_k<<<dim3(32, 32, 3), dim3(32, 8)>>>(W_la, W_v, W_proj, Wla, Wv, Wp);

    // fused QKV GEMM: N-concat of W_la (-> xl) and W_v (-> xv)
    gemm_tc_k<<<dim3(2 * GNN / GBN, M_ / GBM), 256, GSMEM>>>(
        Ah, Al, Wla, Wv, xl, xv);

    ema_local_k<<<(B_*NCH*C_) / 256, 256>>>(xl, la_coef, kraw, fin);
    ema_comb_k<<<(B_*C_ + 255) / 256, 256>>>(fin, la_coef, carry);

    knorm_fp16_k<<<(B_*NH_*T_)/8, 256>>>(kraw, carry, la_coef, kernel_beta, kh, kl);
    vmaket_k<<<dim3(T_/64, B_*NH_), 256>>>(xv, v_coef, value_beta, vth);

    attn_mma_k<<<dim3(T_/AQ, NH_, B_), 256, ASMEM>>>(kh, kl, vth, Ah, Al);

    // projection GEMM (single weight): N = 1024 -> 4 n-tiles
    gemm_tc_k<<<dim3(GNN / GBN, M_ / GBM), 256, GSMEM>>>(
        Ah, Al, Wp, Wp, out, out);
}

// round 10
// speedup vs baseline: 1.9776x; 1.4180x over previous
#include <cuda_runtime.h>
#include <cuda_fp16.h>
#include <cstdint>

#define B_  2
#define T_  2048
#define NH_ 16
#define HS_ 64
#define C_  (NH_*HS_)   // 1024
#define M_  (B_*T_)     // 4096

// ======================= helpers ==============================================
__device__ __forceinline__ uint32_t smem_u32(const void* p) {
    uint32_t a;
    asm("{ .reg .u64 t; cvta.to.shared.u64 t, %1; cvt.u32.u64 %0, t; }" : "=r"(a) : "l"(p));
    return a;
}
#define CP_ASYNC16(dst_u32, src_ptr) \
    asm volatile("cp.async.cg.shared.global [%0], [%1], 16;" :: "r"(dst_u32), "l"(src_ptr))
#define CP_COMMIT() asm volatile("cp.async.commit_group;" ::: "memory")
#define CP_WAIT(n)  asm volatile("cp.async.wait_group %0;" :: "n"(n) : "memory")

__device__ __forceinline__ void ldm_x4(uint32_t& r0, uint32_t& r1, uint32_t& r2, uint32_t& r3,
                                       uint32_t addr) {
    asm volatile("ldmatrix.sync.aligned.m8n8.x4.shared.b16 {%0,%1,%2,%3}, [%4];"
                 : "=r"(r0), "=r"(r1), "=r"(r2), "=r"(r3) : "r"(addr));
}
__device__ __forceinline__ void ldm_x2(uint32_t& r0, uint32_t& r1, uint32_t addr) {
    asm volatile("ldmatrix.sync.aligned.m8n8.x2.shared.b16 {%0,%1}, [%2];"
                 : "=r"(r0), "=r"(r1) : "r"(addr));
}
__device__ __forceinline__ void mma_f16(float* c, const uint32_t* a, const uint32_t* b) {
    asm volatile(
        "mma.sync.aligned.m16n8k16.row.col.f32.f16.f16.f32 "
        "{%0,%1,%2,%3}, {%4,%5,%6,%7}, {%8,%9}, {%0,%1,%2,%3};"
        : "+f"(c[0]), "+f"(c[1]), "+f"(c[2]), "+f"(c[3])
        : "r"(a[0]), "r"(a[1]), "r"(a[2]), "r"(a[3]), "r"(b[0]), "r"(b[1]));
}

// ---------------- scratch (device globals; no allocation allowed) -------------
__device__ float g_xl[(size_t)B_*T_*C_];
__device__ float g_xv[(size_t)B_*T_*C_];
__device__ float g_kraw[(size_t)B_*NH_*T_*HS_];

#define NCH 64
#define TCH 32
__device__ float g_fin[(size_t)B_*NCH*C_];
__device__ float g_carry[(size_t)B_*NCH*C_];

__device__ __half g_A[(size_t)M_*C_];
__device__ __half g_Wla[(size_t)C_*C_];
__device__ __half g_Wv[(size_t)C_*C_];
__device__ __half g_Wp[(size_t)C_*C_];
__device__ __half g_kh[(size_t)B_*NH_*T_*HS_];
__device__ __half g_vth[(size_t)B_*NH_*HS_*T_];   // [b,h,d,t]

// ================= fp32 -> fp16 convert (no transpose) ========================
__global__ void __launch_bounds__(256) conv_fp16_k(
    const float* __restrict__ X, __half* __restrict__ H, int n4)
{
    int i = blockIdx.x * blockDim.x + threadIdx.x;
    if (i >= n4) return;
    float4 v = ((const float4*)X)[i];
    __half2* Hp = (__half2*)H;
    Hp[2*i]   = __half2(__float2half_rn(v.x), __float2half_rn(v.y));
    Hp[2*i+1] = __half2(__float2half_rn(v.z), __float2half_rn(v.w));
}

// ==== batched: 3 weights fp32 [K,N] -> fp16 transposed [N,K] ==================
__global__ void tsplit3_k(const float* __restrict__ W0, const float* __restrict__ W1,
                          const float* __restrict__ W2,
                          __half* __restrict__ T0, __half* __restrict__ T1,
                          __half* __restrict__ T2)
{
    __shared__ float tile[32][33];
    const float* W = (blockIdx.z == 0) ? W0 : (blockIdx.z == 1) ? W1 : W2;
    __half* TH = (blockIdx.z == 0) ? T0 : (blockIdx.z == 1) ? T1 : T2;
    const int n0 = blockIdx.x * 32, k0 = blockIdx.y * 32;
    const int tx = threadIdx.x, ty = threadIdx.y;  // 32 x 8
    #pragma unroll
    for (int j = ty; j < 32; j += 8)
        tile[j][tx] = W[(size_t)(k0 + j) * C_ + n0 + tx];
    __syncthreads();
    #pragma unroll
    for (int j = ty; j < 32; j += 8)
        TH[(size_t)(n0 + j) * C_ + k0 + tx] = __float2half_rn(tile[tx][j]);
}

// ===== fp16 1-pass HMMA GEMM: C = A @ B^T, 128x256 per CTA, 3-stage ===========
#define GBM 128
#define GBN 256
#define GBK 32
#define GK  1024
#define GNN 1024
#define GNK (GK / GBK)                    // 32
#define GLDS 40                           // halves per smem row
#define GA_B (GBM * GLDS * 2)             // 10240 B per A matrix tile
#define GB_B (GBN * GLDS * 2)             // 20480 B per B matrix tile
#define GSTG (GA_B + GB_B)                // 30720 per stage
#define GSMEM (3 * GSTG)                  // 92160

__global__ void __launch_bounds__(256, 1) gemm_tc_k(
    const __half* __restrict__ A,
    const __half* __restrict__ W1, const __half* __restrict__ W2,
    float* __restrict__ C1, float* __restrict__ C2)
{
    extern __shared__ __align__(16) char gsm[];

    const int n0g = blockIdx.x * GBN;
    const bool sel = (n0g >= GNN);
    const int n0 = sel ? (n0g - GNN) : n0g;
    const __half* Bm = sel ? W2 : W1;
    float* Cg = sel ? C2 : C1;

    const int m0 = blockIdx.y * GBM;
    const int tid  = threadIdx.x;
    const int wid  = tid >> 5;
    const int lane = tid & 31;
    const int wm = (wid >> 2) * 64;   // 0 or 64
    const int wn = (wid & 3) * 64;    // 0..192

    float acc[4][8][4];
    #pragma unroll
    for (int i = 0; i < 4; i++)
        #pragma unroll
        for (int j = 0; j < 8; j++)
            #pragma unroll
            for (int e = 0; e < 4; e++) acc[i][j][e] = 0.f;

    auto load_tile = [&](int stage, int kc) {
        const int k0 = kc * GBK;
        char* base = gsm + stage * GSTG;
        #pragma unroll
        for (int i = 0; i < 2; i++) {
            const int idx = tid + i * 256;
            const int row = idx >> 2;
            const int c8  = (idx & 3) * 8;
            const uint32_t so = (uint32_t)(row * GLDS + c8) * 2;
            CP_ASYNC16(smem_u32(base + so), A + (size_t)(m0 + row) * GK + k0 + c8);
        }
        #pragma unroll
        for (int i = 0; i < 4; i++) {
            const int idx = tid + i * 256;
            const int row = idx >> 2;
            const int c8  = (idx & 3) * 8;
            const uint32_t so = (uint32_t)(row * GLDS + c8) * 2;
            CP_ASYNC16(smem_u32(base + GA_B + so), Bm + (size_t)(n0 + row) * GK + k0 + c8);
        }
    };

    load_tile(0, 0);
    CP_COMMIT();
    load_tile(1, 1);
    CP_COMMIT();

    #pragma unroll 1
    for (int kc = 0; kc < GNK; kc++) {
        const int st = kc % 3;
        if (kc + 1 < GNK) { CP_WAIT(1); } else { CP_WAIT(0); }
        __syncthreads();
        if (kc + 2 < GNK) {
            load_tile((kc + 2) % 3, kc + 2);
            CP_COMMIT();
        }

        char* base = gsm + st * GSTG;
        char* bA = base;
        char* bB = base + GA_B;

        #pragma unroll
        for (int ks = 0; ks < 2; ks++) {
            const int koff = ks * 16;
            uint32_t b2[8][2];
            #pragma unroll
            for (int nj = 0; nj < 8; nj++) {
                const int brow = wn + nj*8 + (lane & 7);
                const int bcol = koff + ((lane >> 3) & 1) * 8;
                ldm_x2(b2[nj][0], b2[nj][1], smem_u32(bB + (brow * GLDS + bcol) * 2));
            }
            #pragma unroll
            for (int mi = 0; mi < 4; mi++) {
                const int arow = wm + mi*16 + (lane & 15);
                const int acol = koff + ((lane >> 4) & 1) * 8;
                uint32_t a4[4];
                ldm_x4(a4[0], a4[1], a4[2], a4[3],
                       smem_u32(bA + (arow * GLDS + acol) * 2));
                #pragma unroll
                for (int nj = 0; nj < 8; nj++)
                    mma_f16(acc[mi][nj], a4, b2[nj]);
            }
        }
    }

    const int g = lane >> 2, t = lane & 3;
    #pragma unroll
    for (int mi = 0; mi < 4; mi++) {
        float* row0 = Cg + (size_t)(m0 + wm + mi*16 + g)     * GNN + n0 + wn;
        float* row1 = Cg + (size_t)(m0 + wm + mi*16 + g + 8) * GNN + n0 + wn;
        #pragma unroll
        for (int nj = 0; nj < 8; nj++) {
            *(float2*)(row0 + nj*8 + t*2) = make_float2(acc[mi][nj][0], acc[mi][nj][1]);
            *(float2*)(row1 + nj*8 + t*2) = make_float2(acc[mi][nj][2], acc[mi][nj][3]);
        }
    }
}

// ============== EMA scan: chunked parallel (local scan + combine) =============
__global__ void __launch_bounds__(256) ema_local_k(
    const float* __restrict__ xl, const float* __restrict__ la_coef,
    float* __restrict__ kraw, float* __restrict__ fin)
{
    const int gid = blockIdx.x * blockDim.x + threadIdx.x;
    if (gid >= B_ * NCH * C_) return;
    const int c = gid % C_;
    const int rest = gid / C_;
    const int chunk = rest % NCH;
    const int b = rest / NCH;
    const int h = c >> 6, d = c & 63;

    const float a = la_coef[h];
    const float onem = 1.0f - a;
    float carry = 0.0f;

    const float* src = xl + ((size_t)b * T_ + chunk * TCH) * C_ + c;
    float* dst = kraw + (((size_t)b * NH_ + h) * T_ + chunk * TCH) * HS_ + d;

    #pragma unroll 4
    for (int t = 0; t < TCH; t++) {
        carry = a * carry + onem * src[(size_t)t * C_];
        dst[(size_t)t * HS_] = carry;
    }
    fin[gid] = carry;
}

__global__ void ema_comb_k(const float* __restrict__ fin,
                           const float* __restrict__ la_coef,
                           float* __restrict__ carry_out)
{
    const int gid = blockIdx.x * blockDim.x + threadIdx.x;
    if (gid >= B_ * C_) return;
    const int c = gid % C_;
    const int b = gid / C_;
    const float a = la_coef[c >> 6];
    const float ach = __powf(a, (float)TCH);
    float Cv = 0.0f;
    #pragma unroll
    for (int i = 0; i < NCH; i++) {
        const size_t o = ((size_t)b * NCH + i) * C_ + c;
        carry_out[o] = Cv;
        Cv = ach * Cv + fin[o];
    }
}

// ----- carry-fix + k normalize + kb scale -> fp16, warp per row ---------------
__global__ void knorm_fp16_k(const float* __restrict__ kraw,
                             const float* __restrict__ carry,
                             const float* __restrict__ la_coef,
                             const float* __restrict__ kernel_beta,
                             __half* __restrict__ kh)
{
    const int row = blockIdx.x * (blockDim.x >> 5) + (threadIdx.x >> 5);
    const int lane = threadIdx.x & 31;
    if (row >= B_ * NH_ * T_) return;
    const int t = row % T_;
    const int bh = row / T_;
    const int h = bh % NH_;
    const int b = bh / NH_;
    const int tl = t % TCH;
    const int chunk = t / TCH;

    const float alpha = la_coef[h];
    const float m = __powf(alpha, (float)(tl + 1));
    const float2 C2 = ((const float2*)(carry + ((size_t)b * NCH + chunk) * C_ + h * HS_))[lane];

    float2 v = ((const float2*)(kraw + (size_t)row * HS_))[lane];
    v.x += m * C2.x;
    v.y += m * C2.y;

    float ss = v.x * v.x + v.y * v.y;
    #pragma unroll
    for (int o = 16; o > 0; o >>= 1) ss += __shfl_xor_sync(0xffffffffu, ss, o);

    const float kb = expf(fminf(kernel_beta[h] * 10.0f, 5.0f));
    const float scale = kb * rsqrtf(ss);
    ((__half2*)(kh + (size_t)row * HS_))[lane] =
        __half2(__float2half_rn(v.x * scale), __float2half_rn(v.y * scale));
}

// ---- fused v build + normalize + vb scale + transpose -> fp16 [d][t] ---------
__global__ void __launch_bounds__(256) vmaket_k(
    const float* __restrict__ xv,
    const float* __restrict__ v_coef,
    const float* __restrict__ value_beta,
    __half* __restrict__ vth)
{
    __shared__ float tile[64][65];
    const int t0 = blockIdx.x * 64;
    const int bh = blockIdx.y;
    const int h = bh % NH_;
    const int b = bh / NH_;
    const int tid = threadIdx.x;
    const int wid = tid >> 5;
    const int lane = tid & 31;

    const float c = v_coef[h];
    const float vb = expf(value_beta[h] * 10.0f);

    #pragma unroll
    for (int r = wid; r < 64; r += 8) {
        const int t = t0 + r;
        const float* cur = xv + ((size_t)b * T_ + t) * C_ + h * HS_;
        const float2 vc = ((const float2*)cur)[lane];
        float2 vn = make_float2(0.f, 0.f);
        if (t + 1 < T_) vn = ((const float2*)(cur + C_))[lane];
        float2 vv = make_float2(vn.x * (1.f - c) + vc.x * c,
                                vn.y * (1.f - c) + vc.y * c);
        float ss = vv.x * vv.x + vv.y * vv.y;
        #pragma unroll
        for (int o = 16; o > 0; o >>= 1) ss += __shfl_xor_sync(0xffffffffu, ss, o);
        const float scale = vb * rsqrtf(ss);
        tile[r][2*lane]     = vv.x * scale;
        tile[r][2*lane + 1] = vv.y * scale;
    }
    __syncthreads();

    #pragma unroll
    for (int i = tid; i < 2048; i += 256) {
        const int d = i >> 5;
        const int tt = (i & 31) * 2;
        const float x0 = tile[tt][d], x1 = tile[tt + 1][d];
        const size_t o = ((size_t)bh * HS_ + d) * T_ + t0 + tt;
        *(__half2*)(vth + o) = __half2(__float2half_rn(x0), __float2half_rn(x1));
    }
}

// ====== fp16 1-pass HMMA strict-causal flash attention (q == k) ===============
#define AQ 128
#define AK 64
#define APAD 72
#define AMATB (AK * APAD * 2)     // 9216
#define ASTG  (2 * AMATB)         // 18432 per stage
#define ASMEM (3 * ASTG)          // 55296

__global__ void __launch_bounds__(256) attn_mma_k(
    const __half* __restrict__ kh, const __half* __restrict__ vth,
    __half* __restrict__ Yh)
{
    extern __shared__ __align__(16) char asmem[];

    const int b = blockIdx.z;
    const int h = blockIdx.y;
    const int qb = gridDim.x - 1 - blockIdx.x;
    const int p0 = qb * AQ;
    const int tid = threadIdx.x;
    const int wid = tid >> 5;
    const int lane = tid & 31;
    const int g = lane >> 2, t = lane & 3;
    const int wm = wid * 16;

    const __half* Kh = kh + (((size_t)b * NH_ + h) * T_) * HS_;
    const __half* Vh = vth + (((size_t)b * NH_ + h) * HS_) * T_;

    auto sK = [&](int st, int r, int cc) { return asmem + st*ASTG + (r*APAD + cc)*2; };
    auto sV = [&](int st, int r, int cc) { return asmem + st*ASTG + AMATB + (r*APAD + cc)*2; };

    // ---- stage Q fragments via stage-0 K buffer ----
    uint32_t Q[4][4];
    #pragma unroll
    for (int half = 0; half < 2; half++) {
        #pragma unroll
        for (int i = 0; i < 2; i++) {
            const int v = tid + i * 256;
            const int row = v >> 3, seg = (v & 7) * 8;
            *(uint4*)sK(0, row, seg) =
                *(const uint4*)(Kh + (size_t)(p0 + half * 64 + row) * HS_ + seg);
        }
        __syncthreads();
        if ((wm >> 6) == half) {
            const int lr = (wm & 63) + (lane & 15);
            #pragma unroll
            for (int ks = 0; ks < 4; ks++) {
                const int cc = ks*16 + ((lane >> 4) & 1) * 8;
                ldm_x4(Q[ks][0], Q[ks][1], Q[ks][2], Q[ks][3],
                       smem_u32(sK(0, lr, cc)));
            }
        }
        __syncthreads();
    }

    float m0 = -1e30f, m1 = -1e30f, l0 = 0.f, l1 = 0.f;
    float O[8][4];
    #pragma unroll
    for (int nj = 0; nj < 8; nj++)
        #pragma unroll
        for (int e = 0; e < 4; e++) O[nj][e] = 0.f;

    const int r0 = p0 + wm + g;
    const int r1 = r0 + 8;
    const int ntiles = (p0 + AQ) / AK;

    auto load_tile = [&](int st, int j0) {
        #pragma unroll
        for (int i = 0; i < 2; i++) {
            const int v = tid + i * 256;
            const int row = v >> 3, seg = (v & 7) * 8;
            CP_ASYNC16(smem_u32(sK(st, row, seg)), Kh + (size_t)(j0 + row) * HS_ + seg);
            CP_ASYNC16(smem_u32(sV(st, row, seg)), Vh + (size_t)row * T_ + j0 + seg);
        }
    };

    load_tile(0, 0);
    CP_COMMIT();
    if (ntiles > 1) {
        load_tile(1, AK);
        CP_COMMIT();
    }

    #pragma unroll 1
    for (int kt = 0; kt < ntiles; kt++) {
        const int j0 = kt * AK;
        const int st = kt % 3;
        if (kt + 1 < ntiles) { CP_WAIT(1); } else { CP_WAIT(0); }
        __syncthreads();
        if (kt + 2 < ntiles) {
            load_tile((kt + 2) % 3, (kt + 2) * AK);
            CP_COMMIT();
        }

        const bool active = (j0 < p0 + wm + 16);
        if (active) {
            float S[8][4];
            #pragma unroll
            for (int nj = 0; nj < 8; nj++)
                #pragma unroll
                for (int e = 0; e < 4; e++) S[nj][e] = 0.f;

            #pragma unroll
            for (int ks = 0; ks < 4; ks++) {
                const int koff = ks * 16;
                uint32_t b2[8][2];
                #pragma unroll
                for (int nj = 0; nj < 8; nj++) {
                    const int br = nj*8 + (lane & 7);
                    const int bc = koff + ((lane >> 3) & 1) * 8;
                    ldm_x2(b2[nj][0], b2[nj][1], smem_u32(sK(st, br, bc)));
                }
                #pragma unroll
                for (int nj = 0; nj < 8; nj++)
                    mma_f16(S[nj], Q[ks], b2[nj]);
            }

            if (j0 + AK > p0 + wm) {
                #pragma unroll
                for (int nj = 0; nj < 8; nj++) {
                    const int jb = j0 + nj*8 + 2*t;
                    if (jb     >= r0) S[nj][0] = -1e30f;
                    if (jb + 1 >= r0) S[nj][1] = -1e30f;
                    if (jb     >= r1) S[nj][2] = -1e30f;
                    if (jb + 1 >= r1) S[nj][3] = -1e30f;
                }
            }

            float tm0 = -1e30f, tm1 = -1e30f;
            #pragma unroll
            for (int nj = 0; nj < 8; nj++) {
                tm0 = fmaxf(tm0, fmaxf(S[nj][0], S[nj][1]));
                tm1 = fmaxf(tm1, fmaxf(S[nj][2], S[nj][3]));
            }
            tm0 = fmaxf(tm0, __shfl_xor_sync(0xffffffffu, tm0, 1));
            tm0 = fmaxf(tm0, __shfl_xor_sync(0xffffffffu, tm0, 2));
            tm1 = fmaxf(tm1, __shfl_xor_sync(0xffffffffu, tm1, 1));
            tm1 = fmaxf(tm1, __shfl_xor_sync(0xffffffffu, tm1, 2));

            const float m0n = fmaxf(m0, tm0), m1n = fmaxf(m1, tm1);
            const float c0 = __expf(m0 - m0n), c1 = __expf(m1 - m1n);
            l0 *= c0; l1 *= c1;
            #pragma unroll
            for (int nj = 0; nj < 8; nj++) {
                O[nj][0] *= c0; O[nj][1] *= c0;
                O[nj][2] *= c1; O[nj][3] *= c1;
            }
            m0 = m0n; m1 = m1n;

            uint32_t PA[8][2];
            float s0 = 0.f, s1 = 0.f;
            #pragma unroll
            for (int nj = 0; nj < 8; nj++) {
                float e0 = __expf(S[nj][0] - m0n), e1 = __expf(S[nj][1] - m0n);
                float e2 = __expf(S[nj][2] - m1n), e3 = __expf(S[nj][3] - m1n);
                s0 += e0 + e1; s1 += e2 + e3;
                __half2 h01(__float2half_rn(e0), __float2half_rn(e1));
                __half2 h23(__float2half_rn(e2), __float2half_rn(e3));
                PA[nj][0] = *(uint32_t*)&h01;
                PA[nj][1] = *(uint32_t*)&h23;
            }
            s0 += __shfl_xor_sync(0xffffffffu, s0, 1);
            s0 += __shfl_xor_sync(0xffffffffu, s0, 2);
            s1 += __shfl_xor_sync(0xffffffffu, s1, 1);
            s1 += __shfl_xor_sync(0xffffffffu, s1, 2);
            l0 += s0; l1 += s1;

            #pragma unroll
            for (int ks = 0; ks < 4; ks++) {
                const int koff = ks * 16;
                uint32_t a4[4] = {PA[2*ks][0], PA[2*ks][1], PA[2*ks+1][0], PA[2*ks+1][1]};
                uint32_t bv[8][2];
                #pragma unroll
                for (int nj = 0; nj < 8; nj++) {
                    const int br = nj*8 + (lane & 7);
                    const int bc = koff + ((lane >> 3) & 1) * 8;
                    ldm_x2(bv[nj][0], bv[nj][1], smem_u32(sV(st, br, bc)));
                }
                #pragma unroll
                for (int nj = 0; nj < 8; nj++)
                    mma_f16(O[nj], a4, bv[nj]);
            }
        }
    }

    const float il0 = (r0 == 0) ? 0.f : 1.f / l0;
    const float il1 = 1.f / l1;
    __half* y0 = Yh + ((size_t)b * T_ + r0) * C_ + h * HS_;
    __half* y1 = Yh + ((size_t)b * T_ + r1) * C_ + h * HS_;
    #pragma unroll
    for (int nj = 0; nj < 8; nj++) {
        const int col = nj*8 + 2*t;
        *(__half2*)(y0 + col) = __half2(__float2half_rn(O[nj][0] * il0),
                                        __float2half_rn(O[nj][1] * il0));
        *(__half2*)(y1 + col) = __half2(__float2half_rn(O[nj][2] * il1),
                                        __float2half_rn(O[nj][3] * il1));
    }
}

// ------------------------------- launcher --------------------------------------
extern "C" void kernel_launch(void* const* d_in, const int* in_sizes, int n_in,
                              void* d_out, int out_size)
{
    const float* x           = (const float*)d_in[0];
    const float* W_la        = (const float*)d_in[1];
    const float* la_coef     = (const float*)d_in[2];
    const float* kernel_beta = (const float*)d_in[3];
    const float* value_beta  = (const float*)d_in[4];
    const float* W_v         = (const float*)d_in[5];
    const float* v_coef      = (const float*)d_in[6];
    const float* W_proj      = (const float*)d_in[7];
    float* out = (float*)d_out;

    float *xl, *xv, *kraw, *fin, *carry;
    __half *A, *Wla, *Wv, *Wp, *kh, *vth;
    cudaGetSymbolAddress((void**)&xl,    g_xl);
    cudaGetSymbolAddress((void**)&xv,    g_xv);
    cudaGetSymbolAddress((void**)&kraw,  g_kraw);
    cudaGetSymbolAddress((void**)&fin,   g_fin);
    cudaGetSymbolAddress((void**)&carry, g_carry);
    cudaGetSymbolAddress((void**)&A,     g_A);
    cudaGetSymbolAddress((void**)&Wla,   g_Wla);
    cudaGetSymbolAddress((void**)&Wv,    g_Wv);
    cudaGetSymbolAddress((void**)&Wp,    g_Wp);
    cudaGetSymbolAddress((void**)&kh,    g_kh);
    cudaGetSymbolAddress((void**)&vth,   g_vth);

    cudaFuncSetAttribute(gemm_tc_k, cudaFuncAttributeMaxDynamicSharedMemorySize, GSMEM);
    cudaFuncSetAttribute(attn_mma_k, cudaFuncAttributeMaxDynamicSharedMemorySize, ASMEM);

    const int n4 = (M_ * C_) / 4;

    conv_fp16_k<<<(n4 + 255) / 256, 256>>>(x, A, n4);
    tsplit3_k<<<dim3(32, 32, 3), dim3(32, 8)>>>(W_la, W_v, W_proj, Wla, Wv, Wp);

    // fused QKV GEMM: N-concat of W_la (-> xl) and W_v (-> xv)
    gemm_tc_k<<<dim3(2 * GNN / GBN, M_ / GBM), 256, GSMEM>>>(
        A, Wla, Wv, xl, xv);

    ema_local_k<<<(B_*NCH*C_) / 256, 256>>>(xl, la_coef, kraw, fin);
    ema_comb_k<<<(B_*C_ + 255) / 256, 256>>>(fin, la_coef, carry);

    knorm_fp16_k<<<(B_*NH_*T_)/8, 256>>>(kraw, carry, la_coef, kernel_beta, kh);
    vmaket_k<<<dim3(T_/64, B_*NH_), 256>>>(xv, v_coef, value_beta, vth);

    // attention writes y directly as fp16 into the proj-GEMM A buffer
    attn_mma_k<<<dim3(T_/AQ, NH_, B_), 256, ASMEM>>>(kh, vth, A);

    // projection GEMM: N = 1024 -> 4 n-tiles
    gemm_tc_k<<<dim3(GNN / GBN, M_ / GBM), 256, GSMEM>>>(
        A, Wp, Wp, out, out);
}

// round 11
// speedup vs baseline: 2.0940x; 1.0589x over previous
#include <cuda_runtime.h>
#include <cuda_fp16.h>
#include <cstdint>

#define B_  2
#define T_  2048
#define NH_ 16
#define HS_ 64
#define C_  (NH_*HS_)   // 1024
#define M_  (B_*T_)     // 4096

// ======================= helpers ==============================================
__device__ __forceinline__ uint32_t smem_u32(const void* p) {
    uint32_t a;
    asm("{ .reg .u64 t; cvta.to.shared.u64 t, %1; cvt.u32.u64 %0, t; }" : "=r"(a) : "l"(p));
    return a;
}
#define CP_ASYNC16(dst_u32, src_ptr) \
    asm volatile("cp.async.cg.shared.global [%0], [%1], 16;" :: "r"(dst_u32), "l"(src_ptr))
#define CP_COMMIT() asm volatile("cp.async.commit_group;" ::: "memory")
#define CP_WAIT(n)  asm volatile("cp.async.wait_group %0;" :: "n"(n) : "memory")

__device__ __forceinline__ void ldm_x4(uint32_t& r0, uint32_t& r1, uint32_t& r2, uint32_t& r3,
                                       uint32_t addr) {
    asm volatile("ldmatrix.sync.aligned.m8n8.x4.shared.b16 {%0,%1,%2,%3}, [%4];"
                 : "=r"(r0), "=r"(r1), "=r"(r2), "=r"(r3) : "r"(addr));
}
__device__ __forceinline__ void ldm_x2(uint32_t& r0, uint32_t& r1, uint32_t addr) {
    asm volatile("ldmatrix.sync.aligned.m8n8.x2.shared.b16 {%0,%1}, [%2];"
                 : "=r"(r0), "=r"(r1) : "r"(addr));
}
__device__ __forceinline__ void mma_f16(float* c, const uint32_t* a, const uint32_t* b) {
    asm volatile(
        "mma.sync.aligned.m16n8k16.row.col.f32.f16.f16.f32 "
        "{%0,%1,%2,%3}, {%4,%5,%6,%7}, {%8,%9}, {%0,%1,%2,%3};"
        : "+f"(c[0]), "+f"(c[1]), "+f"(c[2]), "+f"(c[3])
        : "r"(a[0]), "r"(a[1]), "r"(a[2]), "r"(a[3]), "r"(b[0]), "r"(b[1]));
}

// ---------------- scratch (device globals; no allocation allowed) -------------
__device__ __half g_xl[(size_t)B_*T_*C_];
__device__ __half g_xv[(size_t)B_*T_*C_];
__device__ float g_kraw[(size_t)B_*NH_*T_*HS_];

#define NCH 64
#define TCH 32
__device__ float g_fin[(size_t)B_*NCH*C_];
__device__ float g_carry[(size_t)B_*NCH*C_];

__device__ __half g_A[(size_t)M_*C_];
__device__ __half g_Wla[(size_t)C_*C_];
__device__ __half g_Wv[(size_t)C_*C_];
__device__ __half g_Wp[(size_t)C_*C_];
__device__ __half g_kh[(size_t)B_*NH_*T_*HS_];
__device__ __half g_vth[(size_t)B_*NH_*HS_*T_];   // [b,h,d,t]

// ================= fp32 -> fp16 convert (no transpose) ========================
__global__ void __launch_bounds__(256) conv_fp16_k(
    const float* __restrict__ X, __half* __restrict__ H, int n4)
{
    int i = blockIdx.x * blockDim.x + threadIdx.x;
    if (i >= n4) return;
    float4 v = ((const float4*)X)[i];
    __half2* Hp = (__half2*)H;
    Hp[2*i]   = __half2(__float2half_rn(v.x), __float2half_rn(v.y));
    Hp[2*i+1] = __half2(__float2half_rn(v.z), __float2half_rn(v.w));
}

// ==== batched: 3 weights fp32 [K,N] -> fp16 transposed [N,K] ==================
__global__ void tsplit3_k(const float* __restrict__ W0, const float* __restrict__ W1,
                          const float* __restrict__ W2,
                          __half* __restrict__ T0, __half* __restrict__ T1,
                          __half* __restrict__ T2)
{
    __shared__ float tile[32][33];
    const float* W = (blockIdx.z == 0) ? W0 : (blockIdx.z == 1) ? W1 : W2;
    __half* TH = (blockIdx.z == 0) ? T0 : (blockIdx.z == 1) ? T1 : T2;
    const int n0 = blockIdx.x * 32, k0 = blockIdx.y * 32;
    const int tx = threadIdx.x, ty = threadIdx.y;  // 32 x 8
    #pragma unroll
    for (int j = ty; j < 32; j += 8)
        tile[j][tx] = W[(size_t)(k0 + j) * C_ + n0 + tx];
    __syncthreads();
    #pragma unroll
    for (int j = ty; j < 32; j += 8)
        TH[(size_t)(n0 + j) * C_ + k0 + tx] = __float2half_rn(tile[tx][j]);
}

// ===== fp16 1-pass HMMA GEMM: C = A @ B^T, 128x256 per CTA, GBK=64, 3-stage ===
#define GBM 128
#define GBN 256
#define GBK 64
#define GK  1024
#define GNN 1024
#define GNK (GK / GBK)                    // 16
#define GLDS 72                           // halves per smem row
#define GA_B (GBM * GLDS * 2)             // 18432 B per A matrix tile
#define GB_B (GBN * GLDS * 2)             // 36864 B per B matrix tile
#define GSTG (GA_B + GB_B)                // 55296 per stage
#define GSMEM (3 * GSTG)                  // 165888

template <bool HALF_OUT>
__global__ void __launch_bounds__(256, 1) gemm_tc_k(
    const __half* __restrict__ A,
    const __half* __restrict__ W1, const __half* __restrict__ W2,
    void* __restrict__ C1v, void* __restrict__ C2v)
{
    extern __shared__ __align__(16) char gsm[];

    const int n0g = blockIdx.x * GBN;
    const bool sel = (n0g >= GNN);
    const int n0 = sel ? (n0g - GNN) : n0g;
    const __half* Bm = sel ? W2 : W1;
    void* Cv = sel ? C2v : C1v;

    const int m0 = blockIdx.y * GBM;
    const int tid  = threadIdx.x;
    const int wid  = tid >> 5;
    const int lane = tid & 31;
    const int wm = (wid >> 2) * 64;   // 0 or 64
    const int wn = (wid & 3) * 64;    // 0..192

    float acc[4][8][4];
    #pragma unroll
    for (int i = 0; i < 4; i++)
        #pragma unroll
        for (int j = 0; j < 8; j++)
            #pragma unroll
            for (int e = 0; e < 4; e++) acc[i][j][e] = 0.f;

    auto load_tile = [&](int stage, int kc) {
        const int k0 = kc * GBK;
        char* base = gsm + stage * GSTG;
        // A: 128 rows x 8 segs of 16B
        #pragma unroll
        for (int i = 0; i < 4; i++) {
            const int idx = tid + i * 256;
            const int row = idx >> 3;
            const int c8  = (idx & 7) * 8;
            const uint32_t so = (uint32_t)(row * GLDS + c8) * 2;
            CP_ASYNC16(smem_u32(base + so), A + (size_t)(m0 + row) * GK + k0 + c8);
        }
        // B: 256 rows x 8 segs of 16B
        #pragma unroll
        for (int i = 0; i < 8; i++) {
            const int idx = tid + i * 256;
            const int row = idx >> 3;
            const int c8  = (idx & 7) * 8;
            const uint32_t so = (uint32_t)(row * GLDS + c8) * 2;
            CP_ASYNC16(smem_u32(base + GA_B + so), Bm + (size_t)(n0 + row) * GK + k0 + c8);
        }
    };

    load_tile(0, 0);
    CP_COMMIT();
    load_tile(1, 1);
    CP_COMMIT();

    #pragma unroll 1
    for (int kc = 0; kc < GNK; kc++) {
        const int st = kc % 3;
        if (kc + 1 < GNK) { CP_WAIT(1); } else { CP_WAIT(0); }
        __syncthreads();
        if (kc + 2 < GNK) {
            load_tile((kc + 2) % 3, kc + 2);
            CP_COMMIT();
        }

        char* base = gsm + st * GSTG;
        char* bA = base;
        char* bB = base + GA_B;

        #pragma unroll
        for (int ks = 0; ks < 4; ks++) {
            const int koff = ks * 16;
            uint32_t b2[8][2];
            #pragma unroll
            for (int nj = 0; nj < 8; nj++) {
                const int brow = wn + nj*8 + (lane & 7);
                const int bcol = koff + ((lane >> 3) & 1) * 8;
                ldm_x2(b2[nj][0], b2[nj][1], smem_u32(bB + (brow * GLDS + bcol) * 2));
            }
            #pragma unroll
            for (int mi = 0; mi < 4; mi++) {
                const int arow = wm + mi*16 + (lane & 15);
                const int acol = koff + ((lane >> 4) & 1) * 8;
                uint32_t a4[4];
                ldm_x4(a4[0], a4[1], a4[2], a4[3],
                       smem_u32(bA + (arow * GLDS + acol) * 2));
                #pragma unroll
                for (int nj = 0; nj < 8; nj++)
                    mma_f16(acc[mi][nj], a4, b2[nj]);
            }
        }
    }

    const int g = lane >> 2, t = lane & 3;
    if (HALF_OUT) {
        __half* Cg = (__half*)Cv;
        #pragma unroll
        for (int mi = 0; mi < 4; mi++) {
            __half* row0 = Cg + (size_t)(m0 + wm + mi*16 + g)     * GNN + n0 + wn;
            __half* row1 = Cg + (size_t)(m0 + wm + mi*16 + g + 8) * GNN + n0 + wn;
            #pragma unroll
            for (int nj = 0; nj < 8; nj++) {
                *(__half2*)(row0 + nj*8 + t*2) =
                    __half2(__float2half_rn(acc[mi][nj][0]), __float2half_rn(acc[mi][nj][1]));
                *(__half2*)(row1 + nj*8 + t*2) =
                    __half2(__float2half_rn(acc[mi][nj][2]), __float2half_rn(acc[mi][nj][3]));
            }
        }
    } else {
        float* Cg = (float*)Cv;
        #pragma unroll
        for (int mi = 0; mi < 4; mi++) {
            float* row0 = Cg + (size_t)(m0 + wm + mi*16 + g)     * GNN + n0 + wn;
            float* row1 = Cg + (size_t)(m0 + wm + mi*16 + g + 8) * GNN + n0 + wn;
            #pragma unroll
            for (int nj = 0; nj < 8; nj++) {
                *(float2*)(row0 + nj*8 + t*2) = make_float2(acc[mi][nj][0], acc[mi][nj][1]);
                *(float2*)(row1 + nj*8 + t*2) = make_float2(acc[mi][nj][2], acc[mi][nj][3]);
            }
        }
    }
}

// ============== EMA scan: chunked parallel (local scan + combine) =============
__global__ void __launch_bounds__(256) ema_local_k(
    const __half* __restrict__ xl, const float* __restrict__ la_coef,
    float* __restrict__ kraw, float* __restrict__ fin)
{
    const int gid = blockIdx.x * blockDim.x + threadIdx.x;
    if (gid >= B_ * NCH * C_) return;
    const int c = gid % C_;
    const int rest = gid / C_;
    const int chunk = rest % NCH;
    const int b = rest / NCH;
    const int h = c >> 6, d = c & 63;

    const float a = la_coef[h];
    const float onem = 1.0f - a;
    float carry = 0.0f;

    const __half* src = xl + ((size_t)b * T_ + chunk * TCH) * C_ + c;
    float* dst = kraw + (((size_t)b * NH_ + h) * T_ + chunk * TCH) * HS_ + d;

    #pragma unroll 4
    for (int t = 0; t < TCH; t++) {
        carry = a * carry + onem * __half2float(src[(size_t)t * C_]);
        dst[(size_t)t * HS_] = carry;
    }
    fin[gid] = carry;
}

__global__ void ema_comb_k(const float* __restrict__ fin,
                           const float* __restrict__ la_coef,
                           float* __restrict__ carry_out)
{
    const int gid = blockIdx.x * blockDim.x + threadIdx.x;
    if (gid >= B_ * C_) return;
    const int c = gid % C_;
    const int b = gid / C_;
    const float a = la_coef[c >> 6];
    const float ach = __powf(a, (float)TCH);
    float Cv = 0.0f;
    #pragma unroll
    for (int i = 0; i < NCH; i++) {
        const size_t o = ((size_t)b * NCH + i) * C_ + c;
        carry_out[o] = Cv;
        Cv = ach * Cv + fin[o];
    }
}

// ----- carry-fix + k normalize + kb scale -> fp16, warp per row ---------------
__global__ void knorm_fp16_k(const float* __restrict__ kraw,
                             const float* __restrict__ carry,
                             const float* __restrict__ la_coef,
                             const float* __restrict__ kernel_beta,
                             __half* __restrict__ kh)
{
    const int row = blockIdx.x * (blockDim.x >> 5) + (threadIdx.x >> 5);
    const int lane = threadIdx.x & 31;
    if (row >= B_ * NH_ * T_) return;
    const int t = row % T_;
    const int bh = row / T_;
    const int h = bh % NH_;
    const int b = bh / NH_;
    const int tl = t % TCH;
    const int chunk = t / TCH;

    const float alpha = la_coef[h];
    const float m = __powf(alpha, (float)(tl + 1));
    const float2 C2 = ((const float2*)(carry + ((size_t)b * NCH + chunk) * C_ + h * HS_))[lane];

    float2 v = ((const float2*)(kraw + (size_t)row * HS_))[lane];
    v.x += m * C2.x;
    v.y += m * C2.y;

    float ss = v.x * v.x + v.y * v.y;
    #pragma unroll
    for (int o = 16; o > 0; o >>= 1) ss += __shfl_xor_sync(0xffffffffu, ss, o);

    const float kb = expf(fminf(kernel_beta[h] * 10.0f, 5.0f));
    const float scale = kb * rsqrtf(ss);
    ((__half2*)(kh + (size_t)row * HS_))[lane] =
        __half2(__float2half_rn(v.x * scale), __float2half_rn(v.y * scale));
}

// ---- fused v build + normalize + vb scale + transpose -> fp16 [d][t] ---------
__global__ void __launch_bounds__(256) vmaket_k(
    const __half* __restrict__ xv,
    const float* __restrict__ v_coef,
    const float* __restrict__ value_beta,
    __half* __restrict__ vth)
{
    __shared__ float tile[64][65];
    const int t0 = blockIdx.x * 64;
    const int bh = blockIdx.y;
    const int h = bh % NH_;
    const int b = bh / NH_;
    const int tid = threadIdx.x;
    const int wid = tid >> 5;
    const int lane = tid & 31;

    const float c = v_coef[h];
    const float vb = expf(value_beta[h] * 10.0f);

    #pragma unroll
    for (int r = wid; r < 64; r += 8) {
        const int t = t0 + r;
        const __half* cur = xv + ((size_t)b * T_ + t) * C_ + h * HS_;
        const float2 vc = __half22float2(((const __half2*)cur)[lane]);
        float2 vn = make_float2(0.f, 0.f);
        if (t + 1 < T_) vn = __half22float2(((const __half2*)(cur + C_))[lane]);
        float2 vv = make_float2(vn.x * (1.f - c) + vc.x * c,
                                vn.y * (1.f - c) + vc.y * c);
        float ss = vv.x * vv.x + vv.y * vv.y;
        #pragma unroll
        for (int o = 16; o > 0; o >>= 1) ss += __shfl_xor_sync(0xffffffffu, ss, o);
        const float scale = vb * rsqrtf(ss);
        tile[r][2*lane]     = vv.x * scale;
        tile[r][2*lane + 1] = vv.y * scale;
    }
    __syncthreads();

    #pragma unroll
    for (int i = tid; i < 2048; i += 256) {
        const int d = i >> 5;
        const int tt = (i & 31) * 2;
        const float x0 = tile[tt][d], x1 = tile[tt + 1][d];
        const size_t o = ((size_t)bh * HS_ + d) * T_ + t0 + tt;
        *(__half2*)(vth + o) = __half2(__float2half_rn(x0), __float2half_rn(x1));
    }
}

// ====== fp16 1-pass HMMA strict-causal flash attention (q == k) ===============
#define AQ 128
#define AK 64
#define APAD 72
#define AMATB (AK * APAD * 2)     // 9216
#define ASTG  (2 * AMATB)         // 18432 per stage
#define ASMEM (3 * ASTG)          // 55296

__global__ void __launch_bounds__(256, 2) attn_mma_k(
    const __half* __restrict__ kh, const __half* __restrict__ vth,
    __half* __restrict__ Yh)
{
    extern __shared__ __align__(16) char asmem[];

    const int b = blockIdx.z;
    const int h = blockIdx.y;
    const int qb = gridDim.x - 1 - blockIdx.x;
    const int p0 = qb * AQ;
    const int tid = threadIdx.x;
    const int wid = tid >> 5;
    const int lane = tid & 31;
    const int g = lane >> 2, t = lane & 3;
    const int wm = wid * 16;

    const __half* Kh = kh + (((size_t)b * NH_ + h) * T_) * HS_;
    const __half* Vh = vth + (((size_t)b * NH_ + h) * HS_) * T_;

    auto sK = [&](int st, int r, int cc) { return asmem + st*ASTG + (r*APAD + cc)*2; };
    auto sV = [&](int st, int r, int cc) { return asmem + st*ASTG + AMATB + (r*APAD + cc)*2; };

    // ---- stage Q fragments via stage-0 K buffer ----
    uint32_t Q[4][4];
    #pragma unroll
    for (int half = 0; half < 2; half++) {
        #pragma unroll
        for (int i = 0; i < 2; i++) {
            const int v = tid + i * 256;
            const int row = v >> 3, seg = (v & 7) * 8;
            *(uint4*)sK(0, row, seg) =
                *(const uint4*)(Kh + (size_t)(p0 + half * 64 + row) * HS_ + seg);
        }
        __syncthreads();
        if ((wm >> 6) == half) {
            const int lr = (wm & 63) + (lane & 15);
            #pragma unroll
            for (int ks = 0; ks < 4; ks++) {
                const int cc = ks*16 + ((lane >> 4) & 1) * 8;
                ldm_x4(Q[ks][0], Q[ks][1], Q[ks][2], Q[ks][3],
                       smem_u32(sK(0, lr, cc)));
            }
        }
        __syncthreads();
    }

    float m0 = -1e30f, m1 = -1e30f, l0 = 0.f, l1 = 0.f;
    float O[8][4];
    #pragma unroll
    for (int nj = 0; nj < 8; nj++)
        #pragma unroll
        for (int e = 0; e < 4; e++) O[nj][e] = 0.f;

    const int r0 = p0 + wm + g;
    const int r1 = r0 + 8;
    const int ntiles = (p0 + AQ) / AK;

    auto load_tile = [&](int st, int j0) {
        #pragma unroll
        for (int i = 0; i < 2; i++) {
            const int v = tid + i * 256;
            const int row = v >> 3, seg = (v & 7) * 8;
            CP_ASYNC16(smem_u32(sK(st, row, seg)), Kh + (size_t)(j0 + row) * HS_ + seg);
            CP_ASYNC16(smem_u32(sV(st, row, seg)), Vh + (size_t)row * T_ + j0 + seg);
        }
    };

    load_tile(0, 0);
    CP_COMMIT();
    if (ntiles > 1) {
        load_tile(1, AK);
        CP_COMMIT();
    }

    #pragma unroll 1
    for (int kt = 0; kt < ntiles; kt++) {
        const int j0 = kt * AK;
        const int st = kt % 3;
        if (kt + 1 < ntiles) { CP_WAIT(1); } else { CP_WAIT(0); }
        __syncthreads();
        if (kt + 2 < ntiles) {
            load_tile((kt + 2) % 3, (kt + 2) * AK);
            CP_COMMIT();
        }

        const bool active = (j0 < p0 + wm + 16);
        if (active) {
            float S[8][4];
            #pragma unroll
            for (int nj = 0; nj < 8; nj++)
                #pragma unroll
                for (int e = 0; e < 4; e++) S[nj][e] = 0.f;

            #pragma unroll
            for (int ks = 0; ks < 4; ks++) {
                const int koff = ks * 16;
                uint32_t b2[8][2];
                #pragma unroll
                for (int nj = 0; nj < 8; nj++) {
                    const int br = nj*8 + (lane & 7);
                    const int bc = koff + ((lane >> 3) & 1) * 8;
                    ldm_x2(b2[nj][0], b2[nj][1], smem_u32(sK(st, br, bc)));
                }
                #pragma unroll
                for (int nj = 0; nj < 8; nj++)
                    mma_f16(S[nj], Q[ks], b2[nj]);
            }

            if (j0 + AK > p0 + wm) {
                #pragma unroll
                for (int nj = 0; nj < 8; nj++) {
                    const int jb = j0 + nj*8 + 2*t;
                    if (jb     >= r0) S[nj][0] = -1e30f;
                    if (jb + 1 >= r0) S[nj][1] = -1e30f;
                    if (jb     >= r1) S[nj][2] = -1e30f;
                    if (jb + 1 >= r1) S[nj][3] = -1e30f;
                }
            }

            float tm0 = -1e30f, tm1 = -1e30f;
            #pragma unroll
            for (int nj = 0; nj < 8; nj++) {
                tm0 = fmaxf(tm0, fmaxf(S[nj][0], S[nj][1]));
                tm1 = fmaxf(tm1, fmaxf(S[nj][2], S[nj][3]));
            }
            tm0 = fmaxf(tm0, __shfl_xor_sync(0xffffffffu, tm0, 1));
            tm0 = fmaxf(tm0, __shfl_xor_sync(0xffffffffu, tm0, 2));
            tm1 = fmaxf(tm1, __shfl_xor_sync(0xffffffffu, tm1, 1));
            tm1 = fmaxf(tm1, __shfl_xor_sync(0xffffffffu, tm1, 2));

            const float m0n = fmaxf(m0, tm0), m1n = fmaxf(m1, tm1);
            const float c0 = __expf(m0 - m0n), c1 = __expf(m1 - m1n);
            l0 *= c0; l1 *= c1;
            #pragma unroll
            for (int nj = 0; nj < 8; nj++) {
                O[nj][0] *= c0; O[nj][1] *= c0;
                O[nj][2] *= c1; O[nj][3] *= c1;
            }
            m0 = m0n; m1 = m1n;

            uint32_t PA[8][2];
            float s0 = 0.f, s1 = 0.f;
            #pragma unroll
            for (int nj = 0; nj < 8; nj++) {
                float e0 = __expf(S[nj][0] - m0n), e1 = __expf(S[nj][1] - m0n);
                float e2 = __expf(S[nj][2] - m1n), e3 = __expf(S[nj][3] - m1n);
                s0 += e0 + e1; s1 += e2 + e3;
                __half2 h01(__float2half_rn(e0), __float2half_rn(e1));
                __half2 h23(__float2half_rn(e2), __float2half_rn(e3));
                PA[nj][0] = *(uint32_t*)&h01;
                PA[nj][1] = *(uint32_t*)&h23;
            }
            s0 += __shfl_xor_sync(0xffffffffu, s0, 1);
            s0 += __shfl_xor_sync(0xffffffffu, s0, 2);
            s1 += __shfl_xor_sync(0xffffffffu, s1, 1);
            s1 += __shfl_xor_sync(0xffffffffu, s1, 2);
            l0 += s0; l1 += s1;

            #pragma unroll
            for (int ks = 0; ks < 4; ks++) {
                const int koff = ks * 16;
                uint32_t a4[4] = {PA[2*ks][0], PA[2*ks][1], PA[2*ks+1][0], PA[2*ks+1][1]};
                uint32_t bv[8][2];
                #pragma unroll
                for (int nj = 0; nj < 8; nj++) {
                    const int br = nj*8 + (lane & 7);
                    const int bc = koff + ((lane >> 3) & 1) * 8;
                    ldm_x2(bv[nj][0], bv[nj][1], smem_u32(sV(st, br, bc)));
                }
                #pragma unroll
                for (int nj = 0; nj < 8; nj++)
                    mma_f16(O[nj], a4, bv[nj]);
            }
        }
    }

    const float il0 = (r0 == 0) ? 0.f : 1.f / l0;
    const float il1 = 1.f / l1;
    __half* y0 = Yh + ((size_t)b * T_ + r0) * C_ + h * HS_;
    __half* y1 = Yh + ((size_t)b * T_ + r1) * C_ + h * HS_;
    #pragma unroll
    for (int nj = 0; nj < 8; nj++) {
        const int col = nj*8 + 2*t;
        *(__half2*)(y0 + col) = __half2(__float2half_rn(O[nj][0] * il0),
                                        __float2half_rn(O[nj][1] * il0));
        *(__half2*)(y1 + col) = __half2(__float2half_rn(O[nj][2] * il1),
                                        __float2half_rn(O[nj][3] * il1));
    }
}

// ------------------------------- launcher --------------------------------------
extern "C" void kernel_launch(void* const* d_in, const int* in_sizes, int n_in,
                              void* d_out, int out_size)
{
    const float* x           = (const float*)d_in[0];
    const float* W_la        = (const float*)d_in[1];
    const float* la_coef     = (const float*)d_in[2];
    const float* kernel_beta = (const float*)d_in[3];
    const float* value_beta  = (const float*)d_in[4];
    const float* W_v         = (const float*)d_in[5];
    const float* v_coef      = (const float*)d_in[6];
    const float* W_proj      = (const float*)d_in[7];
    float* out = (float*)d_out;

    float *kraw, *fin, *carry;
    __half *xl, *xv, *A, *Wla, *Wv, *Wp, *kh, *vth;
    cudaGetSymbolAddress((void**)&xl,    g_xl);
    cudaGetSymbolAddress((void**)&xv,    g_xv);
    cudaGetSymbolAddress((void**)&kraw,  g_kraw);
    cudaGetSymbolAddress((void**)&fin,   g_fin);
    cudaGetSymbolAddress((void**)&carry, g_carry);
    cudaGetSymbolAddress((void**)&A,     g_A);
    cudaGetSymbolAddress((void**)&Wla,   g_Wla);
    cudaGetSymbolAddress((void**)&Wv,    g_Wv);
    cudaGetSymbolAddress((void**)&Wp,    g_Wp);
    cudaGetSymbolAddress((void**)&kh,    g_kh);
    cudaGetSymbolAddress((void**)&vth,   g_vth);

    cudaFuncSetAttribute(gemm_tc_k<true>,
                         cudaFuncAttributeMaxDynamicSharedMemorySize, GSMEM);
    cudaFuncSetAttribute(gemm_tc_k<false>,
                         cudaFuncAttributeMaxDynamicSharedMemorySize, GSMEM);
    cudaFuncSetAttribute(attn_mma_k, cudaFuncAttributeMaxDynamicSharedMemorySize, ASMEM);

    const int n4 = (M_ * C_) / 4;

    conv_fp16_k<<<(n4 + 255) / 256, 256>>>(x, A, n4);
    tsplit3_k<<<dim3(32, 32, 3), dim3(32, 8)>>>(W_la, W_v, W_proj, Wla, Wv, Wp);

    // fused QKV GEMM: N-concat of W_la (-> xl fp16) and W_v (-> xv fp16)
    gemm_tc_k<true><<<dim3(2 * GNN / GBN, M_ / GBM), 256, GSMEM>>>(
        A, Wla, Wv, xl, xv);

    ema_local_k<<<(B_*NCH*C_) / 256, 256>>>(xl, la_coef, kraw, fin);
    ema_comb_k<<<(B_*C_ + 255) / 256, 256>>>(fin, la_coef, carry);

    knorm_fp16_k<<<(B_*NH_*T_)/8, 256>>>(kraw, carry, la_coef, kernel_beta, kh);
    vmaket_k<<<dim3(T_/64, B_*NH_), 256>>>(xv, v_coef, value_beta, vth);

    // attention writes y directly as fp16 into the proj-GEMM A buffer
    attn_mma_k<<<dim3(T_/AQ, NH_, B_), 256, ASMEM>>>(kh, vth, A);

    // projection GEMM: fp32 output, N = 1024 -> 4 n-tiles
    gemm_tc_k<false><<<dim3(GNN / GBN, M_ / GBM), 256, GSMEM>>>(
        A, Wp, Wp, out, out);
}

// round 12
// speedup vs baseline: 2.1386x; 1.0213x over previous
#include <cuda_runtime.h>
#include <cuda_fp16.h>
#include <cstdint>

#define B_  2
#define T_  2048
#define NH_ 16
#define HS_ 64
#define C_  (NH_*HS_)   // 1024
#define M_  (B_*T_)     // 4096

// ======================= helpers ==============================================
__device__ __forceinline__ uint32_t smem_u32(const void* p) {
    uint32_t a;
    asm("{ .reg .u64 t; cvta.to.shared.u64 t, %1; cvt.u32.u64 %0, t; }" : "=r"(a) : "l"(p));
    return a;
}
#define CP_ASYNC16(dst_u32, src_ptr) \
    asm volatile("cp.async.cg.shared.global [%0], [%1], 16;" :: "r"(dst_u32), "l"(src_ptr))
#define CP_COMMIT() asm volatile("cp.async.commit_group;" ::: "memory")
#define CP_WAIT(n)  asm volatile("cp.async.wait_group %0;" :: "n"(n) : "memory")

__device__ __forceinline__ void ldm_x4(uint32_t& r0, uint32_t& r1, uint32_t& r2, uint32_t& r3,
                                       uint32_t addr) {
    asm volatile("ldmatrix.sync.aligned.m8n8.x4.shared.b16 {%0,%1,%2,%3}, [%4];"
                 : "=r"(r0), "=r"(r1), "=r"(r2), "=r"(r3) : "r"(addr));
}
__device__ __forceinline__ void ldm_x2(uint32_t& r0, uint32_t& r1, uint32_t addr) {
    asm volatile("ldmatrix.sync.aligned.m8n8.x2.shared.b16 {%0,%1}, [%2];"
                 : "=r"(r0), "=r"(r1) : "r"(addr));
}
__device__ __forceinline__ void mma_f16(float* c, const uint32_t* a, const uint32_t* b) {
    asm volatile(
        "mma.sync.aligned.m16n8k16.row.col.f32.f16.f16.f32 "
        "{%0,%1,%2,%3}, {%4,%5,%6,%7}, {%8,%9}, {%0,%1,%2,%3};"
        : "+f"(c[0]), "+f"(c[1]), "+f"(c[2]), "+f"(c[3])
        : "r"(a[0]), "r"(a[1]), "r"(a[2]), "r"(a[3]), "r"(b[0]), "r"(b[1]));
}

// ---------------- scratch (device globals; no allocation allowed) -------------
__device__ __half g_xl[(size_t)B_*T_*C_];
__device__ __half g_xv[(size_t)B_*T_*C_];

#define NCH 64
#define TCH 32
__device__ float g_fin[(size_t)B_*NCH*C_];
__device__ float g_carry[(size_t)B_*NCH*C_];

__device__ __half g_A[(size_t)M_*C_];
__device__ __half g_Wla[(size_t)C_*C_];
__device__ __half g_Wv[(size_t)C_*C_];
__device__ __half g_Wp[(size_t)C_*C_];
__device__ __half g_kh[(size_t)B_*NH_*T_*HS_];
__device__ __half g_vth[(size_t)B_*NH_*HS_*T_];   // [b,h,d,t]

// ================= fp32 -> fp16 convert (no transpose) ========================
__global__ void __launch_bounds__(256) conv_fp16_k(
    const float* __restrict__ X, __half* __restrict__ H, int n4)
{
    int i = blockIdx.x * blockDim.x + threadIdx.x;
    if (i >= n4) return;
    float4 v = ((const float4*)X)[i];
    __half2* Hp = (__half2*)H;
    Hp[2*i]   = __half2(__float2half_rn(v.x), __float2half_rn(v.y));
    Hp[2*i+1] = __half2(__float2half_rn(v.z), __float2half_rn(v.w));
}

// ==== batched: 3 weights fp32 [K,N] -> fp16 transposed [N,K] ==================
__global__ void tsplit3_k(const float* __restrict__ W0, const float* __restrict__ W1,
                          const float* __restrict__ W2,
                          __half* __restrict__ T0, __half* __restrict__ T1,
                          __half* __restrict__ T2)
{
    __shared__ float tile[32][33];
    const float* W = (blockIdx.z == 0) ? W0 : (blockIdx.z == 1) ? W1 : W2;
    __half* TH = (blockIdx.z == 0) ? T0 : (blockIdx.z == 1) ? T1 : T2;
    const int n0 = blockIdx.x * 32, k0 = blockIdx.y * 32;
    const int tx = threadIdx.x, ty = threadIdx.y;  // 32 x 8
    #pragma unroll
    for (int j = ty; j < 32; j += 8)
        tile[j][tx] = W[(size_t)(k0 + j) * C_ + n0 + tx];
    __syncthreads();
    #pragma unroll
    for (int j = ty; j < 32; j += 8)
        TH[(size_t)(n0 + j) * C_ + k0 + tx] = __float2half_rn(tile[tx][j]);
}

// ===== fp16 1-pass HMMA GEMM: C = A @ B^T, 128x256 per CTA, GBK=64, 3-stage ===
#define GBM 128
#define GBN 256
#define GBK 64
#define GK  1024
#define GNN 1024
#define GNK (GK / GBK)                    // 16
#define GLDS 72                           // halves per smem row
#define GA_B (GBM * GLDS * 2)             // 18432 B per A matrix tile
#define GB_B (GBN * GLDS * 2)             // 36864 B per B matrix tile
#define GSTG (GA_B + GB_B)                // 55296 per stage
#define GSMEM (3 * GSTG)                  // 165888

template <bool HALF_OUT>
__global__ void __launch_bounds__(256, 1) gemm_tc_k(
    const __half* __restrict__ A,
    const __half* __restrict__ W1, const __half* __restrict__ W2,
    void* __restrict__ C1v, void* __restrict__ C2v)
{
    extern __shared__ __align__(16) char gsm[];

    const int n0g = blockIdx.x * GBN;
    const bool sel = (n0g >= GNN);
    const int n0 = sel ? (n0g - GNN) : n0g;
    const __half* Bm = sel ? W2 : W1;
    void* Cv = sel ? C2v : C1v;

    const int m0 = blockIdx.y * GBM;
    const int tid  = threadIdx.x;
    const int wid  = tid >> 5;
    const int lane = tid & 31;
    const int wm = (wid >> 2) * 64;   // 0 or 64
    const int wn = (wid & 3) * 64;    // 0..192

    float acc[4][8][4];
    #pragma unroll
    for (int i = 0; i < 4; i++)
        #pragma unroll
        for (int j = 0; j < 8; j++)
            #pragma unroll
            for (int e = 0; e < 4; e++) acc[i][j][e] = 0.f;

    auto load_tile = [&](int stage, int kc) {
        const int k0 = kc * GBK;
        char* base = gsm + stage * GSTG;
        #pragma unroll
        for (int i = 0; i < 4; i++) {
            const int idx = tid + i * 256;
            const int row = idx >> 3;
            const int c8  = (idx & 7) * 8;
            const uint32_t so = (uint32_t)(row * GLDS + c8) * 2;
            CP_ASYNC16(smem_u32(base + so), A + (size_t)(m0 + row) * GK + k0 + c8);
        }
        #pragma unroll
        for (int i = 0; i < 8; i++) {
            const int idx = tid + i * 256;
            const int row = idx >> 3;
            const int c8  = (idx & 7) * 8;
            const uint32_t so = (uint32_t)(row * GLDS + c8) * 2;
            CP_ASYNC16(smem_u32(base + GA_B + so), Bm + (size_t)(n0 + row) * GK + k0 + c8);
        }
    };

    load_tile(0, 0);
    CP_COMMIT();
    load_tile(1, 1);
    CP_COMMIT();

    #pragma unroll 1
    for (int kc = 0; kc < GNK; kc++) {
        const int st = kc % 3;
        if (kc + 1 < GNK) { CP_WAIT(1); } else { CP_WAIT(0); }
        __syncthreads();
        if (kc + 2 < GNK) {
            load_tile((kc + 2) % 3, kc + 2);
            CP_COMMIT();
        }

        char* base = gsm + st * GSTG;
        char* bA = base;
        char* bB = base + GA_B;

        #pragma unroll
        for (int ks = 0; ks < 4; ks++) {
            const int koff = ks * 16;
            uint32_t b2[8][2];
            #pragma unroll
            for (int nj = 0; nj < 8; nj++) {
                const int brow = wn + nj*8 + (lane & 7);
                const int bcol = koff + ((lane >> 3) & 1) * 8;
                ldm_x2(b2[nj][0], b2[nj][1], smem_u32(bB + (brow * GLDS + bcol) * 2));
            }
            #pragma unroll
            for (int mi = 0; mi < 4; mi++) {
                const int arow = wm + mi*16 + (lane & 15);
                const int acol = koff + ((lane >> 4) & 1) * 8;
                uint32_t a4[4];
                ldm_x4(a4[0], a4[1], a4[2], a4[3],
                       smem_u32(bA + (arow * GLDS + acol) * 2));
                #pragma unroll
                for (int nj = 0; nj < 8; nj++)
                    mma_f16(acc[mi][nj], a4, b2[nj]);
            }
        }
    }

    const int g = lane >> 2, t = lane & 3;
    if (HALF_OUT) {
        __half* Cg = (__half*)Cv;
        #pragma unroll
        for (int mi = 0; mi < 4; mi++) {
            __half* row0 = Cg + (size_t)(m0 + wm + mi*16 + g)     * GNN + n0 + wn;
            __half* row1 = Cg + (size_t)(m0 + wm + mi*16 + g + 8) * GNN + n0 + wn;
            #pragma unroll
            for (int nj = 0; nj < 8; nj++) {
                *(__half2*)(row0 + nj*8 + t*2) =
                    __half2(__float2half_rn(acc[mi][nj][0]), __float2half_rn(acc[mi][nj][1]));
                *(__half2*)(row1 + nj*8 + t*2) =
                    __half2(__float2half_rn(acc[mi][nj][2]), __float2half_rn(acc[mi][nj][3]));
            }
        }
    } else {
        float* Cg = (float*)Cv;
        #pragma unroll
        for (int mi = 0; mi < 4; mi++) {
            float* row0 = Cg + (size_t)(m0 + wm + mi*16 + g)     * GNN + n0 + wn;
            float* row1 = Cg + (size_t)(m0 + wm + mi*16 + g + 8) * GNN + n0 + wn;
            #pragma unroll
            for (int nj = 0; nj < 8; nj++) {
                *(float2*)(row0 + nj*8 + t*2) = make_float2(acc[mi][nj][0], acc[mi][nj][1]);
                *(float2*)(row1 + nj*8 + t*2) = make_float2(acc[mi][nj][2], acc[mi][nj][3]);
            }
        }
    }
}

// ============== EMA: per-chunk final values only (no scan output store) =======
__global__ void __launch_bounds__(256) ema_fin_k(
    const __half* __restrict__ xl, const float* __restrict__ la_coef,
    float* __restrict__ fin)
{
    const int gid = blockIdx.x * blockDim.x + threadIdx.x;
    if (gid >= B_ * NCH * C_) return;
    const int c = gid % C_;
    const int rest = gid / C_;
    const int chunk = rest % NCH;
    const int b = rest / NCH;
    const int h = c >> 6;

    const float a = la_coef[h];
    const float onem = 1.0f - a;
    float carry = 0.0f;

    const __half* src = xl + ((size_t)b * T_ + chunk * TCH) * C_ + c;

    #pragma unroll 4
    for (int t = 0; t < TCH; t++)
        carry = a * carry + onem * __half2float(src[(size_t)t * C_]);
    fin[gid] = carry;
}

__global__ void ema_comb_k(const float* __restrict__ fin,
                           const float* __restrict__ la_coef,
                           float* __restrict__ carry_out)
{
    const int gid = blockIdx.x * blockDim.x + threadIdx.x;
    if (gid >= B_ * C_) return;
    const int c = gid % C_;
    const int b = gid / C_;
    const float a = la_coef[c >> 6];
    const float ach = __powf(a, (float)TCH);
    float Cv = 0.0f;
    #pragma unroll
    for (int i = 0; i < NCH; i++) {
        const size_t o = ((size_t)b * NCH + i) * C_ + c;
        carry_out[o] = Cv;
        Cv = ach * Cv + fin[o];
    }
}

// ---- seeded scan + normalize + kb scale -> fp16; warp per (b,h,chunk) --------
__global__ void __launch_bounds__(256) knorm_scan_k(
    const __half* __restrict__ xl,
    const float* __restrict__ carry,
    const float* __restrict__ la_coef,
    const float* __restrict__ kernel_beta,
    __half* __restrict__ kh)
{
    const int w = blockIdx.x * 8 + (threadIdx.x >> 5);   // 0 .. B*NH*NCH-1
    const int lane = threadIdx.x & 31;
    if (w >= B_ * NH_ * NCH) return;
    const int chunk = w % NCH;
    const int bh = w / NCH;
    const int h = bh % NH_;
    const int b = bh / NH_;

    const float a = la_coef[h];
    const float onem = 1.0f - a;
    const float kb = expf(fminf(kernel_beta[h] * 10.0f, 5.0f));

    float2 cr = ((const float2*)(carry + ((size_t)b * NCH + chunk) * C_ + h * HS_))[lane];

    const __half* src = xl + ((size_t)b * T_ + chunk * TCH) * C_ + h * HS_;
    __half* dst = kh + (((size_t)b * NH_ + h) * T_ + chunk * TCH) * HS_;

    #pragma unroll 4
    for (int t = 0; t < TCH; t++) {
        const float2 xv2 = __half22float2(((const __half2*)(src + (size_t)t * C_))[lane]);
        cr.x = a * cr.x + onem * xv2.x;
        cr.y = a * cr.y + onem * xv2.y;

        float ss = cr.x * cr.x + cr.y * cr.y;
        #pragma unroll
        for (int o = 16; o > 0; o >>= 1) ss += __shfl_xor_sync(0xffffffffu, ss, o);

        const float scale = kb * rsqrtf(ss);
        ((__half2*)(dst + (size_t)t * HS_))[lane] =
            __half2(__float2half_rn(cr.x * scale), __float2half_rn(cr.y * scale));
    }
}

// ---- fused v build + normalize + vb scale + transpose -> fp16 [d][t] ---------
__global__ void __launch_bounds__(256) vmaket_k(
    const __half* __restrict__ xv,
    const float* __restrict__ v_coef,
    const float* __restrict__ value_beta,
    __half* __restrict__ vth)
{
    __shared__ float tile[64][65];
    const int t0 = blockIdx.x * 64;
    const int bh = blockIdx.y;
    const int h = bh % NH_;
    const int b = bh / NH_;
    const int tid = threadIdx.x;
    const int wid = tid >> 5;
    const int lane = tid & 31;

    const float c = v_coef[h];
    const float vb = expf(value_beta[h] * 10.0f);

    #pragma unroll
    for (int r = wid; r < 64; r += 8) {
        const int t = t0 + r;
        const __half* cur = xv + ((size_t)b * T_ + t) * C_ + h * HS_;
        const float2 vc = __half22float2(((const __half2*)cur)[lane]);
        float2 vn = make_float2(0.f, 0.f);
        if (t + 1 < T_) vn = __half22float2(((const __half2*)(cur + C_))[lane]);
        float2 vv = make_float2(vn.x * (1.f - c) + vc.x * c,
                                vn.y * (1.f - c) + vc.y * c);
        float ss = vv.x * vv.x + vv.y * vv.y;
        #pragma unroll
        for (int o = 16; o > 0; o >>= 1) ss += __shfl_xor_sync(0xffffffffu, ss, o);
        const float scale = vb * rsqrtf(ss);
        tile[r][2*lane]     = vv.x * scale;
        tile[r][2*lane + 1] = vv.y * scale;
    }
    __syncthreads();

    #pragma unroll
    for (int i = tid; i < 2048; i += 256) {
        const int d = i >> 5;
        const int tt = (i & 31) * 2;
        const float x0 = tile[tt][d], x1 = tile[tt + 1][d];
        const size_t o = ((size_t)bh * HS_ + d) * T_ + t0 + tt;
        *(__half2*)(vth + o) = __half2(__float2half_rn(x0), __float2half_rn(x1));
    }
}

// ====== fp16 1-pass HMMA strict-causal flash attention (q == k) ===============
#define AQ 128
#define AK 64
#define APAD 72
#define AMATB (AK * APAD * 2)     // 9216
#define ASTG  (2 * AMATB)         // 18432 per stage
#define ASMEM (3 * ASTG)          // 55296

__global__ void __launch_bounds__(256, 2) attn_mma_k(
    const __half* __restrict__ kh, const __half* __restrict__ vth,
    __half* __restrict__ Yh)
{
    extern __shared__ __align__(16) char asmem[];

    const int b = blockIdx.z;
    const int h = blockIdx.y;
    const int qb = gridDim.x - 1 - blockIdx.x;
    const int p0 = qb * AQ;
    const int tid = threadIdx.x;
    const int wid = tid >> 5;
    const int lane = tid & 31;
    const int g = lane >> 2, t = lane & 3;
    const int wm = wid * 16;

    const __half* Kh = kh + (((size_t)b * NH_ + h) * T_) * HS_;
    const __half* Vh = vth + (((size_t)b * NH_ + h) * HS_) * T_;

    auto sK = [&](int st, int r, int cc) { return asmem + st*ASTG + (r*APAD + cc)*2; };
    auto sV = [&](int st, int r, int cc) { return asmem + st*ASTG + AMATB + (r*APAD + cc)*2; };

    // ---- stage Q fragments via stage-0 K buffer ----
    uint32_t Q[4][4];
    #pragma unroll
    for (int half = 0; half < 2; half++) {
        #pragma unroll
        for (int i = 0; i < 2; i++) {
            const int v = tid + i * 256;
            const int row = v >> 3, seg = (v & 7) * 8;
            *(uint4*)sK(0, row, seg) =
                *(const uint4*)(Kh + (size_t)(p0 + half * 64 + row) * HS_ + seg);
        }
        __syncthreads();
        if ((wm >> 6) == half) {
            const int lr = (wm & 63) + (lane & 15);
            #pragma unroll
            for (int ks = 0; ks < 4; ks++) {
                const int cc = ks*16 + ((lane >> 4) & 1) * 8;
                ldm_x4(Q[ks][0], Q[ks][1], Q[ks][2], Q[ks][3],
                       smem_u32(sK(0, lr, cc)));
            }
        }
        __syncthreads();
    }

    float m0 = -1e30f, m1 = -1e30f, l0 = 0.f, l1 = 0.f;
    float O[8][4];
    #pragma unroll
    for (int nj = 0; nj < 8; nj++)
        #pragma unroll
        for (int e = 0; e < 4; e++) O[nj][e] = 0.f;

    const int r0 = p0 + wm + g;
    const int r1 = r0 + 8;
    const int ntiles = (p0 + AQ) / AK;

    auto load_tile = [&](int st, int j0) {
        #pragma unroll
        for (int i = 0; i < 2; i++) {
            const int v = tid + i * 256;
            const int row = v >> 3, seg = (v & 7) * 8;
            CP_ASYNC16(smem_u32(sK(st, row, seg)), Kh + (size_t)(j0 + row) * HS_ + seg);
            CP_ASYNC16(smem_u32(sV(st, row, seg)), Vh + (size_t)row * T_ + j0 + seg);
        }
    };

    load_tile(0, 0);
    CP_COMMIT();
    if (ntiles > 1) {
        load_tile(1, AK);
        CP_COMMIT();
    }

    #pragma unroll 1
    for (int kt = 0; kt < ntiles; kt++) {
        const int j0 = kt * AK;
        const int st = kt % 3;
        if (kt + 1 < ntiles) { CP_WAIT(1); } else { CP_WAIT(0); }
        __syncthreads();
        if (kt + 2 < ntiles) {
            load_tile((kt + 2) % 3, (kt + 2) * AK);
            CP_COMMIT();
        }

        const bool active = (j0 < p0 + wm + 16);
        if (active) {
            float S[8][4];
            #pragma unroll
            for (int nj = 0; nj < 8; nj++)
                #pragma unroll
                for (int e = 0; e < 4; e++) S[nj][e] = 0.f;

            #pragma unroll
            for (int ks = 0; ks < 4; ks++) {
                const int koff = ks * 16;
                uint32_t b2[8][2];
                #pragma unroll
                for (int nj = 0; nj < 8; nj++) {
                    const int br = nj*8 + (lane & 7);
                    const int bc = koff + ((lane >> 3) & 1) * 8;
                    ldm_x2(b2[nj][0], b2[nj][1], smem_u32(sK(st, br, bc)));
                }
                #pragma unroll
                for (int nj = 0; nj < 8; nj++)
                    mma_f16(S[nj], Q[ks], b2[nj]);
            }

            if (j0 + AK > p0 + wm) {
                #pragma unroll
                for (int nj = 0; nj < 8; nj++) {
                    const int jb = j0 + nj*8 + 2*t;
                    if (jb     >= r0) S[nj][0] = -1e30f;
                    if (jb + 1 >= r0) S[nj][1] = -1e30f;
                    if (jb     >= r1) S[nj][2] = -1e30f;
                    if (jb + 1 >= r1) S[nj][3] = -1e30f;
                }
            }

            float tm0 = -1e30f, tm1 = -1e30f;
            #pragma unroll
            for (int nj = 0; nj < 8; nj++) {
                tm0 = fmaxf(tm0, fmaxf(S[nj][0], S[nj][1]));
                tm1 = fmaxf(tm1, fmaxf(S[nj][2], S[nj][3]));
            }
            tm0 = fmaxf(tm0, __shfl_xor_sync(0xffffffffu, tm0, 1));
            tm0 = fmaxf(tm0, __shfl_xor_sync(0xffffffffu, tm0, 2));
            tm1 = fmaxf(tm1, __shfl_xor_sync(0xffffffffu, tm1, 1));
            tm1 = fmaxf(tm1, __shfl_xor_sync(0xffffffffu, tm1, 2));

            const float m0n = fmaxf(m0, tm0), m1n = fmaxf(m1, tm1);
            const float c0 = __expf(m0 - m0n), c1 = __expf(m1 - m1n);
            l0 *= c0; l1 *= c1;
            #pragma unroll
            for (int nj = 0; nj < 8; nj++) {
                O[nj][0] *= c0; O[nj][1] *= c0;
                O[nj][2] *= c1; O[nj][3] *= c1;
            }
            m0 = m0n; m1 = m1n;

            uint32_t PA[8][2];
            float s0 = 0.f, s1 = 0.f;
            #pragma unroll
            for (int nj = 0; nj < 8; nj++) {
                float e0 = __expf(S[nj][0] - m0n), e1 = __expf(S[nj][1] - m0n);
                float e2 = __expf(S[nj][2] - m1n), e3 = __expf(S[nj][3] - m1n);
                s0 += e0 + e1; s1 += e2 + e3;
                __half2 h01(__float2half_rn(e0), __float2half_rn(e1));
                __half2 h23(__float2half_rn(e2), __float2half_rn(e3));
                PA[nj][0] = *(uint32_t*)&h01;
                PA[nj][1] = *(uint32_t*)&h23;
            }
            s0 += __shfl_xor_sync(0xffffffffu, s0, 1);
            s0 += __shfl_xor_sync(0xffffffffu, s0, 2);
            s1 += __shfl_xor_sync(0xffffffffu, s1, 1);
            s1 += __shfl_xor_sync(0xffffffffu, s1, 2);
            l0 += s0; l1 += s1;

            #pragma unroll
            for (int ks = 0; ks < 4; ks++) {
                const int koff = ks * 16;
                uint32_t a4[4] = {PA[2*ks][0], PA[2*ks][1], PA[2*ks+1][0], PA[2*ks+1][1]};
                uint32_t bv[8][2];
                #pragma unroll
                for (int nj = 0; nj < 8; nj++) {
                    const int br = nj*8 + (lane & 7);
                    const int bc = koff + ((lane >> 3) & 1) * 8;
                    ldm_x2(bv[nj][0], bv[nj][1], smem_u32(sV(st, br, bc)));
                }
                #pragma unroll
                for (int nj = 0; nj < 8; nj++)
                    mma_f16(O[nj], a4, bv[nj]);
            }
        }
    }

    const float il0 = (r0 == 0) ? 0.f : 1.f / l0;
    const float il1 = 1.f / l1;
    __half* y0 = Yh + ((size_t)b * T_ + r0) * C_ + h * HS_;
    __half* y1 = Yh + ((size_t)b * T_ + r1) * C_ + h * HS_;
    #pragma unroll
    for (int nj = 0; nj < 8; nj++) {
        const int col = nj*8 + 2*t;
        *(__half2*)(y0 + col) = __half2(__float2half_rn(O[nj][0] * il0),
                                        __float2half_rn(O[nj][1] * il0));
        *(__half2*)(y1 + col) = __half2(__float2half_rn(O[nj][2] * il1),
                                        __float2half_rn(O[nj][3] * il1));
    }
}

// ------------------------------- launcher --------------------------------------
extern "C" void kernel_launch(void* const* d_in, const int* in_sizes, int n_in,
                              void* d_out, int out_size)
{
    const float* x           = (const float*)d_in[0];
    const float* W_la        = (const float*)d_in[1];
    const float* la_coef     = (const float*)d_in[2];
    const float* kernel_beta = (const float*)d_in[3];
    const float* value_beta  = (const float*)d_in[4];
    const float* W_v         = (const float*)d_in[5];
    const float* v_coef      = (const float*)d_in[6];
    const float* W_proj      = (const float*)d_in[7];
    float* out = (float*)d_out;

    float *fin, *carry;
    __half *xl, *xv, *A, *Wla, *Wv, *Wp, *kh, *vth;
    cudaGetSymbolAddress((void**)&xl,    g_xl);
    cudaGetSymbolAddress((void**)&xv,    g_xv);
    cudaGetSymbolAddress((void**)&fin,   g_fin);
    cudaGetSymbolAddress((void**)&carry, g_carry);
    cudaGetSymbolAddress((void**)&A,     g_A);
    cudaGetSymbolAddress((void**)&Wla,   g_Wla);
    cudaGetSymbolAddress((void**)&Wv,    g_Wv);
    cudaGetSymbolAddress((void**)&Wp,    g_Wp);
    cudaGetSymbolAddress((void**)&kh,    g_kh);
    cudaGetSymbolAddress((void**)&vth,   g_vth);

    cudaFuncSetAttribute(gemm_tc_k<true>,
                         cudaFuncAttributeMaxDynamicSharedMemorySize, GSMEM);
    cudaFuncSetAttribute(gemm_tc_k<false>,
                         cudaFuncAttributeMaxDynamicSharedMemorySize, GSMEM);
    cudaFuncSetAttribute(attn_mma_k, cudaFuncAttributeMaxDynamicSharedMemorySize, ASMEM);

    const int n4 = (M_ * C_) / 4;

    conv_fp16_k<<<(n4 + 255) / 256, 256>>>(x, A, n4);
    tsplit3_k<<<dim3(32, 32, 3), dim3(32, 8)>>>(W_la, W_v, W_proj, Wla, Wv, Wp);

    // fused QKV GEMM: N-concat of W_la (-> xl fp16) and W_v (-> xv fp16)
    gemm_tc_k<true><<<dim3(2 * GNN / GBN, M_ / GBM), 256, GSMEM>>>(
        A, Wla, Wv, xl, xv);

    ema_fin_k<<<(B_*NCH*C_) / 256, 256>>>(xl, la_coef, fin);
    ema_comb_k<<<(B_*C_ + 255) / 256, 256>>>(fin, la_coef, carry);

    // seeded-scan knorm: warp per (b,h,chunk); writes kh directly
    knorm_scan_k<<<(B_*NH_*NCH) / 8, 256>>>(xl, carry, la_coef, kernel_beta, kh);
    vmaket_k<<<dim3(T_/64, B_*NH_), 256>>>(xv, v_coef, value_beta, vth);

    // attention writes y directly as fp16 into the proj-GEMM A buffer
    attn_mma_k<<<dim3(T_/AQ, NH_, B_), 256, ASMEM>>>(kh, vth, A);

    // projection GEMM: fp32 output, N = 1024 -> 4 n-tiles
    gemm_tc_k<false><<<dim3(GNN / GBN, M_ / GBM), 256, GSMEM>>>(
        A, Wp, Wp, out, out);
}

// round 14
// speedup vs baseline: 2.1937x; 1.0258x over previous
#include <cuda_runtime.h>
#include <cuda_fp16.h>
#include <cstdint>

#define B_  2
#define T_  2048
#define NH_ 16
#define HS_ 64
#define C_  (NH_*HS_)   // 1024
#define M_  (B_*T_)     // 4096

// ======================= helpers ==============================================
__device__ __forceinline__ uint32_t smem_u32(const void* p) {
    uint32_t a;
    asm("{ .reg .u64 t; cvta.to.shared.u64 t, %1; cvt.u32.u64 %0, t; }" : "=r"(a) : "l"(p));
    return a;
}
#define CP_ASYNC16(dst_u32, src_ptr) \
    asm volatile("cp.async.cg.shared.global [%0], [%1], 16;" :: "r"(dst_u32), "l"(src_ptr))
#define CP_COMMIT() asm volatile("cp.async.commit_group;" ::: "memory")
#define CP_WAIT(n)  asm volatile("cp.async.wait_group %0;" :: "n"(n) : "memory")

__device__ __forceinline__ void ldm_x4(uint32_t& r0, uint32_t& r1, uint32_t& r2, uint32_t& r3,
                                       uint32_t addr) {
    asm volatile("ldmatrix.sync.aligned.m8n8.x4.shared.b16 {%0,%1,%2,%3}, [%4];"
                 : "=r"(r0), "=r"(r1), "=r"(r2), "=r"(r3) : "r"(addr));
}
__device__ __forceinline__ void ldm_x2(uint32_t& r0, uint32_t& r1, uint32_t addr) {
    asm volatile("ldmatrix.sync.aligned.m8n8.x2.shared.b16 {%0,%1}, [%2];"
                 : "=r"(r0), "=r"(r1) : "r"(addr));
}
__device__ __forceinline__ void mma_f16(float* c, const uint32_t* a, const uint32_t* b) {
    asm volatile(
        "mma.sync.aligned.m16n8k16.row.col.f32.f16.f16.f32 "
        "{%0,%1,%2,%3}, {%4,%5,%6,%7}, {%8,%9}, {%0,%1,%2,%3};"
        : "+f"(c[0]), "+f"(c[1]), "+f"(c[2]), "+f"(c[3])
        : "r"(a[0]), "r"(a[1]), "r"(a[2]), "r"(a[3]), "r"(b[0]), "r"(b[1]));
}

// ---------------- scratch (device globals; no allocation allowed) -------------
__device__ __half g_xl[(size_t)B_*T_*C_];
__device__ __half g_xv[(size_t)B_*T_*C_];

#define NCH 64
#define TCH 32
__device__ float g_fin[(size_t)B_*NCH*C_];
__device__ float g_carry[(size_t)B_*NCH*C_];

__device__ __half g_A[(size_t)M_*C_];
__device__ __half g_Wla[(size_t)C_*C_];
__device__ __half g_Wv[(size_t)C_*C_];
__device__ __half g_Wp[(size_t)C_*C_];
__device__ __half g_kh[(size_t)B_*NH_*T_*HS_];
__device__ __half g_vth[(size_t)B_*NH_*HS_*T_];   // [b,h,d,t]

// ====== fused prep: x -> fp16 (z=0) + 3 weights fp32->fp16 transposed (z=1..3)
__global__ void prep_k(const float* __restrict__ X, __half* __restrict__ XH,
                       const float* __restrict__ W0, const float* __restrict__ W1,
                       const float* __restrict__ W2,
                       __half* __restrict__ T0, __half* __restrict__ T1,
                       __half* __restrict__ T2)
{
    __shared__ float tile[32][33];
    const int z = blockIdx.z;
    if (z == 0) {
        // conv: 1024 blocks x 256 threads; 4 float4 each (covers M*C/4 = 1M)
        const int bid = blockIdx.y * 32 + blockIdx.x;
        const int tid = threadIdx.y * 32 + threadIdx.x;     // 0..255
        const int base = bid * 1024 + tid;
        #pragma unroll
        for (int r = 0; r < 4; r++) {
            const int i = base + r * 256;
            float4 v = ((const float4*)X)[i];
            __half2* Hp = (__half2*)XH;
            Hp[2*i]   = __half2(__float2half_rn(v.x), __float2half_rn(v.y));
            Hp[2*i+1] = __half2(__float2half_rn(v.z), __float2half_rn(v.w));
        }
        return;
    }
    const float* W = (z == 1) ? W0 : (z == 2) ? W1 : W2;
    __half* TH = (z == 1) ? T0 : (z == 2) ? T1 : T2;
    const int n0 = blockIdx.x * 32, k0 = blockIdx.y * 32;
    const int tx = threadIdx.x, ty = threadIdx.y;  // 32 x 8
    #pragma unroll
    for (int j = ty; j < 32; j += 8)
        tile[j][tx] = W[(size_t)(k0 + j) * C_ + n0 + tx];
    __syncthreads();
    #pragma unroll
    for (int j = ty; j < 32; j += 8)
        TH[(size_t)(n0 + j) * C_ + k0 + tx] = __float2half_rn(tile[tx][j]);
}

// ===== fp16 1-pass HMMA GEMM: C = A @ B^T, 128x256 per CTA, GBK=64, 3-stage ===
#define GBM 128
#define GBN 256
#define GBK 64
#define GK  1024
#define GNN 1024
#define GNK (GK / GBK)                    // 16
#define GLDS 72                           // halves per smem row
#define GA_B (GBM * GLDS * 2)             // 18432 B per A matrix tile
#define GB_B (GBN * GLDS * 2)             // 36864 B per B matrix tile
#define GSTG (GA_B + GB_B)                // 55296 per stage
#define GSMEM (3 * GSTG)                  // 165888

template <bool HALF_OUT>
__global__ void __launch_bounds__(256, 1) gemm_tc_k(
    const __half* __restrict__ A,
    const __half* __restrict__ W1, const __half* __restrict__ W2,
    void* __restrict__ C1v, void* __restrict__ C2v)
{
    extern __shared__ __align__(16) char gsm[];

    const int n0g = blockIdx.x * GBN;
    const bool sel = (n0g >= GNN);
    const int n0 = sel ? (n0g - GNN) : n0g;
    const __half* Bm = sel ? W2 : W1;
    void* Cv = sel ? C2v : C1v;

    const int m0 = blockIdx.y * GBM;
    const int tid  = threadIdx.x;
    const int wid  = tid >> 5;
    const int lane = tid & 31;
    const int wm = (wid >> 2) * 64;   // 0 or 64
    const int wn = (wid & 3) * 64;    // 0..192

    float acc[4][8][4];
    #pragma unroll
    for (int i = 0; i < 4; i++)
        #pragma unroll
        for (int j = 0; j < 8; j++)
            #pragma unroll
            for (int e = 0; e < 4; e++) acc[i][j][e] = 0.f;

    auto load_tile = [&](int stage, int kc) {
        const int k0 = kc * GBK;
        char* base = gsm + stage * GSTG;
        #pragma unroll
        for (int i = 0; i < 4; i++) {
            const int idx = tid + i * 256;
            const int row = idx >> 3;
            const int c8  = (idx & 7) * 8;
            const uint32_t so = (uint32_t)(row * GLDS + c8) * 2;
            CP_ASYNC16(smem_u32(base + so), A + (size_t)(m0 + row) * GK + k0 + c8);
        }
        #pragma unroll
        for (int i = 0; i < 8; i++) {
            const int idx = tid + i * 256;
            const int row = idx >> 3;
            const int c8  = (idx & 7) * 8;
            const uint32_t so = (uint32_t)(row * GLDS + c8) * 2;
            CP_ASYNC16(smem_u32(base + GA_B + so), Bm + (size_t)(n0 + row) * GK + k0 + c8);
        }
    };

    load_tile(0, 0);
    CP_COMMIT();
    load_tile(1, 1);
    CP_COMMIT();

    #pragma unroll 1
    for (int kc = 0; kc < GNK; kc++) {
        const int st = kc % 3;
        if (kc + 1 < GNK) { CP_WAIT(1); } else { CP_WAIT(0); }
        __syncthreads();
        if (kc + 2 < GNK) {
            load_tile((kc + 2) % 3, kc + 2);
            CP_COMMIT();
        }

        char* base = gsm + st * GSTG;
        char* bA = base;
        char* bB = base + GA_B;

        #pragma unroll
        for (int ks = 0; ks < 4; ks++) {
            const int koff = ks * 16;
            uint32_t b2[8][2];
            #pragma unroll
            for (int nj = 0; nj < 8; nj++) {
                const int brow = wn + nj*8 + (lane & 7);
                const int bcol = koff + ((lane >> 3) & 1) * 8;
                ldm_x2(b2[nj][0], b2[nj][1], smem_u32(bB + (brow * GLDS + bcol) * 2));
            }
            #pragma unroll
            for (int mi = 0; mi < 4; mi++) {
                const int arow = wm + mi*16 + (lane & 15);
                const int acol = koff + ((lane >> 4) & 1) * 8;
                uint32_t a4[4];
                ldm_x4(a4[0], a4[1], a4[2], a4[3],
                       smem_u32(bA + (arow * GLDS + acol) * 2));
                #pragma unroll
                for (int nj = 0; nj < 8; nj++)
                    mma_f16(acc[mi][nj], a4, b2[nj]);
            }
        }
    }

    const int g = lane >> 2, t = lane & 3;
    if (HALF_OUT) {
        __half* Cg = (__half*)Cv;
        #pragma unroll
        for (int mi = 0; mi < 4; mi++) {
            __half* row0 = Cg + (size_t)(m0 + wm + mi*16 + g)     * GNN + n0 + wn;
            __half* row1 = Cg + (size_t)(m0 + wm + mi*16 + g + 8) * GNN + n0 + wn;
            #pragma unroll
            for (int nj = 0; nj < 8; nj++) {
                *(__half2*)(row0 + nj*8 + t*2) =
                    __half2(__float2half_rn(acc[mi][nj][0]), __float2half_rn(acc[mi][nj][1]));
                *(__half2*)(row1 + nj*8 + t*2) =
                    __half2(__float2half_rn(acc[mi][nj][2]), __float2half_rn(acc[mi][nj][3]));
            }
        }
    } else {
        float* Cg = (float*)Cv;
        #pragma unroll
        for (int mi = 0; mi < 4; mi++) {
            float* row0 = Cg + (size_t)(m0 + wm + mi*16 + g)     * GNN + n0 + wn;
            float* row1 = Cg + (size_t)(m0 + wm + mi*16 + g + 8) * GNN + n0 + wn;
            #pragma unroll
            for (int nj = 0; nj < 8; nj++) {
                *(float2*)(row0 + nj*8 + t*2) = make_float2(acc[mi][nj][0], acc[mi][nj][1]);
                *(float2*)(row1 + nj*8 + t*2) = make_float2(acc[mi][nj][2], acc[mi][nj][3]);
            }
        }
    }
}

// === fused: ema per-chunk finals (bid<512) + v build/norm/transpose (bid>=512)
__global__ void __launch_bounds__(256) ema_vmake_k(
    const __half* __restrict__ xl, const __half* __restrict__ xv,
    const float* __restrict__ la_coef,
    const float* __restrict__ v_coef, const float* __restrict__ value_beta,
    float* __restrict__ fin, __half* __restrict__ vth)
{
    __shared__ float tile[64][65];
    const int bid = blockIdx.x;
    const int tid = threadIdx.x;

    if (bid < 512) {
        // ---- ema_fin: per-chunk final EMA values ----
        const int gid = bid * 256 + tid;           // < B*NCH*C = 131072
        const int c = gid % C_;
        const int rest = gid / C_;
        const int chunk = rest % NCH;
        const int b = rest / NCH;
        const int h = c >> 6;

        const float a = la_coef[h];
        const float onem = 1.0f - a;
        float carry = 0.0f;

        const __half* src = xl + ((size_t)b * T_ + chunk * TCH) * C_ + c;
        #pragma unroll 4
        for (int t = 0; t < TCH; t++)
            carry = a * carry + onem * __half2float(src[(size_t)t * C_]);
        fin[gid] = carry;
        return;
    }

    // ---- vmaket: blocks 512..1535 -> (t0, bh) ----
    const int vb_id = bid - 512;
    const int t0 = (vb_id & 31) * 64;
    const int bh = vb_id >> 5;
    const int h = bh % NH_;
    const int b = bh / NH_;
    const int wid = tid >> 5;
    const int lane = tid & 31;

    const float c = v_coef[h];
    const float vbeta = expf(value_beta[h] * 10.0f);

    #pragma unroll
    for (int r = wid; r < 64; r += 8) {
        const int t = t0 + r;
        const __half* cur = xv + ((size_t)b * T_ + t) * C_ + h * HS_;
        const float2 vc = __half22float2(((const __half2*)cur)[lane]);
        float2 vn = make_float2(0.f, 0.f);
        if (t + 1 < T_) vn = __half22float2(((const __half2*)(cur + C_))[lane]);
        float2 vv = make_float2(vn.x * (1.f - c) + vc.x * c,
                                vn.y * (1.f - c) + vc.y * c);
        float ss = vv.x * vv.x + vv.y * vv.y;
        #pragma unroll
        for (int o = 16; o > 0; o >>= 1) ss += __shfl_xor_sync(0xffffffffu, ss, o);
        const float scale = vbeta * rsqrtf(ss);
        tile[r][2*lane]     = vv.x * scale;
        tile[r][2*lane + 1] = vv.y * scale;
    }
    __syncthreads();

    #pragma unroll
    for (int i = tid; i < 2048; i += 256) {
        const int d = i >> 5;
        const int tt = (i & 31) * 2;
        const float x0 = tile[tt][d], x1 = tile[tt + 1][d];
        const size_t o = ((size_t)bh * HS_ + d) * T_ + t0 + tt;
        *(__half2*)(vth + o) = __half2(__float2half_rn(x0), __float2half_rn(x1));
    }
}

__global__ void ema_comb_k(const float* __restrict__ fin,
                           const float* __restrict__ la_coef,
                           float* __restrict__ carry_out)
{
    const int gid = blockIdx.x * blockDim.x + threadIdx.x;
    if (gid >= B_ * C_) return;
    const int c = gid % C_;
    const int b = gid / C_;
    const float a = la_coef[c >> 6];
    const float ach = __powf(a, (float)TCH);
    float Cv = 0.0f;
    #pragma unroll
    for (int i = 0; i < NCH; i++) {
        const size_t o = ((size_t)b * NCH + i) * C_ + c;
        carry_out[o] = Cv;
        Cv = ach * Cv + fin[o];
    }
}

// ---- seeded scan + normalize + kb scale -> fp16; warp per (b,h,chunk) --------
__global__ void __launch_bounds__(256) knorm_scan_k(
    const __half* __restrict__ xl,
    const float* __restrict__ carry,
    const float* __restrict__ la_coef,
    const float* __restrict__ kernel_beta,
    __half* __restrict__ kh)
{
    const int w = blockIdx.x * 8 + (threadIdx.x >> 5);   // 0 .. B*NH*NCH-1
    const int lane = threadIdx.x & 31;
    if (w >= B_ * NH_ * NCH) return;
    const int chunk = w % NCH;
    const int bh = w / NCH;
    const int h = bh % NH_;
    const int b = bh / NH_;

    const float a = la_coef[h];
    const float onem = 1.0f - a;
    const float kb = expf(fminf(kernel_beta[h] * 10.0f, 5.0f));

    float2 cr = ((const float2*)(carry + ((size_t)b * NCH + chunk) * C_ + h * HS_))[lane];

    const __half* src = xl + ((size_t)b * T_ + chunk * TCH) * C_ + h * HS_;
    __half* dst = kh + (((size_t)b * NH_ + h) * T_ + chunk * TCH) * HS_;

    #pragma unroll 4
    for (int t = 0; t < TCH; t++) {
        const float2 xv2 = __half22float2(((const __half2*)(src + (size_t)t * C_))[lane]);
        cr.x = a * cr.x + onem * xv2.x;
        cr.y = a * cr.y + onem * xv2.y;

        float ss = cr.x * cr.x + cr.y * cr.y;
        #pragma unroll
        for (int o = 16; o > 0; o >>= 1) ss += __shfl_xor_sync(0xffffffffu, ss, o);

        const float scale = kb * rsqrtf(ss);
        ((__half2*)(dst + (size_t)t * HS_))[lane] =
            __half2(__float2half_rn(cr.x * scale), __float2half_rn(cr.y * scale));
    }
}

// ====== fp16 1-pass HMMA strict-causal flash attention (q == k) ===============
#define AQ 128
#define AK 64
#define APAD 72
#define AMATB (AK * APAD * 2)     // 9216
#define ASTG  (2 * AMATB)         // 18432 per stage
#define ASMEM (3 * ASTG)          // 55296

__global__ void __launch_bounds__(256, 2) attn_mma_k(
    const __half* __restrict__ kh, const __half* __restrict__ vth,
    __half* __restrict__ Yh)
{
    extern __shared__ __align__(16) char asmem[];

    const int b = blockIdx.z;
    const int h = blockIdx.y;
    const int qb = gridDim.x - 1 - blockIdx.x;
    const int p0 = qb * AQ;
    const int tid = threadIdx.x;
    const int wid = tid >> 5;
    const int lane = tid & 31;
    const int g = lane >> 2, t = lane & 3;
    const int wm = wid * 16;

    const __half* Kh = kh + (((size_t)b * NH_ + h) * T_) * HS_;
    const __half* Vh = vth + (((size_t)b * NH_ + h) * HS_) * T_;

    auto sK = [&](int st, int r, int cc) { return asmem + st*ASTG + (r*APAD + cc)*2; };
    auto sV = [&](int st, int r, int cc) { return asmem + st*ASTG + AMATB + (r*APAD + cc)*2; };

    // ---- stage Q fragments via stage-0 K buffer ----
    uint32_t Q[4][4];
    #pragma unroll
    for (int half = 0; half < 2; half++) {
        #pragma unroll
        for (int i = 0; i < 2; i++) {
            const int v = tid + i * 256;
            const int row = v >> 3, seg = (v & 7) * 8;
            *(uint4*)sK(0, row, seg) =
                *(const uint4*)(Kh + (size_t)(p0 + half * 64 + row) * HS_ + seg);
        }
        __syncthreads();
        if ((wm >> 6) == half) {
            const int lr = (wm & 63) + (lane & 15);
            #pragma unroll
            for (int ks = 0; ks < 4; ks++) {
                const int cc = ks*16 + ((lane >> 4) & 1) * 8;
                ldm_x4(Q[ks][0], Q[ks][1], Q[ks][2], Q[ks][3],
                       smem_u32(sK(0, lr, cc)));
            }
        }
        __syncthreads();
    }

    float m0 = -1e30f, m1 = -1e30f, l0 = 0.f, l1 = 0.f;
    float O[8][4];
    #pragma unroll
    for (int nj = 0; nj < 8; nj++)
        #pragma unroll
        for (int e = 0; e < 4; e++) O[nj][e] = 0.f;

    const int r0 = p0 + wm + g;
    const int r1 = r0 + 8;
    const int ntiles = (p0 + AQ) / AK;

    auto load_tile = [&](int st, int j0) {
        #pragma unroll
        for (int i = 0; i < 2; i++) {
            const int v = tid + i * 256;
            const int row = v >> 3, seg = (v & 7) * 8;
            CP_ASYNC16(smem_u32(sK(st, row, seg)), Kh + (size_t)(j0 + row) * HS_ + seg);
            CP_ASYNC16(smem_u32(sV(st, row, seg)), Vh + (size_t)row * T_ + j0 + seg);
        }
    };

    load_tile(0, 0);
    CP_COMMIT();
    if (ntiles > 1) {
        load_tile(1, AK);
        CP_COMMIT();
    }

    #pragma unroll 1
    for (int kt = 0; kt < ntiles; kt++) {
        const int j0 = kt * AK;
        const int st = kt % 3;
        if (kt + 1 < ntiles) { CP_WAIT(1); } else { CP_WAIT(0); }
        __syncthreads();
        if (kt + 2 < ntiles) {
            load_tile((kt + 2) % 3, (kt + 2) * AK);
            CP_COMMIT();
        }

        const bool active = (j0 < p0 + wm + 16);
        if (active) {
            float S[8][4];
            #pragma unroll
            for (int nj = 0; nj < 8; nj++)
                #pragma unroll
                for (int e = 0; e < 4; e++) S[nj][e] = 0.f;

            #pragma unroll
            for (int ks = 0; ks < 4; ks++) {
                const int koff = ks * 16;
                uint32_t b2[8][2];
                #pragma unroll
                for (int nj = 0; nj < 8; nj++) {
                    const int br = nj*8 + (lane & 7);
                    const int bc = koff + ((lane >> 3) & 1) * 8;
                    ldm_x2(b2[nj][0], b2[nj][1], smem_u32(sK(st, br, bc)));
                }
                #pragma unroll
                for (int nj = 0; nj < 8; nj++)
                    mma_f16(S[nj], Q[ks], b2[nj]);
            }

            if (j0 + AK > p0 + wm) {
                #pragma unroll
                for (int nj = 0; nj < 8; nj++) {
                    const int jb = j0 + nj*8 + 2*t;
                    if (jb     >= r0) S[nj][0] = -1e30f;
                    if (jb + 1 >= r0) S[nj][1] = -1e30f;
                    if (jb     >= r1) S[nj][2] = -1e30f;
                    if (jb + 1 >= r1) S[nj][3] = -1e30f;
                }
            }

            float tm0 = -1e30f, tm1 = -1e30f;
            #pragma unroll
            for (int nj = 0; nj < 8; nj++) {
                tm0 = fmaxf(tm0, fmaxf(S[nj][0], S[nj][1]));
                tm1 = fmaxf(tm1, fmaxf(S[nj][2], S[nj][3]));
            }
            tm0 = fmaxf(tm0, __shfl_xor_sync(0xffffffffu, tm0, 1));
            tm0 = fmaxf(tm0, __shfl_xor_sync(0xffffffffu, tm0, 2));
            tm1 = fmaxf(tm1, __shfl_xor_sync(0xffffffffu, tm1, 1));
            tm1 = fmaxf(tm1, __shfl_xor_sync(0xffffffffu, tm1, 2));

            const float m0n = fmaxf(m0, tm0), m1n = fmaxf(m1, tm1);
            const float c0 = __expf(m0 - m0n), c1 = __expf(m1 - m1n);
            l0 *= c0; l1 *= c1;
            #pragma unroll
            for (int nj = 0; nj < 8; nj++) {
                O[nj][0] *= c0; O[nj][1] *= c0;
                O[nj][2] *= c1; O[nj][3] *= c1;
            }
            m0 = m0n; m1 = m1n;

            uint32_t PA[8][2];
            float s0 = 0.f, s1 = 0.f;
            #pragma unroll
            for (int nj = 0; nj < 8; nj++) {
                float e0 = __expf(S[nj][0] - m0n), e1 = __expf(S[nj][1] - m0n);
                float e2 = __expf(S[nj][2] - m1n), e3 = __expf(S[nj][3] - m1n);
                s0 += e0 + e1; s1 += e2 + e3;
                __half2 h01(__float2half_rn(e0), __float2half_rn(e1));
                __half2 h23(__float2half_rn(e2), __float2half_rn(e3));
                PA[nj][0] = *(uint32_t*)&h01;
                PA[nj][1] = *(uint32_t*)&h23;
            }
            s0 += __shfl_xor_sync(0xffffffffu, s0, 1);
            s0 += __shfl_xor_sync(0xffffffffu, s0, 2);
            s1 += __shfl_xor_sync(0xffffffffu, s1, 1);
            s1 += __shfl_xor_sync(0xffffffffu, s1, 2);
            l0 += s0; l1 += s1;

            #pragma unroll
            for (int ks = 0; ks < 4; ks++) {
                const int koff = ks * 16;
                uint32_t a4[4] = {PA[2*ks][0], PA[2*ks][1], PA[2*ks+1][0], PA[2*ks+1][1]};
                uint32_t bv[8][2];
                #pragma unroll
                for (int nj = 0; nj < 8; nj++) {
                    const int br = nj*8 + (lane & 7);
                    const int bc = koff + ((lane >> 3) & 1) * 8;
                    ldm_x2(bv[nj][0], bv[nj][1], smem_u32(sV(st, br, bc)));
                }
                #pragma unroll
                for (int nj = 0; nj < 8; nj++)
                    mma_f16(O[nj], a4, bv[nj]);
            }
        }
    }

    const float il0 = (r0 == 0) ? 0.f : 1.f / l0;
    const float il1 = 1.f / l1;
    __half* y0 = Yh + ((size_t)b * T_ + r0) * C_ + h * HS_;
    __half* y1 = Yh + ((size_t)b * T_ + r1) * C_ + h * HS_;
    #pragma unroll
    for (int nj = 0; nj < 8; nj++) {
        const int col = nj*8 + 2*t;
        *(__half2*)(y0 + col) = __half2(__float2half_rn(O[nj][0] * il0),
                                        __float2half_rn(O[nj][1] * il0));
        *(__half2*)(y1 + col) = __half2(__float2half_rn(O[nj][2] * il1),
                                        __float2half_rn(O[nj][3] * il1));
    }
}

// ------------------------------- launcher --------------------------------------
extern "C" void kernel_launch(void* const* d_in, const int* in_sizes, int n_in,
                              void* d_out, int out_size)
{
    const float* x           = (const float*)d_in[0];
    const float* W_la        = (const float*)d_in[1];
    const float* la_coef     = (const float*)d_in[2];
    const float* kernel_beta = (const float*)d_in[3];
    const float* value_beta  = (const float*)d_in[4];
    const float* W_v         = (const float*)d_in[5];
    const float* v_coef      = (const float*)d_in[6];
    const float* W_proj      = (const float*)d_in[7];
    float* out = (float*)d_out;

    float *fin, *carry;
    __half *xl, *xv, *A, *Wla, *Wv, *Wp, *kh, *vth;
    cudaGetSymbolAddress((void**)&xl,    g_xl);
    cudaGetSymbolAddress((void**)&xv,    g_xv);
    cudaGetSymbolAddress((void**)&fin,   g_fin);
    cudaGetSymbolAddress((void**)&carry, g_carry);
    cudaGetSymbolAddress((void**)&A,     g_A);
    cudaGetSymbolAddress((void**)&Wla,   g_Wla);
    cudaGetSymbolAddress((void**)&Wv,    g_Wv);
    cudaGetSymbolAddress((void**)&Wp,    g_Wp);
    cudaGetSymbolAddress((void**)&kh,    g_kh);
    cudaGetSymbolAddress((void**)&vth,   g_vth);

    cudaFuncSetAttribute(gemm_tc_k<true>,
                         cudaFuncAttributeMaxDynamicSharedMemorySize, GSMEM);
    cudaFuncSetAttribute(gemm_tc_k<false>,
                         cudaFuncAttributeMaxDynamicSharedMemorySize, GSMEM);
    cudaFuncSetAttribute(attn_mma_k, cudaFuncAttributeMaxDynamicSharedMemorySize, ASMEM);

    // fused prep: x conversion (z=0) runs concurrently with 3 weight transposes
    prep_k<<<dim3(32, 32, 4), dim3(32, 8)>>>(x, A, W_la, W_v, W_proj, Wla, Wv, Wp);

    // fused QKV GEMM: N-concat of W_la (-> xl fp16) and W_v (-> xv fp16)
    gemm_tc_k<true><<<dim3(2 * GNN / GBN, M_ / GBM), 256, GSMEM>>>(
        A, Wla, Wv, xl, xv);

    // fused: ema chunk-finals (k-path) || v build+norm+transpose (v-path)
    ema_vmake_k<<<512 + 1024, 256>>>(xl, xv, la_coef, v_coef, value_beta, fin, vth);

    ema_comb_k<<<(B_*C_ + 255) / 256, 256>>>(fin, la_coef, carry);

    // seeded-scan knorm: warp per (b,h,chunk); writes kh directly
    knorm_scan_k<<<(B_*NH_*NCH) / 8, 256>>>(xl, carry, la_coef, kernel_beta, kh);

    // attention writes y directly as fp16 into the proj-GEMM A buffer
    attn_mma_k<<<dim3(T_/AQ, NH_, B_), 256, ASMEM>>>(kh, vth, A);

    // projection GEMM: fp32 output, N = 1024 -> 4 n-tiles
    gemm_tc_k<false><<<dim3(GNN / GBN, M_ / GBM), 256, GSMEM>>>(
        A, Wp, Wp, out, out);
}

// round 15
// speedup vs baseline: 2.1973x; 1.0016x over previous
#include <cuda_runtime.h>
#include <cuda_fp16.h>
#include <cstdint>

#define B_  2
#define T_  2048
#define NH_ 16
#define HS_ 64
#define C_  (NH_*HS_)   // 1024
#define M_  (B_*T_)     // 4096

// ======================= helpers ==============================================
__device__ __forceinline__ uint32_t smem_u32(const void* p) {
    uint32_t a;
    asm("{ .reg .u64 t; cvta.to.shared.u64 t, %1; cvt.u32.u64 %0, t; }" : "=r"(a) : "l"(p));
    return a;
}
#define CP_ASYNC16(dst_u32, src_ptr) \
    asm volatile("cp.async.cg.shared.global [%0], [%1], 16;" :: "r"(dst_u32), "l"(src_ptr))
#define CP_COMMIT() asm volatile("cp.async.commit_group;" ::: "memory")
#define CP_WAIT(n)  asm volatile("cp.async.wait_group %0;" :: "n"(n) : "memory")

__device__ __forceinline__ void ldm_x4(uint32_t& r0, uint32_t& r1, uint32_t& r2, uint32_t& r3,
                                       uint32_t addr) {
    asm volatile("ldmatrix.sync.aligned.m8n8.x4.shared.b16 {%0,%1,%2,%3}, [%4];"
                 : "=r"(r0), "=r"(r1), "=r"(r2), "=r"(r3) : "r"(addr));
}
__device__ __forceinline__ void ldm_x2(uint32_t& r0, uint32_t& r1, uint32_t addr) {
    asm volatile("ldmatrix.sync.aligned.m8n8.x2.shared.b16 {%0,%1}, [%2];"
                 : "=r"(r0), "=r"(r1) : "r"(addr));
}
__device__ __forceinline__ void mma_f16(float* c, const uint32_t* a, const uint32_t* b) {
    asm volatile(
        "mma.sync.aligned.m16n8k16.row.col.f32.f16.f16.f32 "
        "{%0,%1,%2,%3}, {%4,%5,%6,%7}, {%8,%9}, {%0,%1,%2,%3};"
        : "+f"(c[0]), "+f"(c[1]), "+f"(c[2]), "+f"(c[3])
        : "r"(a[0]), "r"(a[1]), "r"(a[2]), "r"(a[3]), "r"(b[0]), "r"(b[1]));
}

// ---------------- scratch (device globals; no allocation allowed) -------------
__device__ __half g_xl[(size_t)B_*T_*C_];
__device__ __half g_xv[(size_t)B_*T_*C_];

#define NCH 64
#define TCH 32
__device__ float g_fin[(size_t)B_*NCH*C_];
__device__ float g_carry[(size_t)B_*NCH*C_];

__device__ __half g_A[(size_t)M_*C_];
__device__ __half g_Wla[(size_t)C_*C_];
__device__ __half g_Wv[(size_t)C_*C_];
__device__ __half g_Wp[(size_t)C_*C_];
__device__ __half g_kh[(size_t)B_*NH_*T_*HS_];
__device__ __half g_vth[(size_t)B_*NH_*HS_*T_];   // [b,h,d,t]

// ====== fused prep: x -> fp16 (z=0) + 3 weights fp32->fp16 transposed (z=1..3)
__global__ void prep_k(const float* __restrict__ X, __half* __restrict__ XH,
                       const float* __restrict__ W0, const float* __restrict__ W1,
                       const float* __restrict__ W2,
                       __half* __restrict__ T0, __half* __restrict__ T1,
                       __half* __restrict__ T2)
{
    __shared__ float tile[32][33];
    const int z = blockIdx.z;
    if (z == 0) {
        const int bid = blockIdx.y * 32 + blockIdx.x;
        const int tid = threadIdx.y * 32 + threadIdx.x;     // 0..255
        const int base = bid * 1024 + tid;
        #pragma unroll
        for (int r = 0; r < 4; r++) {
            const int i = base + r * 256;
            float4 v = ((const float4*)X)[i];
            __half2* Hp = (__half2*)XH;
            Hp[2*i]   = __half2(__float2half_rn(v.x), __float2half_rn(v.y));
            Hp[2*i+1] = __half2(__float2half_rn(v.z), __float2half_rn(v.w));
        }
        return;
    }
    const float* W = (z == 1) ? W0 : (z == 2) ? W1 : W2;
    __half* TH = (z == 1) ? T0 : (z == 2) ? T1 : T2;
    const int n0 = blockIdx.x * 32, k0 = blockIdx.y * 32;
    const int tx = threadIdx.x, ty = threadIdx.y;  // 32 x 8
    #pragma unroll
    for (int j = ty; j < 32; j += 8)
        tile[j][tx] = W[(size_t)(k0 + j) * C_ + n0 + tx];
    __syncthreads();
    #pragma unroll
    for (int j = ty; j < 32; j += 8)
        TH[(size_t)(n0 + j) * C_ + k0 + tx] = __float2half_rn(tile[tx][j]);
}

// ===== fp16 1-pass HMMA GEMM: C = A @ B^T, 128x256 per CTA, GBK=64, 3-stage ===
#define GBM 128
#define GBN 256
#define GBK 64
#define GK  1024
#define GNN 1024
#define GNK (GK / GBK)                    // 16
#define GLDS 72                           // halves per smem row
#define GA_B (GBM * GLDS * 2)             // 18432 B per A matrix tile
#define GB_B (GBN * GLDS * 2)             // 36864 B per B matrix tile
#define GSTG (GA_B + GB_B)                // 55296 per stage
#define GSMEM (3 * GSTG)                  // 165888

template <bool HALF_OUT>
__global__ void __launch_bounds__(256, 1) gemm_tc_k(
    const __half* __restrict__ A,
    const __half* __restrict__ W1, const __half* __restrict__ W2,
    void* __restrict__ C1v, void* __restrict__ C2v)
{
    extern __shared__ __align__(16) char gsm[];

    const int n0g = blockIdx.x * GBN;
    const bool sel = (n0g >= GNN);
    const int n0 = sel ? (n0g - GNN) : n0g;
    const __half* Bm = sel ? W2 : W1;
    void* Cv = sel ? C2v : C1v;

    const int m0 = blockIdx.y * GBM;
    const int tid  = threadIdx.x;
    const int wid  = tid >> 5;
    const int lane = tid & 31;
    const int wm = (wid >> 2) * 64;   // 0 or 64
    const int wn = (wid & 3) * 64;    // 0..192

    float acc[4][8][4];
    #pragma unroll
    for (int i = 0; i < 4; i++)
        #pragma unroll
        for (int j = 0; j < 8; j++)
            #pragma unroll
            for (int e = 0; e < 4; e++) acc[i][j][e] = 0.f;

    auto load_tile = [&](int stage, int kc) {
        const int k0 = kc * GBK;
        char* base = gsm + stage * GSTG;
        #pragma unroll
        for (int i = 0; i < 4; i++) {
            const int idx = tid + i * 256;
            const int row = idx >> 3;
            const int c8  = (idx & 7) * 8;
            const uint32_t so = (uint32_t)(row * GLDS + c8) * 2;
            CP_ASYNC16(smem_u32(base + so), A + (size_t)(m0 + row) * GK + k0 + c8);
        }
        #pragma unroll
        for (int i = 0; i < 8; i++) {
            const int idx = tid + i * 256;
            const int row = idx >> 3;
            const int c8  = (idx & 7) * 8;
            const uint32_t so = (uint32_t)(row * GLDS + c8) * 2;
            CP_ASYNC16(smem_u32(base + GA_B + so), Bm + (size_t)(n0 + row) * GK + k0 + c8);
        }
    };

    load_tile(0, 0);
    CP_COMMIT();
    load_tile(1, 1);
    CP_COMMIT();

    #pragma unroll 1
    for (int kc = 0; kc < GNK; kc++) {
        const int st = kc % 3;
        if (kc + 1 < GNK) { CP_WAIT(1); } else { CP_WAIT(0); }
        __syncthreads();
        if (kc + 2 < GNK) {
            load_tile((kc + 2) % 3, kc + 2);
            CP_COMMIT();
        }

        char* base = gsm + st * GSTG;
        char* bA = base;
        char* bB = base + GA_B;

        #pragma unroll
        for (int ks = 0; ks < 4; ks++) {
            const int koff = ks * 16;
            uint32_t b2[8][2];
            #pragma unroll
            for (int nj = 0; nj < 8; nj++) {
                const int brow = wn + nj*8 + (lane & 7);
                const int bcol = koff + ((lane >> 3) & 1) * 8;
                ldm_x2(b2[nj][0], b2[nj][1], smem_u32(bB + (brow * GLDS + bcol) * 2));
            }
            #pragma unroll
            for (int mi = 0; mi < 4; mi++) {
                const int arow = wm + mi*16 + (lane & 15);
                const int acol = koff + ((lane >> 4) & 1) * 8;
                uint32_t a4[4];
                ldm_x4(a4[0], a4[1], a4[2], a4[3],
                       smem_u32(bA + (arow * GLDS + acol) * 2));
                #pragma unroll
                for (int nj = 0; nj < 8; nj++)
                    mma_f16(acc[mi][nj], a4, b2[nj]);
            }
        }
    }

    const int g = lane >> 2, t = lane & 3;
    if (HALF_OUT) {
        __half* Cg = (__half*)Cv;
        #pragma unroll
        for (int mi = 0; mi < 4; mi++) {
            __half* row0 = Cg + (size_t)(m0 + wm + mi*16 + g)     * GNN + n0 + wn;
            __half* row1 = Cg + (size_t)(m0 + wm + mi*16 + g + 8) * GNN + n0 + wn;
            #pragma unroll
            for (int nj = 0; nj < 8; nj++) {
                *(__half2*)(row0 + nj*8 + t*2) =
                    __half2(__float2half_rn(acc[mi][nj][0]), __float2half_rn(acc[mi][nj][1]));
                *(__half2*)(row1 + nj*8 + t*2) =
                    __half2(__float2half_rn(acc[mi][nj][2]), __float2half_rn(acc[mi][nj][3]));
            }
        }
    } else {
        float* Cg = (float*)Cv;
        #pragma unroll
        for (int mi = 0; mi < 4; mi++) {
            float* row0 = Cg + (size_t)(m0 + wm + mi*16 + g)     * GNN + n0 + wn;
            float* row1 = Cg + (size_t)(m0 + wm + mi*16 + g + 8) * GNN + n0 + wn;
            #pragma unroll
            for (int nj = 0; nj < 8; nj++) {
                *(float2*)(row0 + nj*8 + t*2) = make_float2(acc[mi][nj][0], acc[mi][nj][1]);
                *(float2*)(row1 + nj*8 + t*2) = make_float2(acc[mi][nj][2], acc[mi][nj][3]);
            }
        }
    }
}

// === fused: ema per-chunk finals (bid<512) + v build/norm/transpose (bid>=512)
__global__ void __launch_bounds__(256) ema_vmake_k(
    const __half* __restrict__ xl, const __half* __restrict__ xv,
    const float* __restrict__ la_coef,
    const float* __restrict__ v_coef, const float* __restrict__ value_beta,
    float* __restrict__ fin, __half* __restrict__ vth)
{
    __shared__ float tile[64][65];
    const int bid = blockIdx.x;
    const int tid = threadIdx.x;

    if (bid < 512) {
        const int gid = bid * 256 + tid;           // < B*NCH*C = 131072
        const int c = gid % C_;
        const int rest = gid / C_;
        const int chunk = rest % NCH;
        const int b = rest / NCH;
        const int h = c >> 6;

        const float a = la_coef[h];
        const float onem = 1.0f - a;
        float carry = 0.0f;

        const __half* src = xl + ((size_t)b * T_ + chunk * TCH) * C_ + c;
        #pragma unroll 4
        for (int t = 0; t < TCH; t++)
            carry = a * carry + onem * __half2float(src[(size_t)t * C_]);
        fin[gid] = carry;
        return;
    }

    const int vb_id = bid - 512;
    const int t0 = (vb_id & 31) * 64;
    const int bh = vb_id >> 5;
    const int h = bh % NH_;
    const int b = bh / NH_;
    const int wid = tid >> 5;
    const int lane = tid & 31;

    const float c = v_coef[h];
    const float vbeta = expf(value_beta[h] * 10.0f);

    #pragma unroll
    for (int r = wid; r < 64; r += 8) {
        const int t = t0 + r;
        const __half* cur = xv + ((size_t)b * T_ + t) * C_ + h * HS_;
        const float2 vc = __half22float2(((const __half2*)cur)[lane]);
        float2 vn = make_float2(0.f, 0.f);
        if (t + 1 < T_) vn = __half22float2(((const __half2*)(cur + C_))[lane]);
        float2 vv = make_float2(vn.x * (1.f - c) + vc.x * c,
                                vn.y * (1.f - c) + vc.y * c);
        float ss = vv.x * vv.x + vv.y * vv.y;
        #pragma unroll
        for (int o = 16; o > 0; o >>= 1) ss += __shfl_xor_sync(0xffffffffu, ss, o);
        const float scale = vbeta * rsqrtf(ss);
        tile[r][2*lane]     = vv.x * scale;
        tile[r][2*lane + 1] = vv.y * scale;
    }
    __syncthreads();

    #pragma unroll
    for (int i = tid; i < 2048; i += 256) {
        const int d = i >> 5;
        const int tt = (i & 31) * 2;
        const float x0 = tile[tt][d], x1 = tile[tt + 1][d];
        const size_t o = ((size_t)bh * HS_ + d) * T_ + t0 + tt;
        *(__half2*)(vth + o) = __half2(__float2half_rn(x0), __float2half_rn(x1));
    }
}

// ===== warp-parallel affine-scan combine: one warp per (b,c), 2 chunks/lane ===
__global__ void __launch_bounds__(256) ema_comb_k(
    const float* __restrict__ fin,
    const float* __restrict__ la_coef,
    float* __restrict__ carry_out)
{
    const int w = blockIdx.x * 8 + (threadIdx.x >> 5);   // 0 .. B*C-1
    const int lane = threadIdx.x & 31;
    if (w >= B_ * C_) return;
    const int c = w % C_;
    const int b = w / C_;

    const float a = la_coef[c >> 6];
    const float ach = __powf(a, (float)TCH);

    const int j0 = 2 * lane;
    const float f0 = fin[((size_t)b * NCH + j0    ) * C_ + c];
    const float f1 = fin[((size_t)b * NCH + j0 + 1) * C_ + c];

    // local compose of two chunk maps: x -> ach^2 * x + (ach*f0 + f1)
    float s = ach * ach;
    float av = ach * f0 + f1;

    // inclusive Hillis-Steele scan over affine maps (prev applied first)
    #pragma unroll
    for (int step = 1; step < 32; step <<= 1) {
        const float sp = __shfl_up_sync(0xffffffffu, s, step);
        const float ap = __shfl_up_sync(0xffffffffu, av, step);
        if (lane >= step) {
            av = s * ap + av;   // compose: cur after prev
            s  = s * sp;
        }
    }

    // carry for chunk j0 = inclusive value of lane-1 (0 for lane 0)
    const float incl_prev = __shfl_up_sync(0xffffffffu, av, 1);
    const float c0 = (lane == 0) ? 0.f : incl_prev;
    const float c1 = ach * c0 + f0;

    carry_out[((size_t)b * NCH + j0    ) * C_ + c] = c0;
    carry_out[((size_t)b * NCH + j0 + 1) * C_ + c] = c1;
}

// ---- seeded scan + normalize + kb scale -> fp16; warp per (b,h,chunk) --------
__global__ void __launch_bounds__(256) knorm_scan_k(
    const __half* __restrict__ xl,
    const float* __restrict__ carry,
    const float* __restrict__ la_coef,
    const float* __restrict__ kernel_beta,
    __half* __restrict__ kh)
{
    const int w = blockIdx.x * 8 + (threadIdx.x >> 5);   // 0 .. B*NH*NCH-1
    const int lane = threadIdx.x & 31;
    if (w >= B_ * NH_ * NCH) return;
    const int chunk = w % NCH;
    const int bh = w / NCH;
    const int h = bh % NH_;
    const int b = bh / NH_;

    const float a = la_coef[h];
    const float onem = 1.0f - a;
    const float kb = expf(fminf(kernel_beta[h] * 10.0f, 5.0f));

    float2 cr = ((const float2*)(carry + ((size_t)b * NCH + chunk) * C_ + h * HS_))[lane];

    const __half* src = xl + ((size_t)b * T_ + chunk * TCH) * C_ + h * HS_;
    __half* dst = kh + (((size_t)b * NH_ + h) * T_ + chunk * TCH) * HS_;

    #pragma unroll 4
    for (int t = 0; t < TCH; t++) {
        const float2 xv2 = __half22float2(((const __half2*)(src + (size_t)t * C_))[lane]);
        cr.x = a * cr.x + onem * xv2.x;
        cr.y = a * cr.y + onem * xv2.y;

        float ss = cr.x * cr.x + cr.y * cr.y;
        #pragma unroll
        for (int o = 16; o > 0; o >>= 1) ss += __shfl_xor_sync(0xffffffffu, ss, o);

        const float scale = kb * rsqrtf(ss);
        ((__half2*)(dst + (size_t)t * HS_))[lane] =
            __half2(__float2half_rn(cr.x * scale), __float2half_rn(cr.y * scale));
    }
}

// ====== fp16 1-pass HMMA strict-causal flash attention (q == k) ===============
#define AQ 128
#define AK 64
#define APAD 72
#define AMATB (AK * APAD * 2)     // 9216
#define ASTG  (2 * AMATB)         // 18432 per stage
#define ASMEM (3 * ASTG)          // 55296

__global__ void __launch_bounds__(256, 2) attn_mma_k(
    const __half* __restrict__ kh, const __half* __restrict__ vth,
    __half* __restrict__ Yh)
{
    extern __shared__ __align__(16) char asmem[];

    const int b = blockIdx.z;
    const int h = blockIdx.y;
    const int qb = gridDim.x - 1 - blockIdx.x;
    const int p0 = qb * AQ;
    const int tid = threadIdx.x;
    const int wid = tid >> 5;
    const int lane = tid & 31;
    const int g = lane >> 2, t = lane & 3;
    const int wm = wid * 16;

    const __half* Kh = kh + (((size_t)b * NH_ + h) * T_) * HS_;
    const __half* Vh = vth + (((size_t)b * NH_ + h) * HS_) * T_;

    auto sK = [&](int st, int r, int cc) { return asmem + st*ASTG + (r*APAD + cc)*2; };
    auto sV = [&](int st, int r, int cc) { return asmem + st*ASTG + AMATB + (r*APAD + cc)*2; };

    // ---- stage Q fragments via stage-0 K buffer ----
    uint32_t Q[4][4];
    #pragma unroll
    for (int half = 0; half < 2; half++) {
        #pragma unroll
        for (int i = 0; i < 2; i++) {
            const int v = tid + i * 256;
            const int row = v >> 3, seg = (v & 7) * 8;
            *(uint4*)sK(0, row, seg) =
                *(const uint4*)(Kh + (size_t)(p0 + half * 64 + row) * HS_ + seg);
        }
        __syncthreads();
        if ((wm >> 6) == half) {
            const int lr = (wm & 63) + (lane & 15);
            #pragma unroll
            for (int ks = 0; ks < 4; ks++) {
                const int cc = ks*16 + ((lane >> 4) & 1) * 8;
                ldm_x4(Q[ks][0], Q[ks][1], Q[ks][2], Q[ks][3],
                       smem_u32(sK(0, lr, cc)));
            }
        }
        __syncthreads();
    }

    float m0 = -1e30f, m1 = -1e30f, l0 = 0.f, l1 = 0.f;
    float O[8][4];
    #pragma unroll
    for (int nj = 0; nj < 8; nj++)
        #pragma unroll
        for (int e = 0; e < 4; e++) O[nj][e] = 0.f;

    const int r0 = p0 + wm + g;
    const int r1 = r0 + 8;
    const int ntiles = (p0 + AQ) / AK;

    auto load_tile = [&](int st, int j0) {
        #pragma unroll
        for (int i = 0; i < 2; i++) {
            const int v = tid + i * 256;
            const int row = v >> 3, seg = (v & 7) * 8;
            CP_ASYNC16(smem_u32(sK(st, row, seg)), Kh + (size_t)(j0 + row) * HS_ + seg);
            CP_ASYNC16(smem_u32(sV(st, row, seg)), Vh + (size_t)row * T_ + j0 + seg);
        }
    };

    load_tile(0, 0);
    CP_COMMIT();
    if (ntiles > 1) {
        load_tile(1, AK);
        CP_COMMIT();
    }

    #pragma unroll 1
    for (int kt = 0; kt < ntiles; kt++) {
        const int j0 = kt * AK;
        const int st = kt % 3;
        if (kt + 1 < ntiles) { CP_WAIT(1); } else { CP_WAIT(0); }
        __syncthreads();
        if (kt + 2 < ntiles) {
            load_tile((kt + 2) % 3, (kt + 2) * AK);
            CP_COMMIT();
        }

        const bool active = (j0 < p0 + wm + 16);
        if (active) {
            float S[8][4];
            #pragma unroll
            for (int nj = 0; nj < 8; nj++)
                #pragma unroll
                for (int e = 0; e < 4; e++) S[nj][e] = 0.f;

            #pragma unroll
            for (int ks = 0; ks < 4; ks++) {
                const int koff = ks * 16;
                uint32_t b2[8][2];
                #pragma unroll
                for (int nj = 0; nj < 8; nj++) {
                    const int br = nj*8 + (lane & 7);
                    const int bc = koff + ((lane >> 3) & 1) * 8;
                    ldm_x2(b2[nj][0], b2[nj][1], smem_u32(sK(st, br, bc)));
                }
                #pragma unroll
                for (int nj = 0; nj < 8; nj++)
                    mma_f16(S[nj], Q[ks], b2[nj]);
            }

            if (j0 + AK > p0 + wm) {
                #pragma unroll
                for (int nj = 0; nj < 8; nj++) {
                    const int jb = j0 + nj*8 + 2*t;
                    if (jb     >= r0) S[nj][0] = -1e30f;
                    if (jb + 1 >= r0) S[nj][1] = -1e30f;
                    if (jb     >= r1) S[nj][2] = -1e30f;
                    if (jb + 1 >= r1) S[nj][3] = -1e30f;
                }
            }

            float tm0 = -1e30f, tm1 = -1e30f;
            #pragma unroll
            for (int nj = 0; nj < 8; nj++) {
                tm0 = fmaxf(tm0, fmaxf(S[nj][0], S[nj][1]));
                tm1 = fmaxf(tm1, fmaxf(S[nj][2], S[nj][3]));
            }
            tm0 = fmaxf(tm0, __shfl_xor_sync(0xffffffffu, tm0, 1));
            tm0 = fmaxf(tm0, __shfl_xor_sync(0xffffffffu, tm0, 2));
            tm1 = fmaxf(tm1, __shfl_xor_sync(0xffffffffu, tm1, 1));
            tm1 = fmaxf(tm1, __shfl_xor_sync(0xffffffffu, tm1, 2));

            const float m0n = fmaxf(m0, tm0), m1n = fmaxf(m1, tm1);
            const float c0 = __expf(m0 - m0n), c1 = __expf(m1 - m1n);
            l0 *= c0; l1 *= c1;
            #pragma unroll
            for (int nj = 0; nj < 8; nj++) {
                O[nj][0] *= c0; O[nj][1] *= c0;
                O[nj][2] *= c1; O[nj][3] *= c1;
            }
            m0 = m0n; m1 = m1n;

            uint32_t PA[8][2];
            float s0 = 0.f, s1 = 0.f;
            #pragma unroll
            for (int nj = 0; nj < 8; nj++) {
                float e0 = __expf(S[nj][0] - m0n), e1 = __expf(S[nj][1] - m0n);
                float e2 = __expf(S[nj][2] - m1n), e3 = __expf(S[nj][3] - m1n);
                s0 += e0 + e1; s1 += e2 + e3;
                __half2 h01(__float2half_rn(e0), __float2half_rn(e1));
                __half2 h23(__float2half_rn(e2), __float2half_rn(e3));
                PA[nj][0] = *(uint32_t*)&h01;
                PA[nj][1] = *(uint32_t*)&h23;
            }
            s0 += __shfl_xor_sync(0xffffffffu, s0, 1);
            s0 += __shfl_xor_sync(0xffffffffu, s0, 2);
            s1 += __shfl_xor_sync(0xffffffffu, s1, 1);
            s1 += __shfl_xor_sync(0xffffffffu, s1, 2);
            l0 += s0; l1 += s1;

            #pragma unroll
            for (int ks = 0; ks < 4; ks++) {
                const int koff = ks * 16;
                uint32_t a4[4] = {PA[2*ks][0], PA[2*ks][1], PA[2*ks+1][0], PA[2*ks+1][1]};
                uint32_t bv[8][2];
                #pragma unroll
                for (int nj = 0; nj < 8; nj++) {
                    const int br = nj*8 + (lane & 7);
                    const int bc = koff + ((lane >> 3) & 1) * 8;
                    ldm_x2(bv[nj][0], bv[nj][1], smem_u32(sV(st, br, bc)));
                }
                #pragma unroll
                for (int nj = 0; nj < 8; nj++)
                    mma_f16(O[nj], a4, bv[nj]);
            }
        }
    }

    const float il0 = (r0 == 0) ? 0.f : 1.f / l0;
    const float il1 = 1.f / l1;
    __half* y0 = Yh + ((size_t)b * T_ + r0) * C_ + h * HS_;
    __half* y1 = Yh + ((size_t)b * T_ + r1) * C_ + h * HS_;
    #pragma unroll
    for (int nj = 0; nj < 8; nj++) {
        const int col = nj*8 + 2*t;
        *(__half2*)(y0 + col) = __half2(__float2half_rn(O[nj][0] * il0),
                                        __float2half_rn(O[nj][1] * il0));
        *(__half2*)(y1 + col) = __half2(__float2half_rn(O[nj][2] * il1),
                                        __float2half_rn(O[nj][3] * il1));
    }
}

// ------------------------------- launcher --------------------------------------
extern "C" void kernel_launch(void* const* d_in, const int* in_sizes, int n_in,
                              void* d_out, int out_size)
{
    const float* x           = (const float*)d_in[0];
    const float* W_la        = (const float*)d_in[1];
    const float* la_coef     = (const float*)d_in[2];
    const float* kernel_beta = (const float*)d_in[3];
    const float* value_beta  = (const float*)d_in[4];
    const float* W_v         = (const float*)d_in[5];
    const float* v_coef      = (const float*)d_in[6];
    const float* W_proj      = (const float*)d_in[7];
    float* out = (float*)d_out;

    float *fin, *carry;
    __half *xl, *xv, *A, *Wla, *Wv, *Wp, *kh, *vth;
    cudaGetSymbolAddress((void**)&xl,    g_xl);
    cudaGetSymbolAddress((void**)&xv,    g_xv);
    cudaGetSymbolAddress((void**)&fin,   g_fin);
    cudaGetSymbolAddress((void**)&carry, g_carry);
    cudaGetSymbolAddress((void**)&A,     g_A);
    cudaGetSymbolAddress((void**)&Wla,   g_Wla);
    cudaGetSymbolAddress((void**)&Wv,    g_Wv);
    cudaGetSymbolAddress((void**)&Wp,    g_Wp);
    cudaGetSymbolAddress((void**)&kh,    g_kh);
    cudaGetSymbolAddress((void**)&vth,   g_vth);

    cudaFuncSetAttribute(gemm_tc_k<true>,
                         cudaFuncAttributeMaxDynamicSharedMemorySize, GSMEM);
    cudaFuncSetAttribute(gemm_tc_k<false>,
                         cudaFuncAttributeMaxDynamicSharedMemorySize, GSMEM);
    cudaFuncSetAttribute(attn_mma_k, cudaFuncAttributeMaxDynamicSharedMemorySize, ASMEM);

    // fused prep: x conversion (z=0) runs concurrently with 3 weight transposes
    prep_k<<<dim3(32, 32, 4), dim3(32, 8)>>>(x, A, W_la, W_v, W_proj, Wla, Wv, Wp);

    // fused QKV GEMM: N-concat of W_la (-> xl fp16) and W_v (-> xv fp16)
    gemm_tc_k<true><<<dim3(2 * GNN / GBN, M_ / GBM), 256, GSMEM>>>(
        A, Wla, Wv, xl, xv);

    // fused: ema chunk-finals (k-path) || v build+norm+transpose (v-path)
    ema_vmake_k<<<512 + 1024, 256>>>(xl, xv, la_coef, v_coef, value_beta, fin, vth);

    // warp-parallel affine-scan combine (one warp per (b,c))
    ema_comb_k<<<(B_*C_) / 8, 256>>>(fin, la_coef, carry);

    // seeded-scan knorm: warp per (b,h,chunk); writes kh directly
    knorm_scan_k<<<(B_*NH_*NCH) / 8, 256>>>(xl, carry, la_coef, kernel_beta, kh);

    // attention writes y directly as fp16 into the proj-GEMM A buffer
    attn_mma_k<<<dim3(T_/AQ, NH_, B_), 256, ASMEM>>>(kh, vth, A);

    // projection GEMM: fp32 output, N = 1024 -> 4 n-tiles
    gemm_tc_k<false><<<dim3(GNN / GBN, M_ / GBM), 256, GSMEM>>>(
        A, Wp, Wp, out, out);
}